// round 5
// baseline (speedup 1.0000x reference)
#include <cuda_runtime.h>

#define BATCH  64
#define NPG    512
#define NTOT   32768
#define EDGES  524288
#define EPG    8192
#define NCHK   16
#define ODIM   200
#define IDIM   100
#define H3     600
#define CDIM   300
#define P1     254
#define P2     127
#define GP1    16256
#define GP2    8128
#define NCLS   7

// ----------------------------- device scratch -----------------------------
__device__ float  d_h0[NTOT*ODIM];
__device__ float  d_h1[NTOT*ODIM];
__device__ float2 d_h0hl[NTOT*ODIM];
__device__ float2 d_h1hl[NTOT*ODIM];
__device__ float2 d_ahl[NTOT*ODIM];
__device__ float  d_Ht[NTOT*4*ODIM];
__device__ float  d_gi[NTOT*H3];
__device__ float  d_gh[NTOT*H3];
__device__ float2 d_Wst2[ODIM*4*ODIM];     // [d][t*200+o]
__device__ float2 d_WihT[ODIM*H3];
__device__ float2 d_WhhT[ODIM*H3];
__device__ float  d_nbias[NTOT*ODIM];
__device__ int    d_deg4[NTOT*4];
__device__ int    d_indptr[NTOT+1];
__device__ int    d_ccnt[NTOT*NCHK];
__device__ int    d_srcs[EDGES];
__device__ int    d_typs[EDGES];
__device__ float2 d_cThl[CDIM*NTOT + 64];
__device__ float2 d_w1yhl[3*ODIM*ODIM];
__device__ float2 d_w1zhl[3*CDIM*CDIM];
__device__ float2 d_w2yhl[ODIM*ODIM];
__device__ float2 d_w2zhl[CDIM*CDIM];
__device__ float2 d_wmyhl[NCLS*ODIM];
__device__ float2 d_wmzhl[NCLS*CDIM];
__device__ float  d_y1[ODIM*NTOT];
__device__ float  d_z1[CDIM*NTOT];
__device__ float2 d_yp1hl[ODIM*GP1];
__device__ float2 d_zp1hl[CDIM*GP1];
__device__ float  d_y2[ODIM*GP1];
__device__ float  d_z2[CDIM*GP1];
__device__ float2 d_yp2hl[ODIM*GP2];
__device__ float2 d_zp2hl[CDIM*GP2];
__device__ float  d_ly[NCLS*GP2];
__device__ float  d_lz[NCLS*GP2];

// ----------------------------- helpers ------------------------------------
__device__ __forceinline__ unsigned f2tf32(float f) {
    unsigned u;
    asm("cvt.rna.tf32.f32 %0, %1;" : "=r"(u) : "f"(f));
    return u;
}
__device__ __forceinline__ float2 spl(float f) {
    unsigned h = f2tf32(f);
    float hf = __uint_as_float(h);
    unsigned l = f2tf32(f - hf);
    return make_float2(hf, __uint_as_float(l));
}

// ----------------------------- setup kernels ------------------------------
__global__ void zero_int_k(int* p, int n) {
    int i = blockIdx.x * blockDim.x + threadIdx.x;
    if (i < n) p[i] = 0;
}

__global__ void hist_k(const int* __restrict__ edst, const int* __restrict__ etyp) {
    int e = blockIdx.x * blockDim.x + threadIdx.x;
    if (e < EDGES) atomicAdd(&d_deg4[edst[e] * 4 + etyp[e]], 1);
}

__global__ void scan_k() {
    __shared__ int ssum[1024];
    int t = threadIdx.x;
    int loc[32];
    int s = 0;
#pragma unroll
    for (int i = 0; i < 32; i++) {
        int n = t * 32 + i;
        int d = d_deg4[n*4] + d_deg4[n*4+1] + d_deg4[n*4+2] + d_deg4[n*4+3];
        loc[i] = s; s += d;
    }
    ssum[t] = s;
    __syncthreads();
    if (t == 0) {
        int acc = 0;
        for (int i = 0; i < 1024; i++) { int v = ssum[i]; ssum[i] = acc; acc += v; }
        d_indptr[NTOT] = acc;
    }
    __syncthreads();
    int off = ssum[t];
#pragma unroll
    for (int i = 0; i < 32; i++) d_indptr[t * 32 + i] = off + loc[i];
}

__global__ void chunk_hist_k(const int* __restrict__ edst) {
    __shared__ int h[NPG];
    int g = blockIdx.y, c = blockIdx.x;
    h[threadIdx.x] = 0;
    __syncthreads();
    int e = g * EPG + c * 512 + threadIdx.x;
    atomicAdd(&h[edst[e] - g * NPG], 1);
    __syncthreads();
    d_ccnt[(g * NPG + threadIdx.x) * NCHK + c] = h[threadIdx.x];
}

__global__ void chunk_scan_k() {
    int n = blockIdx.x * blockDim.x + threadIdx.x;
    if (n < NTOT) {
        int base = d_indptr[n];
#pragma unroll
        for (int c = 0; c < NCHK; c++) {
            int v = d_ccnt[n * NCHK + c];
            d_ccnt[n * NCHK + c] = base;
            base += v;
        }
    }
}

__global__ void scatter_k(const int* __restrict__ esrc, const int* __restrict__ edst,
                          const int* __restrict__ etyp) {
    __shared__ int sd[512];
    int g = blockIdx.y, c = blockIdx.x;
    int e = g * EPG + c * 512 + threadIdx.x;
    int dl = edst[e] - g * NPG;
    sd[threadIdx.x] = dl;
    __syncthreads();
    int rank = 0;
    for (int i = 0; i < threadIdx.x; i++) rank += (sd[i] == dl);
    int pos = d_ccnt[(g * NPG + dl) * NCHK + c] + rank;
    d_srcs[pos] = esrc[e];
    d_typs[pos] = etyp[e];
}

// etype_W [4][o][d] -> Wst2[d][t*200+o] hi/lo
__global__ void pack_wstack2_k(const float* __restrict__ W) {
    int idx = blockIdx.x * blockDim.x + threadIdx.x;
    if (idx < 4 * ODIM * ODIM) {
        int o = idx % ODIM;
        int d = (idx / ODIM) % ODIM;
        int t = idx / (ODIM * ODIM);
        d_Wst2[d * (4 * ODIM) + t * ODIM + o] = spl(W[(t * ODIM + o) * ODIM + d]);
    }
}

// W[600][200] -> out[200][600] hi/lo
__global__ void pack_T_hl_k(const float* __restrict__ W, float2* __restrict__ out) {
    int idx = blockIdx.x * blockDim.x + threadIdx.x;
    if (idx < ODIM * H3) {
        int j = idx % H3;
        int d = idx / H3;
        out[d * H3 + j] = spl(W[j * ODIM + d]);
    }
}

// conv weight [C][C][3] -> [k][co][ci] hi/lo
__global__ void pack_conv_hl_k(const float* __restrict__ W, float2* __restrict__ out, int C) {
    int idx = blockIdx.x * blockDim.x + threadIdx.x;
    if (idx < 3 * C * C) {
        int ci = idx % C;
        int co = (idx / C) % C;
        int k  = idx / (C * C);
        out[idx] = spl(W[(co * C + ci) * 3 + k]);
    }
}

__global__ void split_mat_k(const float* __restrict__ in, float2* __restrict__ out, int n) {
    int i = blockIdx.x * blockDim.x + threadIdx.x;
    if (i < n) out[i] = spl(in[i]);
}

__global__ void init_h_k(const float* __restrict__ feat) {
    int idx = blockIdx.x * blockDim.x + threadIdx.x;
    if (idx < NTOT * ODIM) {
        int d = idx % ODIM;
        int n = idx / ODIM;
        float v = (d < IDIM) ? feat[n * IDIM + d] : 0.f;
        d_h0[idx] = v;
        d_h0hl[idx] = spl(v);
    }
}

__global__ void nodebias_k(const float* __restrict__ eb) {
    int idx = blockIdx.x * blockDim.x + threadIdx.x;
    if (idx < NTOT * ODIM) {
        int o = idx % ODIM;
        int n = idx / ODIM;
        float s = 0.f;
#pragma unroll
        for (int t = 0; t < 4; t++) s += (float)d_deg4[n * 4 + t] * eb[t * ODIM + o];
        d_nbias[idx] = s;
    }
}

// a[n][o] = sum_{edges->n} Ht[src][t*200+o]; out split with nbias folded in
__global__ void spmm_k(const float* __restrict__ Ht) {
    __shared__ int so[128];
    int n = blockIdx.x;
    int tid = threadIdx.x;
    int beg = d_indptr[n], end = d_indptr[n + 1];
    float a = 0.f;
    for (int base = beg; base < end; base += 128) {
        int cnt = min(128, end - base);
        if (tid < cnt) so[tid] = d_srcs[base + tid] * (4 * ODIM) + d_typs[base + tid] * ODIM;
        __syncthreads();
        if (tid < ODIM) {
            for (int e = 0; e < cnt; e++) a += Ht[so[e] + tid];
        }
        __syncthreads();
    }
    if (tid < ODIM) {
        int o = n * ODIM + tid;
        d_ahl[o] = spl(a + d_nbias[o]);
    }
}

// --------------------------- tensor-core GEMM ------------------------------
// 3xTF32, operands pre-split (float2 hi/lo). Pure LDS+MMA inner loop.
// C[M,N] = sum_s A_s[M,K]*B_s[K,N] (+bias). A_s = A + s*aStep, B_s = B + s.
// BMODE: 0 none, 1 bias[col], 3 bias[row]. lda/ldb in float2 elements.

__device__ __forceinline__ void mma_tf32(float* d, const unsigned* a, const unsigned* b) {
    asm volatile(
        "mma.sync.aligned.m16n8k8.row.col.f32.tf32.tf32.f32 "
        "{%0,%1,%2,%3}, {%4,%5,%6,%7}, {%8,%9}, {%0,%1,%2,%3};"
        : "+f"(d[0]), "+f"(d[1]), "+f"(d[2]), "+f"(d[3])
        : "r"(a[0]), "r"(a[1]), "r"(a[2]), "r"(a[3]), "r"(b[0]), "r"(b[1]));
}
__device__ __forceinline__ void cpa16(void* dst, const void* src, int sb) {
    unsigned sa = (unsigned)__cvta_generic_to_shared(dst);
    asm volatile("cp.async.cg.shared.global [%0], [%1], 16, %2;" :: "r"(sa), "l"(src), "r"(sb));
}
__device__ __forceinline__ void cpa8(void* dst, const void* src, int sb) {
    unsigned sa = (unsigned)__cvta_generic_to_shared(dst);
    asm volatile("cp.async.ca.shared.global [%0], [%1], 8, %2;" :: "r"(sa), "l"(src), "r"(sb));
}

#define APADF2 20
#define BPADF2 132
#define SMEM_GEMM (int)(2*(128*APADF2 + 16*BPADF2)*sizeof(float2))

template<int BMODE, int NSPLIT>
__global__ __launch_bounds__(256, 2) void gemm_tc(
    const float2* __restrict__ A, const float2* __restrict__ B,
    float* __restrict__ C, const float* __restrict__ bias,
    int M, int N, int K, int lda, int ldb, int ldc, int aStep)
{
    extern __shared__ float2 sm[];
    float2* Ab = sm;                      // [2][128][APADF2]
    float2* Bb = sm + 2 * 128 * APADF2;   // [2][16][BPADF2]

    const int tid  = threadIdx.x;
    const int lane = tid & 31;
    const int w    = tid >> 5;
    const int wm   = w & 3;
    const int wn   = w >> 2;
    const int row0 = blockIdx.y * 128;
    const int col0 = blockIdx.x * 128;

    const int ktiles = (K + 15) >> 4;
    const int total  = ktiles * NSPLIT;

    float acc[2][8][4];
#pragma unroll
    for (int mt = 0; mt < 2; mt++)
#pragma unroll
        for (int nt = 0; nt < 8; nt++)
#pragma unroll
            for (int i = 0; i < 4; i++) acc[mt][nt][i] = 0.f;

    auto stage = [&](int t, int b) {
        const int sI = (NSPLIT == 1) ? 0 : (t / ktiles);
        const int kt = (NSPLIT == 1) ? t : (t % ktiles);
        const int k0 = kt << 4;
        const float2* Ap = A + (size_t)sI * aStep;
        // A: 128 rows x 16 k float2 = 1024 16B chunks
#pragma unroll
        for (int i = 0; i < 4; i++) {
            int ch = tid + (i << 8);
            int row = ch >> 3, kp = (ch & 7) << 1;
            int gr = row0 + row, gk = k0 + kp;
            int sb = (gr < M && gk < K) ? 16 : 0;
            const float2* src = sb ? (Ap + (size_t)gr * lda + gk) : Ap;
            cpa16(&Ab[(b * 128 + row) * APADF2 + kp], src, sb);
        }
        if (NSPLIT == 1) {
#pragma unroll
            for (int i = 0; i < 4; i++) {
                int ch = tid + (i << 8);
                int krow = ch >> 6, cp = (ch & 63) << 1;
                int gk = k0 + krow, gc = col0 + cp;
                int sb = (gk < K && gc < N) ? 16 : 0;
                const float2* src = sb ? (B + (size_t)gk * ldb + gc) : B;
                cpa16(&Bb[(b * 16 + krow) * BPADF2 + cp], src, sb);
            }
        } else {
#pragma unroll
            for (int i = 0; i < 8; i++) {
                int ch = tid + (i << 8);
                int krow = ch >> 7, c = ch & 127;
                int gk = k0 + krow, gc = col0 + c;
                int sb = (gk < K && gc < N) ? 8 : 0;
                const float2* src = sb ? (B + (size_t)gk * ldb + gc + sI) : B;
                cpa8(&Bb[(b * 16 + krow) * BPADF2 + c], src, sb);
            }
        }
        asm volatile("cp.async.commit_group;");
    };

    stage(0, 0);
    asm volatile("cp.async.wait_group 0;");
    __syncthreads();

    int buf = 0;
    const int r_  = lane >> 2;
    const int cc_ = lane & 3;

    for (int t = 0; t < total; t++) {
        if (t + 1 < total) stage(t + 1, buf ^ 1);

#pragma unroll
        for (int k2 = 0; k2 < 2; k2++) {
            unsigned ah[2][4], al[2][4];
#pragma unroll
            for (int mt = 0; mt < 2; mt++) {
                const float2* Ar = &Ab[(buf * 128 + wm * 32 + mt * 16) * APADF2];
                float2 v0 = Ar[(r_    ) * APADF2 + k2 * 8 + cc_];
                float2 v1 = Ar[(r_ + 8) * APADF2 + k2 * 8 + cc_];
                float2 v2 = Ar[(r_    ) * APADF2 + k2 * 8 + cc_ + 4];
                float2 v3 = Ar[(r_ + 8) * APADF2 + k2 * 8 + cc_ + 4];
                ah[mt][0] = __float_as_uint(v0.x); al[mt][0] = __float_as_uint(v0.y);
                ah[mt][1] = __float_as_uint(v1.x); al[mt][1] = __float_as_uint(v1.y);
                ah[mt][2] = __float_as_uint(v2.x); al[mt][2] = __float_as_uint(v2.y);
                ah[mt][3] = __float_as_uint(v3.x); al[mt][3] = __float_as_uint(v3.y);
            }
#pragma unroll
            for (int nt = 0; nt < 8; nt++) {
                int cb = wn * 64 + nt * 8 + r_;
                int kb = k2 * 8 + cc_;
                float2 g0 = Bb[(buf * 16 + kb    ) * BPADF2 + cb];
                float2 g1 = Bb[(buf * 16 + kb + 4) * BPADF2 + cb];
                unsigned bh[2], bl[2];
                bh[0] = __float_as_uint(g0.x); bl[0] = __float_as_uint(g0.y);
                bh[1] = __float_as_uint(g1.x); bl[1] = __float_as_uint(g1.y);
#pragma unroll
                for (int mt = 0; mt < 2; mt++) {
                    mma_tf32(acc[mt][nt], ah[mt], bl);
                    mma_tf32(acc[mt][nt], al[mt], bh);
                    mma_tf32(acc[mt][nt], ah[mt], bh);
                }
            }
        }

        if (t + 1 < total) asm volatile("cp.async.wait_group 0;");
        __syncthreads();
        buf ^= 1;
    }

    // ---- epilogue ----
    const int gid = lane >> 2, tig = lane & 3;
#pragma unroll
    for (int mt = 0; mt < 2; mt++) {
#pragma unroll
        for (int half = 0; half < 2; half++) {
            int r = row0 + wm * 32 + mt * 16 + half * 8 + gid;
            if (r >= M) continue;
            float rb = (BMODE == 3) ? bias[r] : 0.f;
#pragma unroll
            for (int nt = 0; nt < 8; nt++) {
                int c = col0 + wn * 64 + nt * 8 + tig * 2;
                if (c >= N) continue;
                float v0 = acc[mt][nt][half * 2 + 0];
                float v1 = acc[mt][nt][half * 2 + 1];
                if (BMODE == 1)      { v0 += bias[c]; v1 += bias[c + 1]; }
                else if (BMODE == 3) { v0 += rb; v1 += rb; }
                float2 o; o.x = v0; o.y = v1;
                *(float2*)(C + (size_t)r * ldc + c) = o;
            }
        }
    }
}

static void run_gemm(const float2* A, const float2* B, float* C, const float* bias,
                     int M, int N, int K, int lda, int ldb, int ldc,
                     int bmode, int nsplit, int aStep)
{
    dim3 grid((N + 127) / 128, (M + 127) / 128);
    if (nsplit == 3) {
        cudaFuncSetAttribute(gemm_tc<3,3>, cudaFuncAttributeMaxDynamicSharedMemorySize, SMEM_GEMM);
        gemm_tc<3,3><<<grid,256,SMEM_GEMM>>>(A,B,C,bias,M,N,K,lda,ldb,ldc,aStep);
    } else {
        switch (bmode) {
            case 0:
                cudaFuncSetAttribute(gemm_tc<0,1>, cudaFuncAttributeMaxDynamicSharedMemorySize, SMEM_GEMM);
                gemm_tc<0,1><<<grid,256,SMEM_GEMM>>>(A,B,C,bias,M,N,K,lda,ldb,ldc,aStep); break;
            case 1:
                cudaFuncSetAttribute(gemm_tc<1,1>, cudaFuncAttributeMaxDynamicSharedMemorySize, SMEM_GEMM);
                gemm_tc<1,1><<<grid,256,SMEM_GEMM>>>(A,B,C,bias,M,N,K,lda,ldb,ldc,aStep); break;
            default:
                cudaFuncSetAttribute(gemm_tc<3,1>, cudaFuncAttributeMaxDynamicSharedMemorySize, SMEM_GEMM);
                gemm_tc<3,1><<<grid,256,SMEM_GEMM>>>(A,B,C,bias,M,N,K,lda,ldb,ldc,aStep); break;
        }
    }
}

// GRU gates: writes hout raw + hi/lo
__global__ void gates_k(const float* __restrict__ hin, float* __restrict__ hout,
                        float2* __restrict__ houthl) {
    int idx = blockIdx.x * blockDim.x + threadIdx.x;
    if (idx < NTOT * 50) {
        int n = idx / 50, q = idx % 50;
        size_t g4 = (size_t)n * 150 + q;
        const float4* gi4 = (const float4*)d_gi;
        const float4* gh4 = (const float4*)d_gh;
        float4 ir4 = gi4[g4],        hr4 = gh4[g4];
        float4 iz4 = gi4[g4 + 50],   hz4 = gh4[g4 + 50];
        float4 in4 = gi4[g4 + 100],  hn4 = gh4[g4 + 100];
        float4 h4  = ((const float4*)hin)[(size_t)n * 50 + q];
        float4 o;
        {
            float r = 1.f / (1.f + __expf(-(ir4.x + hr4.x)));
            float z = 1.f / (1.f + __expf(-(iz4.x + hz4.x)));
            float nn = tanhf(in4.x + r * hn4.x);
            o.x = (1.f - z) * nn + z * h4.x;
        }
        {
            float r = 1.f / (1.f + __expf(-(ir4.y + hr4.y)));
            float z = 1.f / (1.f + __expf(-(iz4.y + hz4.y)));
            float nn = tanhf(in4.y + r * hn4.y);
            o.y = (1.f - z) * nn + z * h4.y;
        }
        {
            float r = 1.f / (1.f + __expf(-(ir4.z + hr4.z)));
            float z = 1.f / (1.f + __expf(-(iz4.z + hz4.z)));
            float nn = tanhf(in4.z + r * hn4.z);
            o.z = (1.f - z) * nn + z * h4.z;
        }
        {
            float r = 1.f / (1.f + __expf(-(ir4.w + hr4.w)));
            float z = 1.f / (1.f + __expf(-(iz4.w + hz4.w)));
            float nn = tanhf(in4.w + r * hn4.w);
            o.w = (1.f - z) * nn + z * h4.w;
        }
        ((float4*)hout)[(size_t)n * 50 + q] = o;
        float2 s0 = spl(o.x), s1 = spl(o.y), s2 = spl(o.z), s3 = spl(o.w);
        float4 p0; p0.x = s0.x; p0.y = s0.y; p0.z = s1.x; p0.w = s1.y;
        float4 p1; p1.x = s2.x; p1.y = s2.y; p1.z = s3.x; p1.w = s3.y;
        float4* oh = (float4*)houthl;
        oh[((size_t)n * 50 + q) * 2]     = p0;
        oh[((size_t)n * 50 + q) * 2 + 1] = p1;
    }
}

// in [G][C] raw -> out [C][G] hi/lo
__global__ void transpose_hl_k(const float* __restrict__ in, float2* __restrict__ out,
                               int G, int C) {
    __shared__ float tile[32][33];
    int c0 = blockIdx.x * 32;
    int g0 = blockIdx.y * 32;
    int c = c0 + threadIdx.x;
#pragma unroll
    for (int j = 0; j < 32; j += 8) {
        int g = g0 + threadIdx.y + j;
        tile[threadIdx.y + j][threadIdx.x] = (c < C && g < G) ? in[(size_t)g * C + c] : 0.f;
    }
    __syncthreads();
    int g = g0 + threadIdx.x;
#pragma unroll
    for (int j = 0; j < 32; j += 8) {
        int cc = c0 + threadIdx.y + j;
        if (cc < C && g < G) out[(size_t)cc * G + g] = spl(tile[threadIdx.x][threadIdx.y + j]);
    }
}

__global__ void pool3_k(const float* __restrict__ in, float2* __restrict__ out, int C) {
    int idx = blockIdx.x * blockDim.x + threadIdx.x;
    if (idx < C * GP1) {
        int co = idx / GP1;
        int r = idx % GP1;
        int b = r / P1, p = r % P1;
        int base = co * NTOT + b * NPG + 2 * p;
        float m = fmaxf(fmaxf(in[base], in[base + 1]), in[base + 2]);
        out[idx] = spl(fmaxf(m, 0.f));
    }
}

__global__ void pool2_k(const float* __restrict__ in, float2* __restrict__ out, int C) {
    int idx = blockIdx.x * blockDim.x + threadIdx.x;
    if (idx < C * GP2) {
        int co = idx / GP2;
        int r = idx % GP2;
        int b = r / P2, p = r % P2;
        int base = co * GP1 + b * P1 + 2 * p;
        out[idx] = spl(fmaxf(fmaxf(in[base], in[base + 1]), 0.f));
    }
}

__global__ void final_k(const float* __restrict__ by, const float* __restrict__ bz,
                        float* __restrict__ out) {
    __shared__ float red[NCLS][128];
    int b = blockIdx.x;
    int tid = threadIdx.x;
    float part[NCLS] = {};
    for (int p = tid; p < P2; p += blockDim.x) {
        int base = b * P2 + p;
#pragma unroll
        for (int cl = 0; cl < NCLS; cl++) {
            float y = d_ly[cl * GP2 + base] + by[cl];
            float z = d_lz[cl * GP2 + base] + bz[cl];
            part[cl] += y * z;
        }
    }
#pragma unroll
    for (int cl = 0; cl < NCLS; cl++) red[cl][tid] = part[cl];
    __syncthreads();
    if (tid == 0) {
        float v[NCLS];
        for (int cl = 0; cl < NCLS; cl++) {
            float s = 0.f;
            for (int i = 0; i < 128; i++) s += red[cl][i];
            v[cl] = s / (float)P2;
        }
        float mx = v[0];
        for (int cl = 1; cl < NCLS; cl++) mx = fmaxf(mx, v[cl]);
        float se = 0.f;
        for (int cl = 0; cl < NCLS; cl++) { v[cl] = __expf(v[cl] - mx); se += v[cl]; }
        for (int cl = 0; cl < NCLS; cl++) out[b * NCLS + cl] = v[cl] / se;
    }
}

// ----------------------------- host side ----------------------------------
static void* getsym(const void* s) {
    void* p = nullptr;
    cudaGetSymbolAddress(&p, s);
    return p;
}

extern "C" void kernel_launch(void* const* d_in, const int* in_sizes, int n_in,
                              void* d_out, int out_size)
{
    const float* features = (const float*)d_in[0];
    const int*   esrc     = (const int*)  d_in[1];
    const int*   edst     = (const int*)  d_in[2];
    const int*   etyp     = (const int*)  d_in[3];
    const float* etype_W  = (const float*)d_in[4];
    const float* etype_b  = (const float*)d_in[5];
    const float* W_ih     = (const float*)d_in[6];
    const float* b_ih     = (const float*)d_in[7];
    const float* W_hh     = (const float*)d_in[8];
    const float* b_hh     = (const float*)d_in[9];
    const float* conv1_w  = (const float*)d_in[10];
    const float* conv1_b  = (const float*)d_in[11];
    const float* conv2_w  = (const float*)d_in[12];
    const float* conv2_b  = (const float*)d_in[13];
    const float* convc1_w = (const float*)d_in[14];
    const float* convc1_b = (const float*)d_in[15];
    const float* convc2_w = (const float*)d_in[16];
    const float* convc2_b = (const float*)d_in[17];
    const float* mlp_y_w  = (const float*)d_in[18];
    const float* mlp_y_b  = (const float*)d_in[19];
    const float* mlp_z_w  = (const float*)d_in[20];
    const float* mlp_z_b  = (const float*)d_in[21];

    float*  p_h0    = (float*) getsym(d_h0);
    float*  p_h1    = (float*) getsym(d_h1);
    float2* p_h0hl  = (float2*)getsym(d_h0hl);
    float2* p_h1hl  = (float2*)getsym(d_h1hl);
    float2* p_ahl   = (float2*)getsym(d_ahl);
    float*  p_Ht    = (float*) getsym(d_Ht);
    float*  p_gi    = (float*) getsym(d_gi);
    float*  p_gh    = (float*) getsym(d_gh);
    float2* p_Wst2  = (float2*)getsym(d_Wst2);
    float2* p_WihT  = (float2*)getsym(d_WihT);
    float2* p_WhhT  = (float2*)getsym(d_WhhT);
    int*    p_deg4  = (int*)   getsym(d_deg4);
    float2* p_cThl  = (float2*)getsym(d_cThl);
    float2* p_w1yhl = (float2*)getsym(d_w1yhl);
    float2* p_w1zhl = (float2*)getsym(d_w1zhl);
    float2* p_w2yhl = (float2*)getsym(d_w2yhl);
    float2* p_w2zhl = (float2*)getsym(d_w2zhl);
    float2* p_wmyhl = (float2*)getsym(d_wmyhl);
    float2* p_wmzhl = (float2*)getsym(d_wmzhl);
    float*  p_y1    = (float*) getsym(d_y1);
    float*  p_z1    = (float*) getsym(d_z1);
    float2* p_yp1hl = (float2*)getsym(d_yp1hl);
    float2* p_zp1hl = (float2*)getsym(d_zp1hl);
    float*  p_y2    = (float*) getsym(d_y2);
    float*  p_z2    = (float*) getsym(d_z2);
    float2* p_yp2hl = (float2*)getsym(d_yp2hl);
    float2* p_zp2hl = (float2*)getsym(d_zp2hl);
    float*  p_ly    = (float*) getsym(d_ly);
    float*  p_lz    = (float*) getsym(d_lz);

    const int T = 256;

    // ---- first launches: keep gh GEMM at profiler slot 3 ----
    init_h_k<<<(NTOT * ODIM + T - 1) / T, T>>>(features);                    // 0
    pack_T_hl_k<<<(ODIM * H3 + T - 1) / T, T>>>(W_hh, p_WhhT);               // 1
    pack_T_hl_k<<<(ODIM * H3 + T - 1) / T, T>>>(W_ih, p_WihT);               // 2
    run_gemm(p_h0hl, p_WhhT, p_gh, b_hh, NTOT, H3, ODIM, ODIM, H3, H3, 1, 1, 0); // 3

    // ---- rest of setup ----
    zero_int_k<<<(NTOT * 4 + T - 1) / T, T>>>(p_deg4, NTOT * 4);
    hist_k<<<(EDGES + T - 1) / T, T>>>(edst, etyp);
    scan_k<<<1, 1024>>>();
    chunk_hist_k<<<dim3(NCHK, BATCH), 512>>>(edst);
    chunk_scan_k<<<(NTOT + T - 1) / T, T>>>();
    scatter_k<<<dim3(NCHK, BATCH), 512>>>(esrc, edst, etyp);
    pack_wstack2_k<<<(4 * ODIM * ODIM + T - 1) / T, T>>>(etype_W);
    pack_conv_hl_k<<<(3 * ODIM * ODIM + T - 1) / T, T>>>(conv1_w, p_w1yhl, ODIM);
    pack_conv_hl_k<<<(3 * CDIM * CDIM + T - 1) / T, T>>>(convc1_w, p_w1zhl, CDIM);
    split_mat_k<<<(ODIM * ODIM + T - 1) / T, T>>>(conv2_w, p_w2yhl, ODIM * ODIM);
    split_mat_k<<<(CDIM * CDIM + T - 1) / T, T>>>(convc2_w, p_w2zhl, CDIM * CDIM);
    split_mat_k<<<(NCLS * ODIM + T - 1) / T, T>>>(mlp_y_w, p_wmyhl, NCLS * ODIM);
    split_mat_k<<<(NCLS * CDIM + T - 1) / T, T>>>(mlp_z_w, p_wmzhl, NCLS * CDIM);
    nodebias_k<<<(NTOT * ODIM + T - 1) / T, T>>>(etype_b);

    // ---- GGNN: 8 steps ----
    for (int s = 0; s < 8; s++) {
        const float*  hin    = (s & 1) ? p_h1 : p_h0;
        float*        hout   = (s & 1) ? p_h0 : p_h1;
        const float2* hinhl  = (s & 1) ? p_h1hl : p_h0hl;
        float2*       houthl = (s & 1) ? p_h0hl : p_h1hl;
        // Ht[n][t*200+o] = sum_d h[n][d] W_t[o][d]
        run_gemm(hinhl, p_Wst2, p_Ht, nullptr, NTOT, 4 * ODIM, ODIM, ODIM, 4 * ODIM, 4 * ODIM, 0, 1, 0);
        spmm_k<<<NTOT, 256>>>(p_Ht);
        run_gemm(p_ahl, p_WihT, p_gi, b_ih, NTOT, H3, ODIM, ODIM, H3, H3, 1, 1, 0);
        if (s > 0)
            run_gemm(hinhl, p_WhhT, p_gh, b_hh, NTOT, H3, ODIM, ODIM, H3, H3, 1, 1, 0);
        gates_k<<<(NTOT * 50 + T - 1) / T, T>>>(hin, hout, houthl);
    }
    float* p_hf = p_h0;

    // ---- readout ----
    transpose_hl_k<<<dim3((ODIM + 31) / 32, NTOT / 32), dim3(32, 8)>>>(p_hf, p_cThl, NTOT, ODIM);
    transpose_hl_k<<<dim3((IDIM + 31) / 32, NTOT / 32), dim3(32, 8)>>>(features, p_cThl + (size_t)ODIM * NTOT, NTOT, IDIM);

    run_gemm(p_w1yhl, p_cThl, p_y1, conv1_b, ODIM, NTOT, ODIM, ODIM, NTOT, NTOT, 3, 3, ODIM * ODIM);
    pool3_k<<<(ODIM * GP1 + T - 1) / T, T>>>(p_y1, p_yp1hl, ODIM);
    run_gemm(p_w2yhl, p_yp1hl, p_y2, conv2_b, ODIM, GP1, ODIM, ODIM, GP1, GP1, 3, 1, 0);
    pool2_k<<<(ODIM * GP2 + T - 1) / T, T>>>(p_y2, p_yp2hl, ODIM);

    run_gemm(p_w1zhl, p_cThl, p_z1, convc1_b, CDIM, NTOT, CDIM, CDIM, NTOT, NTOT, 3, 3, CDIM * CDIM);
    pool3_k<<<(CDIM * GP1 + T - 1) / T, T>>>(p_z1, p_zp1hl, CDIM);
    run_gemm(p_w2zhl, p_zp1hl, p_z2, convc2_b, CDIM, GP1, CDIM, CDIM, GP1, GP1, 3, 1, 0);
    pool2_k<<<(CDIM * GP2 + T - 1) / T, T>>>(p_z2, p_zp2hl, CDIM);

    run_gemm(p_wmyhl, p_yp2hl, p_ly, nullptr, NCLS, GP2, ODIM, ODIM, GP2, GP2, 0, 1, 0);
    run_gemm(p_wmzhl, p_zp2hl, p_lz, nullptr, NCLS, GP2, CDIM, CDIM, GP2, GP2, 0, 1, 0);

    final_k<<<BATCH, 128>>>(mlp_y_b, mlp_z_b, (float*)d_out);
}

// round 6
// speedup vs baseline: 1.1130x; 1.1130x over previous
#include <cuda_runtime.h>

#define BATCH  64
#define NPG    512
#define NTOT   32768
#define EDGES  524288
#define EPG    8192
#define NCHK   16
#define ODIM   200
#define IDIM   100
#define H3     600
#define CDIM   300
#define P1     254
#define P2     127
#define GP1    16256
#define GP2    8128
#define NCLS   7

// ----------------------------- device scratch -----------------------------
__device__ float  d_h0[NTOT*ODIM];
__device__ float  d_h1[NTOT*ODIM];
__device__ float  d_a[NTOT*ODIM];
__device__ float  d_Ht[NTOT*4*ODIM];
__device__ float  d_gi[NTOT*H3];
__device__ float  d_gh[NTOT*H3];
__device__ float2 d_Wst2[ODIM*4*ODIM];     // [d][t*200+o] hi/lo
__device__ float2 d_WihT[ODIM*H3];
__device__ float2 d_WhhT[ODIM*H3];
__device__ float  d_nbias[NTOT*ODIM];
__device__ int    d_deg4[NTOT*4];
__device__ int    d_indptr[NTOT+1];
__device__ int    d_ccnt[NTOT*NCHK];
__device__ int    d_srcs[EDGES];
__device__ int    d_typs[EDGES];
__device__ float2 d_cThl[CDIM*NTOT + 64];
__device__ float2 d_w1yhl[3*ODIM*ODIM];
__device__ float2 d_w1zhl[3*CDIM*CDIM];
__device__ float2 d_w2yhl[ODIM*ODIM];
__device__ float2 d_w2zhl[CDIM*CDIM];
__device__ float2 d_wmyhl[NCLS*ODIM];
__device__ float2 d_wmzhl[NCLS*CDIM];
__device__ float  d_y1[ODIM*NTOT];
__device__ float  d_z1[CDIM*NTOT];
__device__ float2 d_yp1hl[ODIM*GP1];
__device__ float2 d_zp1hl[CDIM*GP1];
__device__ float  d_y2[ODIM*GP1];
__device__ float  d_z2[CDIM*GP1];
__device__ float2 d_yp2hl[ODIM*GP2];
__device__ float2 d_zp2hl[CDIM*GP2];
__device__ float  d_ly[NCLS*GP2];
__device__ float  d_lz[NCLS*GP2];

// ----------------------------- helpers ------------------------------------
__device__ __forceinline__ unsigned f2tf32(float f) {
    unsigned u;
    asm("cvt.rna.tf32.f32 %0, %1;" : "=r"(u) : "f"(f));
    return u;
}
__device__ __forceinline__ float2 spl(float f) {
    unsigned h = f2tf32(f);
    float hf = __uint_as_float(h);
    unsigned l = f2tf32(f - hf);
    return make_float2(hf, __uint_as_float(l));
}

// ----------------------------- setup kernels ------------------------------
__global__ void zero_int_k(int* p, int n) {
    int i = blockIdx.x * blockDim.x + threadIdx.x;
    if (i < n) p[i] = 0;
}

__global__ void hist_k(const int* __restrict__ edst, const int* __restrict__ etyp) {
    int e = blockIdx.x * blockDim.x + threadIdx.x;
    if (e < EDGES) atomicAdd(&d_deg4[edst[e] * 4 + etyp[e]], 1);
}

__global__ void scan_k() {
    __shared__ int ssum[1024];
    int t = threadIdx.x;
    int loc[32];
    int s = 0;
#pragma unroll
    for (int i = 0; i < 32; i++) {
        int n = t * 32 + i;
        int d = d_deg4[n*4] + d_deg4[n*4+1] + d_deg4[n*4+2] + d_deg4[n*4+3];
        loc[i] = s; s += d;
    }
    ssum[t] = s;
    __syncthreads();
    if (t == 0) {
        int acc = 0;
        for (int i = 0; i < 1024; i++) { int v = ssum[i]; ssum[i] = acc; acc += v; }
        d_indptr[NTOT] = acc;
    }
    __syncthreads();
    int off = ssum[t];
#pragma unroll
    for (int i = 0; i < 32; i++) d_indptr[t * 32 + i] = off + loc[i];
}

__global__ void chunk_hist_k(const int* __restrict__ edst) {
    __shared__ int h[NPG];
    int g = blockIdx.y, c = blockIdx.x;
    h[threadIdx.x] = 0;
    __syncthreads();
    int e = g * EPG + c * 512 + threadIdx.x;
    atomicAdd(&h[edst[e] - g * NPG], 1);
    __syncthreads();
    d_ccnt[(g * NPG + threadIdx.x) * NCHK + c] = h[threadIdx.x];
}

__global__ void chunk_scan_k() {
    int n = blockIdx.x * blockDim.x + threadIdx.x;
    if (n < NTOT) {
        int base = d_indptr[n];
#pragma unroll
        for (int c = 0; c < NCHK; c++) {
            int v = d_ccnt[n * NCHK + c];
            d_ccnt[n * NCHK + c] = base;
            base += v;
        }
    }
}

__global__ void scatter_k(const int* __restrict__ esrc, const int* __restrict__ edst,
                          const int* __restrict__ etyp) {
    __shared__ int sd[512];
    int g = blockIdx.y, c = blockIdx.x;
    int e = g * EPG + c * 512 + threadIdx.x;
    int dl = edst[e] - g * NPG;
    sd[threadIdx.x] = dl;
    __syncthreads();
    int rank = 0;
    for (int i = 0; i < threadIdx.x; i++) rank += (sd[i] == dl);
    int pos = d_ccnt[(g * NPG + dl) * NCHK + c] + rank;
    d_srcs[pos] = esrc[e];
    d_typs[pos] = etyp[e];
}

// etype_W [4][o][d] -> Wst2[d][t*200+o] hi/lo
__global__ void pack_wstack2_k(const float* __restrict__ W) {
    int idx = blockIdx.x * blockDim.x + threadIdx.x;
    if (idx < 4 * ODIM * ODIM) {
        int o = idx % ODIM;
        int d = (idx / ODIM) % ODIM;
        int t = idx / (ODIM * ODIM);
        d_Wst2[d * (4 * ODIM) + t * ODIM + o] = spl(W[(t * ODIM + o) * ODIM + d]);
    }
}

// W[600][200] -> out[200][600] hi/lo
__global__ void pack_T_hl_k(const float* __restrict__ W, float2* __restrict__ out) {
    int idx = blockIdx.x * blockDim.x + threadIdx.x;
    if (idx < ODIM * H3) {
        int j = idx % H3;
        int d = idx / H3;
        out[d * H3 + j] = spl(W[j * ODIM + d]);
    }
}

// conv weight [C][C][3] -> [k][co][ci] hi/lo
__global__ void pack_conv_hl_k(const float* __restrict__ W, float2* __restrict__ out, int C) {
    int idx = blockIdx.x * blockDim.x + threadIdx.x;
    if (idx < 3 * C * C) {
        int ci = idx % C;
        int co = (idx / C) % C;
        int k  = idx / (C * C);
        out[idx] = spl(W[(co * C + ci) * 3 + k]);
    }
}

__global__ void split_mat_k(const float* __restrict__ in, float2* __restrict__ out, int n) {
    int i = blockIdx.x * blockDim.x + threadIdx.x;
    if (i < n) out[i] = spl(in[i]);
}

__global__ void init_h_k(const float* __restrict__ feat) {
    int idx = blockIdx.x * blockDim.x + threadIdx.x;
    if (idx < NTOT * ODIM) {
        int d = idx % ODIM;
        int n = idx / ODIM;
        d_h0[idx] = (d < IDIM) ? feat[n * IDIM + d] : 0.f;
    }
}

__global__ void nodebias_k(const float* __restrict__ eb) {
    int idx = blockIdx.x * blockDim.x + threadIdx.x;
    if (idx < NTOT * ODIM) {
        int o = idx % ODIM;
        int n = idx / ODIM;
        float s = 0.f;
#pragma unroll
        for (int t = 0; t < 4; t++) s += (float)d_deg4[n * 4 + t] * eb[t * ODIM + o];
        d_nbias[idx] = s;
    }
}

// a[n][o] = nbias[n][o] + sum_{edges->n} Ht[src][t*200+o]
__global__ void spmm_k(const float* __restrict__ Ht) {
    __shared__ int so[128];
    int n = blockIdx.x;
    int tid = threadIdx.x;
    int beg = d_indptr[n], end = d_indptr[n + 1];
    float a = 0.f;
    for (int base = beg; base < end; base += 128) {
        int cnt = min(128, end - base);
        if (tid < cnt) so[tid] = d_srcs[base + tid] * (4 * ODIM) + d_typs[base + tid] * ODIM;
        __syncthreads();
        if (tid < ODIM) {
            for (int e = 0; e < cnt; e++) a += Ht[so[e] + tid];
        }
        __syncthreads();
    }
    if (tid < ODIM) {
        int o = n * ODIM + tid;
        d_a[o] = a + d_nbias[o];
    }
}

// --------------------------- tensor-core GEMM ------------------------------
// 3xTF32. B always pre-split float2 hi/lo. A raw fp32 (ASPL=0, in-reg split)
// or pre-split float2 (ASPL=1). C[M,N] = sum_s A_s*B_s (+bias).
// BMODE: 0 none, 1 bias[col], 3 bias[row]. lda in A elements, ldb in float2.

__device__ __forceinline__ void mma_tf32(float* d, const unsigned* a, const unsigned* b) {
    asm volatile(
        "mma.sync.aligned.m16n8k8.row.col.f32.tf32.tf32.f32 "
        "{%0,%1,%2,%3}, {%4,%5,%6,%7}, {%8,%9}, {%0,%1,%2,%3};"
        : "+f"(d[0]), "+f"(d[1]), "+f"(d[2]), "+f"(d[3])
        : "r"(a[0]), "r"(a[1]), "r"(a[2]), "r"(a[3]), "r"(b[0]), "r"(b[1]));
}
__device__ __forceinline__ void cpa16(void* dst, const void* src, int sb) {
    unsigned sa = (unsigned)__cvta_generic_to_shared(dst);
    asm volatile("cp.async.cg.shared.global [%0], [%1], 16, %2;" :: "r"(sa), "l"(src), "r"(sb));
}
__device__ __forceinline__ void cpa8(void* dst, const void* src, int sb) {
    unsigned sa = (unsigned)__cvta_generic_to_shared(dst);
    asm volatile("cp.async.ca.shared.global [%0], [%1], 8, %2;" :: "r"(sa), "l"(src), "r"(sb));
}

#define APAD   20
#define BPADF2 132

template<int BMODE, int NSPLIT, int ASPL>
__global__ __launch_bounds__(256, 2) void gemm_tc(
    const void* __restrict__ Av, const float2* __restrict__ B,
    float* __restrict__ C, const float* __restrict__ bias,
    int M, int N, int K, int lda, int ldb, int ldc, int aStep)
{
    extern __shared__ char smraw[];
    constexpr int AELT = ASPL ? 8 : 4;                 // bytes per A element
    constexpr int ABUF = 128 * APAD * AELT;            // bytes per A buffer
    float*  Af  = (float*)smraw;
    float2* Af2 = (float2*)smraw;
    float2* Bb  = (float2*)(smraw + 2 * ABUF);         // [2][16][BPADF2]

    const int tid  = threadIdx.x;
    const int lane = tid & 31;
    const int w    = tid >> 5;
    const int wm   = w & 3;
    const int wn   = w >> 2;
    const int row0 = blockIdx.y * 128;
    const int col0 = blockIdx.x * 128;

    const int ktiles = (K + 15) >> 4;
    const int total  = ktiles * NSPLIT;

    float acc[2][8][4];
#pragma unroll
    for (int mt = 0; mt < 2; mt++)
#pragma unroll
        for (int nt = 0; nt < 8; nt++)
#pragma unroll
            for (int i = 0; i < 4; i++) acc[mt][nt][i] = 0.f;

    auto stage = [&](int t, int b) {
        const int sI = (NSPLIT == 1) ? 0 : (t / ktiles);
        const int kt = (NSPLIT == 1) ? t : (t % ktiles);
        const int k0 = kt << 4;
        if (ASPL == 0) {
            const float* Ap = (const float*)Av + (size_t)sI * aStep;
#pragma unroll
            for (int i = 0; i < 2; i++) {
                int ch = tid + (i << 8);
                int row = ch >> 2, part = (ch & 3) << 2;
                int gr = row0 + row, gk = k0 + part;
                int sb = (gr < M && gk < K) ? 16 : 0;
                const float* src = sb ? (Ap + (size_t)gr * lda + gk) : Ap;
                cpa16(&Af[(size_t)b * (ABUF / 4) + row * APAD + part], src, sb);
            }
        } else {
            const float2* Ap = (const float2*)Av + (size_t)sI * aStep;
#pragma unroll
            for (int i = 0; i < 4; i++) {
                int ch = tid + (i << 8);
                int row = ch >> 3, kp = (ch & 7) << 1;
                int gr = row0 + row, gk = k0 + kp;
                int sb = (gr < M && gk < K) ? 16 : 0;
                const float2* src = sb ? (Ap + (size_t)gr * lda + gk) : Ap;
                cpa16(&Af2[(size_t)b * (ABUF / 8) + row * APAD + kp], src, sb);
            }
        }
        if (NSPLIT == 1) {
#pragma unroll
            for (int i = 0; i < 4; i++) {
                int ch = tid + (i << 8);
                int krow = ch >> 6, cp = (ch & 63) << 1;
                int gk = k0 + krow, gc = col0 + cp;
                int sb = (gk < K && gc < N) ? 16 : 0;
                const float2* src = sb ? (B + (size_t)gk * ldb + gc) : B;
                cpa16(&Bb[(b * 16 + krow) * BPADF2 + cp], src, sb);
            }
        } else {
#pragma unroll
            for (int i = 0; i < 8; i++) {
                int ch = tid + (i << 8);
                int krow = ch >> 7, c = ch & 127;
                int gk = k0 + krow, gc = col0 + c;
                int sb = (gk < K && gc < N) ? 8 : 0;
                const float2* src = sb ? (B + (size_t)gk * ldb + gc + sI) : B;
                cpa8(&Bb[(b * 16 + krow) * BPADF2 + c], src, sb);
            }
        }
        asm volatile("cp.async.commit_group;");
    };

    stage(0, 0);
    asm volatile("cp.async.wait_group 0;");
    __syncthreads();

    int buf = 0;
    const int r_  = lane >> 2;
    const int cc_ = lane & 3;

    for (int t = 0; t < total; t++) {
        if (t + 1 < total) stage(t + 1, buf ^ 1);

#pragma unroll
        for (int k2 = 0; k2 < 2; k2++) {
            unsigned ah[2][4], al[2][4];
#pragma unroll
            for (int mt = 0; mt < 2; mt++) {
                int rb = wm * 32 + mt * 16;
                if (ASPL == 0) {
                    const float* Ar = Af + (size_t)buf * (ABUF / 4);
                    float f0 = Ar[(rb + r_    ) * APAD + k2 * 8 + cc_];
                    float f1 = Ar[(rb + r_ + 8) * APAD + k2 * 8 + cc_];
                    float f2 = Ar[(rb + r_    ) * APAD + k2 * 8 + cc_ + 4];
                    float f3 = Ar[(rb + r_ + 8) * APAD + k2 * 8 + cc_ + 4];
                    ah[mt][0] = f2tf32(f0); al[mt][0] = f2tf32(f0 - __uint_as_float(ah[mt][0]));
                    ah[mt][1] = f2tf32(f1); al[mt][1] = f2tf32(f1 - __uint_as_float(ah[mt][1]));
                    ah[mt][2] = f2tf32(f2); al[mt][2] = f2tf32(f2 - __uint_as_float(ah[mt][2]));
                    ah[mt][3] = f2tf32(f3); al[mt][3] = f2tf32(f3 - __uint_as_float(ah[mt][3]));
                } else {
                    const float2* Ar = Af2 + (size_t)buf * (ABUF / 8);
                    float2 v0 = Ar[(rb + r_    ) * APAD + k2 * 8 + cc_];
                    float2 v1 = Ar[(rb + r_ + 8) * APAD + k2 * 8 + cc_];
                    float2 v2 = Ar[(rb + r_    ) * APAD + k2 * 8 + cc_ + 4];
                    float2 v3 = Ar[(rb + r_ + 8) * APAD + k2 * 8 + cc_ + 4];
                    ah[mt][0] = __float_as_uint(v0.x); al[mt][0] = __float_as_uint(v0.y);
                    ah[mt][1] = __float_as_uint(v1.x); al[mt][1] = __float_as_uint(v1.y);
                    ah[mt][2] = __float_as_uint(v2.x); al[mt][2] = __float_as_uint(v2.y);
                    ah[mt][3] = __float_as_uint(v3.x); al[mt][3] = __float_as_uint(v3.y);
                }
            }
#pragma unroll
            for (int nt = 0; nt < 8; nt++) {
                int cb = wn * 64 + nt * 8 + r_;
                int kb = k2 * 8 + cc_;
                float2 g0 = Bb[(buf * 16 + kb    ) * BPADF2 + cb];
                float2 g1 = Bb[(buf * 16 + kb + 4) * BPADF2 + cb];
                unsigned bh[2], bl[2];
                bh[0] = __float_as_uint(g0.x); bl[0] = __float_as_uint(g0.y);
                bh[1] = __float_as_uint(g1.x); bl[1] = __float_as_uint(g1.y);
#pragma unroll
                for (int mt = 0; mt < 2; mt++) {
                    mma_tf32(acc[mt][nt], ah[mt], bl);
                    mma_tf32(acc[mt][nt], al[mt], bh);
                    mma_tf32(acc[mt][nt], ah[mt], bh);
                }
            }
        }

        if (t + 1 < total) asm volatile("cp.async.wait_group 0;");
        __syncthreads();
        buf ^= 1;
    }

    // ---- epilogue ----
    const int gid = lane >> 2, tig = lane & 3;
#pragma unroll
    for (int mt = 0; mt < 2; mt++) {
#pragma unroll
        for (int half = 0; half < 2; half++) {
            int r = row0 + wm * 32 + mt * 16 + half * 8 + gid;
            if (r >= M) continue;
            float rb = (BMODE == 3) ? bias[r] : 0.f;
#pragma unroll
            for (int nt = 0; nt < 8; nt++) {
                int c = col0 + wn * 64 + nt * 8 + tig * 2;
                if (c >= N) continue;
                float v0 = acc[mt][nt][half * 2 + 0];
                float v1 = acc[mt][nt][half * 2 + 1];
                if (BMODE == 1)      { v0 += bias[c]; v1 += bias[c + 1]; }
                else if (BMODE == 3) { v0 += rb; v1 += rb; }
                float2 o; o.x = v0; o.y = v1;
                *(float2*)(C + (size_t)r * ldc + c) = o;
            }
        }
    }
}

#define SMEM_A0 (2 * 128 * APAD * 4 + 2 * 16 * BPADF2 * 8)
#define SMEM_A1 (2 * 128 * APAD * 8 + 2 * 16 * BPADF2 * 8)

template<int BMODE, int NSPLIT, int ASPL>
static void launch_gemm(const void* A, const float2* B, float* C, const float* bias,
                        int M, int N, int K, int lda, int ldb, int ldc, int aStep)
{
    constexpr int SM = ASPL ? SMEM_A1 : SMEM_A0;
    cudaFuncSetAttribute(gemm_tc<BMODE, NSPLIT, ASPL>,
                         cudaFuncAttributeMaxDynamicSharedMemorySize, SM);
    dim3 grid((N + 127) / 128, (M + 127) / 128);
    gemm_tc<BMODE, NSPLIT, ASPL><<<grid, 256, SM>>>(A, B, C, bias, M, N, K, lda, ldb, ldc, aStep);
}

// GRU gates (raw in/out)
__global__ void gates_k(const float* __restrict__ hin, float* __restrict__ hout) {
    int idx = blockIdx.x * blockDim.x + threadIdx.x;
    if (idx < NTOT * 50) {
        int n = idx / 50, q = idx % 50;
        size_t g4 = (size_t)n * 150 + q;
        const float4* gi4 = (const float4*)d_gi;
        const float4* gh4 = (const float4*)d_gh;
        float4 ir4 = gi4[g4],        hr4 = gh4[g4];
        float4 iz4 = gi4[g4 + 50],   hz4 = gh4[g4 + 50];
        float4 in4 = gi4[g4 + 100],  hn4 = gh4[g4 + 100];
        float4 h4  = ((const float4*)hin)[(size_t)n * 50 + q];
        float4 o;
        {
            float r = 1.f / (1.f + __expf(-(ir4.x + hr4.x)));
            float z = 1.f / (1.f + __expf(-(iz4.x + hz4.x)));
            float nn = tanhf(in4.x + r * hn4.x);
            o.x = (1.f - z) * nn + z * h4.x;
        }
        {
            float r = 1.f / (1.f + __expf(-(ir4.y + hr4.y)));
            float z = 1.f / (1.f + __expf(-(iz4.y + hz4.y)));
            float nn = tanhf(in4.y + r * hn4.y);
            o.y = (1.f - z) * nn + z * h4.y;
        }
        {
            float r = 1.f / (1.f + __expf(-(ir4.z + hr4.z)));
            float z = 1.f / (1.f + __expf(-(iz4.z + hz4.z)));
            float nn = tanhf(in4.z + r * hn4.z);
            o.z = (1.f - z) * nn + z * h4.z;
        }
        {
            float r = 1.f / (1.f + __expf(-(ir4.w + hr4.w)));
            float z = 1.f / (1.f + __expf(-(iz4.w + hz4.w)));
            float nn = tanhf(in4.w + r * hn4.w);
            o.w = (1.f - z) * nn + z * h4.w;
        }
        ((float4*)hout)[(size_t)n * 50 + q] = o;
    }
}

// in [G][C] raw -> out [C][G] hi/lo
__global__ void transpose_hl_k(const float* __restrict__ in, float2* __restrict__ out,
                               int G, int C) {
    __shared__ float tile[32][33];
    int c0 = blockIdx.x * 32;
    int g0 = blockIdx.y * 32;
    int c = c0 + threadIdx.x;
#pragma unroll
    for (int j = 0; j < 32; j += 8) {
        int g = g0 + threadIdx.y + j;
        tile[threadIdx.y + j][threadIdx.x] = (c < C && g < G) ? in[(size_t)g * C + c] : 0.f;
    }
    __syncthreads();
    int g = g0 + threadIdx.x;
#pragma unroll
    for (int j = 0; j < 32; j += 8) {
        int cc = c0 + threadIdx.y + j;
        if (cc < C && g < G) out[(size_t)cc * G + g] = spl(tile[threadIdx.x][threadIdx.y + j]);
    }
}

__global__ void pool3_k(const float* __restrict__ in, float2* __restrict__ out, int C) {
    int idx = blockIdx.x * blockDim.x + threadIdx.x;
    if (idx < C * GP1) {
        int co = idx / GP1;
        int r = idx % GP1;
        int b = r / P1, p = r % P1;
        int base = co * NTOT + b * NPG + 2 * p;
        float m = fmaxf(fmaxf(in[base], in[base + 1]), in[base + 2]);
        out[idx] = spl(fmaxf(m, 0.f));
    }
}

__global__ void pool2_k(const float* __restrict__ in, float2* __restrict__ out, int C) {
    int idx = blockIdx.x * blockDim.x + threadIdx.x;
    if (idx < C * GP2) {
        int co = idx / GP2;
        int r = idx % GP2;
        int b = r / P2, p = r % P2;
        int base = co * GP1 + b * P1 + 2 * p;
        out[idx] = spl(fmaxf(fmaxf(in[base], in[base + 1]), 0.f));
    }
}

__global__ void final_k(const float* __restrict__ by, const float* __restrict__ bz,
                        float* __restrict__ out) {
    __shared__ float red[NCLS][128];
    int b = blockIdx.x;
    int tid = threadIdx.x;
    float part[NCLS] = {};
    for (int p = tid; p < P2; p += blockDim.x) {
        int base = b * P2 + p;
#pragma unroll
        for (int cl = 0; cl < NCLS; cl++) {
            float y = d_ly[cl * GP2 + base] + by[cl];
            float z = d_lz[cl * GP2 + base] + bz[cl];
            part[cl] += y * z;
        }
    }
#pragma unroll
    for (int cl = 0; cl < NCLS; cl++) red[cl][tid] = part[cl];
    __syncthreads();
    if (tid == 0) {
        float v[NCLS];
        for (int cl = 0; cl < NCLS; cl++) {
            float s = 0.f;
            for (int i = 0; i < 128; i++) s += red[cl][i];
            v[cl] = s / (float)P2;
        }
        float mx = v[0];
        for (int cl = 1; cl < NCLS; cl++) mx = fmaxf(mx, v[cl]);
        float se = 0.f;
        for (int cl = 0; cl < NCLS; cl++) { v[cl] = __expf(v[cl] - mx); se += v[cl]; }
        for (int cl = 0; cl < NCLS; cl++) out[b * NCLS + cl] = v[cl] / se;
    }
}

// ----------------------------- host side ----------------------------------
static void* getsym(const void* s) {
    void* p = nullptr;
    cudaGetSymbolAddress(&p, s);
    return p;
}

extern "C" void kernel_launch(void* const* d_in, const int* in_sizes, int n_in,
                              void* d_out, int out_size)
{
    const float* features = (const float*)d_in[0];
    const int*   esrc     = (const int*)  d_in[1];
    const int*   edst     = (const int*)  d_in[2];
    const int*   etyp     = (const int*)  d_in[3];
    const float* etype_W  = (const float*)d_in[4];
    const float* etype_b  = (const float*)d_in[5];
    const float* W_ih     = (const float*)d_in[6];
    const float* b_ih     = (const float*)d_in[7];
    const float* W_hh     = (const float*)d_in[8];
    const float* b_hh     = (const float*)d_in[9];
    const float* conv1_w  = (const float*)d_in[10];
    const float* conv1_b  = (const float*)d_in[11];
    const float* conv2_w  = (const float*)d_in[12];
    const float* conv2_b  = (const float*)d_in[13];
    const float* convc1_w = (const float*)d_in[14];
    const float* convc1_b = (const float*)d_in[15];
    const float* convc2_w = (const float*)d_in[16];
    const float* convc2_b = (const float*)d_in[17];
    const float* mlp_y_w  = (const float*)d_in[18];
    const float* mlp_y_b  = (const float*)d_in[19];
    const float* mlp_z_w  = (const float*)d_in[20];
    const float* mlp_z_b  = (const float*)d_in[21];

    float*  p_h0    = (float*) getsym(d_h0);
    float*  p_h1    = (float*) getsym(d_h1);
    float*  p_a     = (float*) getsym(d_a);
    float*  p_Ht    = (float*) getsym(d_Ht);
    float*  p_gi    = (float*) getsym(d_gi);
    float*  p_gh    = (float*) getsym(d_gh);
    float2* p_Wst2  = (float2*)getsym(d_Wst2);
    float2* p_WihT  = (float2*)getsym(d_WihT);
    float2* p_WhhT  = (float2*)getsym(d_WhhT);
    int*    p_deg4  = (int*)   getsym(d_deg4);
    float2* p_cThl  = (float2*)getsym(d_cThl);
    float2* p_w1yhl = (float2*)getsym(d_w1yhl);
    float2* p_w1zhl = (float2*)getsym(d_w1zhl);
    float2* p_w2yhl = (float2*)getsym(d_w2yhl);
    float2* p_w2zhl = (float2*)getsym(d_w2zhl);
    float2* p_wmyhl = (float2*)getsym(d_wmyhl);
    float2* p_wmzhl = (float2*)getsym(d_wmzhl);
    float*  p_y1    = (float*) getsym(d_y1);
    float*  p_z1    = (float*) getsym(d_z1);
    float2* p_yp1hl = (float2*)getsym(d_yp1hl);
    float2* p_zp1hl = (float2*)getsym(d_zp1hl);
    float*  p_y2    = (float*) getsym(d_y2);
    float*  p_z2    = (float*) getsym(d_z2);
    float2* p_yp2hl = (float2*)getsym(d_yp2hl);
    float2* p_zp2hl = (float2*)getsym(d_zp2hl);
    float*  p_ly    = (float*) getsym(d_ly);
    float*  p_lz    = (float*) getsym(d_lz);

    const int T = 256;

    // ---- first launches: gh GEMM at profiler slot 3 ----
    init_h_k<<<(NTOT * ODIM + T - 1) / T, T>>>(features);                    // 0
    pack_T_hl_k<<<(ODIM * H3 + T - 1) / T, T>>>(W_hh, p_WhhT);               // 1
    pack_T_hl_k<<<(ODIM * H3 + T - 1) / T, T>>>(W_ih, p_WihT);               // 2
    launch_gemm<1,1,0>(p_h0, p_WhhT, p_gh, b_hh, NTOT, H3, ODIM, ODIM, H3, H3, 0); // 3

    // ---- rest of setup ----
    zero_int_k<<<(NTOT * 4 + T - 1) / T, T>>>(p_deg4, NTOT * 4);
    hist_k<<<(EDGES + T - 1) / T, T>>>(edst, etyp);
    scan_k<<<1, 1024>>>();
    chunk_hist_k<<<dim3(NCHK, BATCH), 512>>>(edst);
    chunk_scan_k<<<(NTOT + T - 1) / T, T>>>();
    scatter_k<<<dim3(NCHK, BATCH), 512>>>(esrc, edst, etyp);
    pack_wstack2_k<<<(4 * ODIM * ODIM + T - 1) / T, T>>>(etype_W);
    pack_conv_hl_k<<<(3 * ODIM * ODIM + T - 1) / T, T>>>(conv1_w, p_w1yhl, ODIM);
    pack_conv_hl_k<<<(3 * CDIM * CDIM + T - 1) / T, T>>>(convc1_w, p_w1zhl, CDIM);
    split_mat_k<<<(ODIM * ODIM + T - 1) / T, T>>>(conv2_w, p_w2yhl, ODIM * ODIM);
    split_mat_k<<<(CDIM * CDIM + T - 1) / T, T>>>(convc2_w, p_w2zhl, CDIM * CDIM);
    split_mat_k<<<(NCLS * ODIM + T - 1) / T, T>>>(mlp_y_w, p_wmyhl, NCLS * ODIM);
    split_mat_k<<<(NCLS * CDIM + T - 1) / T, T>>>(mlp_z_w, p_wmzhl, NCLS * CDIM);
    nodebias_k<<<(NTOT * ODIM + T - 1) / T, T>>>(etype_b);

    // ---- GGNN: 8 steps ----
    for (int s = 0; s < 8; s++) {
        const float* hin  = (s & 1) ? p_h1 : p_h0;
        float*       hout = (s & 1) ? p_h0 : p_h1;
        // Ht[n][t*200+o] = sum_d h[n][d] W_t[o][d]
        launch_gemm<0,1,0>(hin, p_Wst2, p_Ht, nullptr, NTOT, 4 * ODIM, ODIM, ODIM, 4 * ODIM, 4 * ODIM, 0);
        spmm_k<<<NTOT, 256>>>(p_Ht);
        launch_gemm<1,1,0>(p_a, p_WihT, p_gi, b_ih, NTOT, H3, ODIM, ODIM, H3, H3, 0);
        if (s > 0)
            launch_gemm<1,1,0>(hin, p_WhhT, p_gh, b_hh, NTOT, H3, ODIM, ODIM, H3, H3, 0);
        gates_k<<<(NTOT * 50 + T - 1) / T, T>>>(hin, hout);
    }
    float* p_hf = p_h0;

    // ---- readout ----
    transpose_hl_k<<<dim3((ODIM + 31) / 32, NTOT / 32), dim3(32, 8)>>>(p_hf, p_cThl, NTOT, ODIM);
    transpose_hl_k<<<dim3((IDIM + 31) / 32, NTOT / 32), dim3(32, 8)>>>(features, p_cThl + (size_t)ODIM * NTOT, NTOT, IDIM);

    launch_gemm<3,3,1>(p_w1yhl, p_cThl, p_y1, conv1_b, ODIM, NTOT, ODIM, ODIM, NTOT, NTOT, ODIM * ODIM);
    pool3_k<<<(ODIM * GP1 + T - 1) / T, T>>>(p_y1, p_yp1hl, ODIM);
    launch_gemm<3,1,1>(p_w2yhl, p_yp1hl, p_y2, conv2_b, ODIM, GP1, ODIM, ODIM, GP1, GP1, 0);
    pool2_k<<<(ODIM * GP2 + T - 1) / T, T>>>(p_y2, p_yp2hl, ODIM);

    launch_gemm<3,3,1>(p_w1zhl, p_cThl, p_z1, convc1_b, CDIM, NTOT, CDIM, CDIM, NTOT, NTOT, CDIM * CDIM);
    pool3_k<<<(CDIM * GP1 + T - 1) / T, T>>>(p_z1, p_zp1hl, CDIM);
    launch_gemm<3,1,1>(p_w2zhl, p_zp1hl, p_z2, convc2_b, CDIM, GP1, CDIM, CDIM, GP1, GP1, 0);
    pool2_k<<<(CDIM * GP2 + T - 1) / T, T>>>(p_z2, p_zp2hl, CDIM);

    launch_gemm<0,1,1>(p_wmyhl, p_yp2hl, p_ly, nullptr, NCLS, GP2, ODIM, ODIM, GP2, GP2, 0);
    launch_gemm<0,1,1>(p_wmzhl, p_zp2hl, p_lz, nullptr, NCLS, GP2, CDIM, CDIM, GP2, GP2, 0);

    final_k<<<BATCH, 128>>>(mlp_y_b, mlp_z_b, (float*)d_out);
}

// round 7
// speedup vs baseline: 1.4515x; 1.3041x over previous
#include <cuda_runtime.h>

#define BATCH  64
#define NPG    512
#define NTOT   32768
#define EDGES  524288
#define EPG    8192
#define NCHK   16
#define ODIM   200
#define IDIM   100
#define H3     600
#define CDIM   300
#define P1     254
#define P2     127
#define GP1    16256
#define GP2    8128
#define NCLS   7

// ----------------------------- device scratch -----------------------------
__device__ float  d_h0[NTOT*ODIM];
__device__ float  d_h1[NTOT*ODIM];
__device__ float  d_a[NTOT*ODIM];
__device__ float  d_Ht[NTOT*4*ODIM];
__device__ float  d_gi[NTOT*H3];
__device__ float  d_gh[NTOT*H3];
__device__ float2 d_Wst2[ODIM*4*ODIM];     // [d][t*200+o] hi/lo
__device__ float2 d_WihT[ODIM*H3];
__device__ float2 d_WhhT[ODIM*H3];
__device__ float  d_nbias[NTOT*ODIM];
__device__ int    d_deg4[NTOT*4];
__device__ int    d_indptr[NTOT+1];
__device__ int    d_ccnt[NTOT*NCHK];
__device__ int    d_srcs[EDGES];
__device__ int    d_typs[EDGES];
__device__ float2 d_cThl[CDIM*NTOT + 64];
__device__ float2 d_w1yhl[3*ODIM*ODIM];
__device__ float2 d_w1zhl[3*CDIM*CDIM];
__device__ float2 d_w2yhl[ODIM*ODIM];
__device__ float2 d_w2zhl[CDIM*CDIM];
__device__ float2 d_wmyhl[NCLS*ODIM];
__device__ float2 d_wmzhl[NCLS*CDIM];
__device__ float  d_y1[ODIM*NTOT];
__device__ float  d_z1[CDIM*NTOT];
__device__ float2 d_yp1hl[ODIM*GP1];
__device__ float2 d_zp1hl[CDIM*GP1];
__device__ float  d_y2[ODIM*GP1];
__device__ float  d_z2[CDIM*GP1];
__device__ float2 d_yp2hl[ODIM*GP2];
__device__ float2 d_zp2hl[CDIM*GP2];
__device__ float  d_ly[NCLS*GP2];
__device__ float  d_lz[NCLS*GP2];

// ----------------------------- helpers ------------------------------------
__device__ __forceinline__ unsigned f2tf32(float f) {
    unsigned u;
    asm("cvt.rna.tf32.f32 %0, %1;" : "=r"(u) : "f"(f));
    return u;
}
__device__ __forceinline__ float2 spl(float f) {
    unsigned h = f2tf32(f);
    float hf = __uint_as_float(h);
    unsigned l = f2tf32(f - hf);
    return make_float2(hf, __uint_as_float(l));
}

// ----------------------------- setup kernels ------------------------------
__global__ void zero_int_k(int* p, int n) {
    int i = blockIdx.x * blockDim.x + threadIdx.x;
    if (i < n) p[i] = 0;
}

__global__ void hist_k(const int* __restrict__ edst, const int* __restrict__ etyp) {
    int e = blockIdx.x * blockDim.x + threadIdx.x;
    if (e < EDGES) atomicAdd(&d_deg4[edst[e] * 4 + etyp[e]], 1);
}

__global__ void scan_k() {
    __shared__ int ssum[1024];
    int t = threadIdx.x;
    int loc[32];
    int s = 0;
#pragma unroll
    for (int i = 0; i < 32; i++) {
        int n = t * 32 + i;
        int d = d_deg4[n*4] + d_deg4[n*4+1] + d_deg4[n*4+2] + d_deg4[n*4+3];
        loc[i] = s; s += d;
    }
    ssum[t] = s;
    __syncthreads();
    if (t == 0) {
        int acc = 0;
        for (int i = 0; i < 1024; i++) { int v = ssum[i]; ssum[i] = acc; acc += v; }
        d_indptr[NTOT] = acc;
    }
    __syncthreads();
    int off = ssum[t];
#pragma unroll
    for (int i = 0; i < 32; i++) d_indptr[t * 32 + i] = off + loc[i];
}

__global__ void chunk_hist_k(const int* __restrict__ edst) {
    __shared__ int h[NPG];
    int g = blockIdx.y, c = blockIdx.x;
    h[threadIdx.x] = 0;
    __syncthreads();
    int e = g * EPG + c * 512 + threadIdx.x;
    atomicAdd(&h[edst[e] - g * NPG], 1);
    __syncthreads();
    d_ccnt[(g * NPG + threadIdx.x) * NCHK + c] = h[threadIdx.x];
}

__global__ void chunk_scan_k() {
    int n = blockIdx.x * blockDim.x + threadIdx.x;
    if (n < NTOT) {
        int base = d_indptr[n];
#pragma unroll
        for (int c = 0; c < NCHK; c++) {
            int v = d_ccnt[n * NCHK + c];
            d_ccnt[n * NCHK + c] = base;
            base += v;
        }
    }
}

__global__ void scatter_k(const int* __restrict__ esrc, const int* __restrict__ edst,
                          const int* __restrict__ etyp) {
    __shared__ int sd[512];
    int g = blockIdx.y, c = blockIdx.x;
    int e = g * EPG + c * 512 + threadIdx.x;
    int dl = edst[e] - g * NPG;
    sd[threadIdx.x] = dl;
    __syncthreads();
    int rank = 0;
    for (int i = 0; i < threadIdx.x; i++) rank += (sd[i] == dl);
    int pos = d_ccnt[(g * NPG + dl) * NCHK + c] + rank;
    d_srcs[pos] = esrc[e];
    d_typs[pos] = etyp[e];
}

// etype_W [4][o][d] -> Wst2[d][t*200+o] hi/lo
__global__ void pack_wstack2_k(const float* __restrict__ W) {
    int idx = blockIdx.x * blockDim.x + threadIdx.x;
    if (idx < 4 * ODIM * ODIM) {
        int o = idx % ODIM;
        int d = (idx / ODIM) % ODIM;
        int t = idx / (ODIM * ODIM);
        d_Wst2[d * (4 * ODIM) + t * ODIM + o] = spl(W[(t * ODIM + o) * ODIM + d]);
    }
}

// W[600][200] -> out[200][600] hi/lo
__global__ void pack_T_hl_k(const float* __restrict__ W, float2* __restrict__ out) {
    int idx = blockIdx.x * blockDim.x + threadIdx.x;
    if (idx < ODIM * H3) {
        int j = idx % H3;
        int d = idx / H3;
        out[d * H3 + j] = spl(W[j * ODIM + d]);
    }
}

// conv weight [C][C][3] -> [k][co][ci] hi/lo
__global__ void pack_conv_hl_k(const float* __restrict__ W, float2* __restrict__ out, int C) {
    int idx = blockIdx.x * blockDim.x + threadIdx.x;
    if (idx < 3 * C * C) {
        int ci = idx % C;
        int co = (idx / C) % C;
        int k  = idx / (C * C);
        out[idx] = spl(W[(co * C + ci) * 3 + k]);
    }
}

__global__ void split_mat_k(const float* __restrict__ in, float2* __restrict__ out, int n) {
    int i = blockIdx.x * blockDim.x + threadIdx.x;
    if (i < n) out[i] = spl(in[i]);
}

__global__ void init_h_k(const float* __restrict__ feat) {
    int idx = blockIdx.x * blockDim.x + threadIdx.x;
    if (idx < NTOT * ODIM) {
        int d = idx % ODIM;
        int n = idx / ODIM;
        d_h0[idx] = (d < IDIM) ? feat[n * IDIM + d] : 0.f;
    }
}

__global__ void nodebias_k(const float* __restrict__ eb) {
    int idx = blockIdx.x * blockDim.x + threadIdx.x;
    if (idx < NTOT * ODIM) {
        int o = idx % ODIM;
        int n = idx / ODIM;
        float s = 0.f;
#pragma unroll
        for (int t = 0; t < 4; t++) s += (float)d_deg4[n * 4 + t] * eb[t * ODIM + o];
        d_nbias[idx] = s;
    }
}

// a[n][o] = nbias[n][o] + sum_{edges->n} Ht[src][t*200+o]
__global__ void spmm_k(const float* __restrict__ Ht) {
    __shared__ int so[128];
    int n = blockIdx.x;
    int tid = threadIdx.x;
    int beg = d_indptr[n], end = d_indptr[n + 1];
    float a = 0.f;
    for (int base = beg; base < end; base += 128) {
        int cnt = min(128, end - base);
        if (tid < cnt) so[tid] = d_srcs[base + tid] * (4 * ODIM) + d_typs[base + tid] * ODIM;
        __syncthreads();
        if (tid < ODIM) {
            for (int e = 0; e < cnt; e++) a += Ht[so[e] + tid];
        }
        __syncthreads();
    }
    if (tid < ODIM) {
        int o = n * ODIM + tid;
        d_a[o] = a + d_nbias[o];
    }
}

// --------------------------- tensor-core GEMM ------------------------------
// 2xTF32: A rounded to one tf32 (ASPL=0: cvt in reg; ASPL=1: hi of pre-split),
// B pre-split float2 hi/lo (full precision). C = ah*bl + ah*bh.
// C[M,N] = sum_s A_s*B_s (+bias). BMODE: 0 none, 1 bias[col], 3 bias[row].

__device__ __forceinline__ void mma_tf32(float* d, const unsigned* a, const unsigned* b) {
    asm volatile(
        "mma.sync.aligned.m16n8k8.row.col.f32.tf32.tf32.f32 "
        "{%0,%1,%2,%3}, {%4,%5,%6,%7}, {%8,%9}, {%0,%1,%2,%3};"
        : "+f"(d[0]), "+f"(d[1]), "+f"(d[2]), "+f"(d[3])
        : "r"(a[0]), "r"(a[1]), "r"(a[2]), "r"(a[3]), "r"(b[0]), "r"(b[1]));
}
__device__ __forceinline__ void cpa16(void* dst, const void* src, int sb) {
    unsigned sa = (unsigned)__cvta_generic_to_shared(dst);
    asm volatile("cp.async.cg.shared.global [%0], [%1], 16, %2;" :: "r"(sa), "l"(src), "r"(sb));
}
__device__ __forceinline__ void cpa8(void* dst, const void* src, int sb) {
    unsigned sa = (unsigned)__cvta_generic_to_shared(dst);
    asm volatile("cp.async.ca.shared.global [%0], [%1], 8, %2;" :: "r"(sa), "l"(src), "r"(sb));
}

#define APAD   20
#define BPADF2 132

template<int BMODE, int NSPLIT, int ASPL>
__global__ __launch_bounds__(256, 2) void gemm_tc(
    const void* __restrict__ Av, const float2* __restrict__ B,
    float* __restrict__ C, const float* __restrict__ bias,
    int M, int N, int K, int lda, int ldb, int ldc, int aStep)
{
    extern __shared__ char smraw[];
    constexpr int AELT = ASPL ? 8 : 4;                 // bytes per A element
    constexpr int ABUF = 128 * APAD * AELT;            // bytes per A buffer
    float*  Af  = (float*)smraw;
    float2* Af2 = (float2*)smraw;
    float2* Bb  = (float2*)(smraw + 2 * ABUF);         // [2][16][BPADF2]

    const int tid  = threadIdx.x;
    const int lane = tid & 31;
    const int w    = tid >> 5;
    const int wm   = w & 3;
    const int wn   = w >> 2;
    const int row0 = blockIdx.y * 128;
    const int col0 = blockIdx.x * 128;

    const int ktiles = (K + 15) >> 4;
    const int total  = ktiles * NSPLIT;

    float acc[2][8][4];
#pragma unroll
    for (int mt = 0; mt < 2; mt++)
#pragma unroll
        for (int nt = 0; nt < 8; nt++)
#pragma unroll
            for (int i = 0; i < 4; i++) acc[mt][nt][i] = 0.f;

    auto stage = [&](int t, int b) {
        const int sI = (NSPLIT == 1) ? 0 : (t / ktiles);
        const int kt = (NSPLIT == 1) ? t : (t % ktiles);
        const int k0 = kt << 4;
        if (ASPL == 0) {
            const float* Ap = (const float*)Av + (size_t)sI * aStep;
#pragma unroll
            for (int i = 0; i < 2; i++) {
                int ch = tid + (i << 8);
                int row = ch >> 2, part = (ch & 3) << 2;
                int gr = row0 + row, gk = k0 + part;
                int sb = (gr < M && gk < K) ? 16 : 0;
                const float* src = sb ? (Ap + (size_t)gr * lda + gk) : Ap;
                cpa16(&Af[(size_t)b * (ABUF / 4) + row * APAD + part], src, sb);
            }
        } else {
            const float2* Ap = (const float2*)Av + (size_t)sI * aStep;
#pragma unroll
            for (int i = 0; i < 4; i++) {
                int ch = tid + (i << 8);
                int row = ch >> 3, kp = (ch & 7) << 1;
                int gr = row0 + row, gk = k0 + kp;
                int sb = (gr < M && gk < K) ? 16 : 0;
                const float2* src = sb ? (Ap + (size_t)gr * lda + gk) : Ap;
                cpa16(&Af2[(size_t)b * (ABUF / 8) + row * APAD + kp], src, sb);
            }
        }
        if (NSPLIT == 1) {
#pragma unroll
            for (int i = 0; i < 4; i++) {
                int ch = tid + (i << 8);
                int krow = ch >> 6, cp = (ch & 63) << 1;
                int gk = k0 + krow, gc = col0 + cp;
                int sb = (gk < K && gc < N) ? 16 : 0;
                const float2* src = sb ? (B + (size_t)gk * ldb + gc) : B;
                cpa16(&Bb[(b * 16 + krow) * BPADF2 + cp], src, sb);
            }
        } else {
#pragma unroll
            for (int i = 0; i < 8; i++) {
                int ch = tid + (i << 8);
                int krow = ch >> 7, c = ch & 127;
                int gk = k0 + krow, gc = col0 + c;
                int sb = (gk < K && gc < N) ? 8 : 0;
                const float2* src = sb ? (B + (size_t)gk * ldb + gc + sI) : B;
                cpa8(&Bb[(b * 16 + krow) * BPADF2 + c], src, sb);
            }
        }
        asm volatile("cp.async.commit_group;");
    };

    stage(0, 0);
    asm volatile("cp.async.wait_group 0;");
    __syncthreads();

    int buf = 0;
    const int r_  = lane >> 2;
    const int cc_ = lane & 3;

    for (int t = 0; t < total; t++) {
        if (t + 1 < total) stage(t + 1, buf ^ 1);

#pragma unroll
        for (int k2 = 0; k2 < 2; k2++) {
            unsigned ah[2][4];
#pragma unroll
            for (int mt = 0; mt < 2; mt++) {
                int rb = wm * 32 + mt * 16;
                if (ASPL == 0) {
                    const float* Ar = Af + (size_t)buf * (ABUF / 4);
                    float f0 = Ar[(rb + r_    ) * APAD + k2 * 8 + cc_];
                    float f1 = Ar[(rb + r_ + 8) * APAD + k2 * 8 + cc_];
                    float f2 = Ar[(rb + r_    ) * APAD + k2 * 8 + cc_ + 4];
                    float f3 = Ar[(rb + r_ + 8) * APAD + k2 * 8 + cc_ + 4];
                    ah[mt][0] = f2tf32(f0);
                    ah[mt][1] = f2tf32(f1);
                    ah[mt][2] = f2tf32(f2);
                    ah[mt][3] = f2tf32(f3);
                } else {
                    const float2* Ar = Af2 + (size_t)buf * (ABUF / 8);
                    float2 v0 = Ar[(rb + r_    ) * APAD + k2 * 8 + cc_];
                    float2 v1 = Ar[(rb + r_ + 8) * APAD + k2 * 8 + cc_];
                    float2 v2 = Ar[(rb + r_    ) * APAD + k2 * 8 + cc_ + 4];
                    float2 v3 = Ar[(rb + r_ + 8) * APAD + k2 * 8 + cc_ + 4];
                    ah[mt][0] = __float_as_uint(v0.x);
                    ah[mt][1] = __float_as_uint(v1.x);
                    ah[mt][2] = __float_as_uint(v2.x);
                    ah[mt][3] = __float_as_uint(v3.x);
                }
            }
#pragma unroll
            for (int nt = 0; nt < 8; nt++) {
                int cb = wn * 64 + nt * 8 + r_;
                int kb = k2 * 8 + cc_;
                float2 g0 = Bb[(buf * 16 + kb    ) * BPADF2 + cb];
                float2 g1 = Bb[(buf * 16 + kb + 4) * BPADF2 + cb];
                unsigned bh[2], bl[2];
                bh[0] = __float_as_uint(g0.x); bl[0] = __float_as_uint(g0.y);
                bh[1] = __float_as_uint(g1.x); bl[1] = __float_as_uint(g1.y);
#pragma unroll
                for (int mt = 0; mt < 2; mt++) {
                    mma_tf32(acc[mt][nt], ah[mt], bl);
                    mma_tf32(acc[mt][nt], ah[mt], bh);
                }
            }
        }

        if (t + 1 < total) asm volatile("cp.async.wait_group 0;");
        __syncthreads();
        buf ^= 1;
    }

    // ---- epilogue ----
    const int gid = lane >> 2, tig = lane & 3;
#pragma unroll
    for (int mt = 0; mt < 2; mt++) {
#pragma unroll
        for (int half = 0; half < 2; half++) {
            int r = row0 + wm * 32 + mt * 16 + half * 8 + gid;
            if (r >= M) continue;
            float rb = (BMODE == 3) ? bias[r] : 0.f;
#pragma unroll
            for (int nt = 0; nt < 8; nt++) {
                int c = col0 + wn * 64 + nt * 8 + tig * 2;
                if (c >= N) continue;
                float v0 = acc[mt][nt][half * 2 + 0];
                float v1 = acc[mt][nt][half * 2 + 1];
                if (BMODE == 1)      { v0 += bias[c]; v1 += bias[c + 1]; }
                else if (BMODE == 3) { v0 += rb; v1 += rb; }
                float2 o; o.x = v0; o.y = v1;
                *(float2*)(C + (size_t)r * ldc + c) = o;
            }
        }
    }
}

#define SMEM_A0 (2 * 128 * APAD * 4 + 2 * 16 * BPADF2 * 8)
#define SMEM_A1 (2 * 128 * APAD * 8 + 2 * 16 * BPADF2 * 8)

template<int BMODE, int NSPLIT, int ASPL>
static void launch_gemm(const void* A, const float2* B, float* C, const float* bias,
                        int M, int N, int K, int lda, int ldb, int ldc, int aStep)
{
    constexpr int SM = ASPL ? SMEM_A1 : SMEM_A0;
    cudaFuncSetAttribute(gemm_tc<BMODE, NSPLIT, ASPL>,
                         cudaFuncAttributeMaxDynamicSharedMemorySize, SM);
    dim3 grid((N + 127) / 128, (M + 127) / 128);
    gemm_tc<BMODE, NSPLIT, ASPL><<<grid, 256, SM>>>(A, B, C, bias, M, N, K, lda, ldb, ldc, aStep);
}

// GRU gates (raw in/out)
__global__ void gates_k(const float* __restrict__ hin, float* __restrict__ hout) {
    int idx = blockIdx.x * blockDim.x + threadIdx.x;
    if (idx < NTOT * 50) {
        int n = idx / 50, q = idx % 50;
        size_t g4 = (size_t)n * 150 + q;
        const float4* gi4 = (const float4*)d_gi;
        const float4* gh4 = (const float4*)d_gh;
        float4 ir4 = gi4[g4],        hr4 = gh4[g4];
        float4 iz4 = gi4[g4 + 50],   hz4 = gh4[g4 + 50];
        float4 in4 = gi4[g4 + 100],  hn4 = gh4[g4 + 100];
        float4 h4  = ((const float4*)hin)[(size_t)n * 50 + q];
        float4 o;
        {
            float r = 1.f / (1.f + __expf(-(ir4.x + hr4.x)));
            float z = 1.f / (1.f + __expf(-(iz4.x + hz4.x)));
            float nn = tanhf(in4.x + r * hn4.x);
            o.x = (1.f - z) * nn + z * h4.x;
        }
        {
            float r = 1.f / (1.f + __expf(-(ir4.y + hr4.y)));
            float z = 1.f / (1.f + __expf(-(iz4.y + hz4.y)));
            float nn = tanhf(in4.y + r * hn4.y);
            o.y = (1.f - z) * nn + z * h4.y;
        }
        {
            float r = 1.f / (1.f + __expf(-(ir4.z + hr4.z)));
            float z = 1.f / (1.f + __expf(-(iz4.z + hz4.z)));
            float nn = tanhf(in4.z + r * hn4.z);
            o.z = (1.f - z) * nn + z * h4.z;
        }
        {
            float r = 1.f / (1.f + __expf(-(ir4.w + hr4.w)));
            float z = 1.f / (1.f + __expf(-(iz4.w + hz4.w)));
            float nn = tanhf(in4.w + r * hn4.w);
            o.w = (1.f - z) * nn + z * h4.w;
        }
        ((float4*)hout)[(size_t)n * 50 + q] = o;
    }
}

// in [G][C] raw -> out [C][G] hi/lo
__global__ void transpose_hl_k(const float* __restrict__ in, float2* __restrict__ out,
                               int G, int C) {
    __shared__ float tile[32][33];
    int c0 = blockIdx.x * 32;
    int g0 = blockIdx.y * 32;
    int c = c0 + threadIdx.x;
#pragma unroll
    for (int j = 0; j < 32; j += 8) {
        int g = g0 + threadIdx.y + j;
        tile[threadIdx.y + j][threadIdx.x] = (c < C && g < G) ? in[(size_t)g * C + c] : 0.f;
    }
    __syncthreads();
    int g = g0 + threadIdx.x;
#pragma unroll
    for (int j = 0; j < 32; j += 8) {
        int cc = c0 + threadIdx.y + j;
        if (cc < C && g < G) out[(size_t)cc * G + g] = spl(tile[threadIdx.x][threadIdx.y + j]);
    }
}

__global__ void pool3_k(const float* __restrict__ in, float2* __restrict__ out, int C) {
    int idx = blockIdx.x * blockDim.x + threadIdx.x;
    if (idx < C * GP1) {
        int co = idx / GP1;
        int r = idx % GP1;
        int b = r / P1, p = r % P1;
        int base = co * NTOT + b * NPG + 2 * p;
        float m = fmaxf(fmaxf(in[base], in[base + 1]), in[base + 2]);
        out[idx] = spl(fmaxf(m, 0.f));
    }
}

__global__ void pool2_k(const float* __restrict__ in, float2* __restrict__ out, int C) {
    int idx = blockIdx.x * blockDim.x + threadIdx.x;
    if (idx < C * GP2) {
        int co = idx / GP2;
        int r = idx % GP2;
        int b = r / P2, p = r % P2;
        int base = co * GP1 + b * P1 + 2 * p;
        out[idx] = spl(fmaxf(fmaxf(in[base], in[base + 1]), 0.f));
    }
}

__global__ void final_k(const float* __restrict__ by, const float* __restrict__ bz,
                        float* __restrict__ out) {
    __shared__ float red[NCLS][128];
    int b = blockIdx.x;
    int tid = threadIdx.x;
    float part[NCLS] = {};
    for (int p = tid; p < P2; p += blockDim.x) {
        int base = b * P2 + p;
#pragma unroll
        for (int cl = 0; cl < NCLS; cl++) {
            float y = d_ly[cl * GP2 + base] + by[cl];
            float z = d_lz[cl * GP2 + base] + bz[cl];
            part[cl] += y * z;
        }
    }
#pragma unroll
    for (int cl = 0; cl < NCLS; cl++) red[cl][tid] = part[cl];
    __syncthreads();
    if (tid == 0) {
        float v[NCLS];
        for (int cl = 0; cl < NCLS; cl++) {
            float s = 0.f;
            for (int i = 0; i < 128; i++) s += red[cl][i];
            v[cl] = s / (float)P2;
        }
        float mx = v[0];
        for (int cl = 1; cl < NCLS; cl++) mx = fmaxf(mx, v[cl]);
        float se = 0.f;
        for (int cl = 0; cl < NCLS; cl++) { v[cl] = __expf(v[cl] - mx); se += v[cl]; }
        for (int cl = 0; cl < NCLS; cl++) out[b * NCLS + cl] = v[cl] / se;
    }
}

// ----------------------------- host side ----------------------------------
static void* getsym(const void* s) {
    void* p = nullptr;
    cudaGetSymbolAddress(&p, s);
    return p;
}

extern "C" void kernel_launch(void* const* d_in, const int* in_sizes, int n_in,
                              void* d_out, int out_size)
{
    const float* features = (const float*)d_in[0];
    const int*   esrc     = (const int*)  d_in[1];
    const int*   edst     = (const int*)  d_in[2];
    const int*   etyp     = (const int*)  d_in[3];
    const float* etype_W  = (const float*)d_in[4];
    const float* etype_b  = (const float*)d_in[5];
    const float* W_ih     = (const float*)d_in[6];
    const float* b_ih     = (const float*)d_in[7];
    const float* W_hh     = (const float*)d_in[8];
    const float* b_hh     = (const float*)d_in[9];
    const float* conv1_w  = (const float*)d_in[10];
    const float* conv1_b  = (const float*)d_in[11];
    const float* conv2_w  = (const float*)d_in[12];
    const float* conv2_b  = (const float*)d_in[13];
    const float* convc1_w = (const float*)d_in[14];
    const float* convc1_b = (const float*)d_in[15];
    const float* convc2_w = (const float*)d_in[16];
    const float* convc2_b = (const float*)d_in[17];
    const float* mlp_y_w  = (const float*)d_in[18];
    const float* mlp_y_b  = (const float*)d_in[19];
    const float* mlp_z_w  = (const float*)d_in[20];
    const float* mlp_z_b  = (const float*)d_in[21];

    float*  p_h0    = (float*) getsym(d_h0);
    float*  p_h1    = (float*) getsym(d_h1);
    float*  p_a     = (float*) getsym(d_a);
    float*  p_Ht    = (float*) getsym(d_Ht);
    float*  p_gi    = (float*) getsym(d_gi);
    float*  p_gh    = (float*) getsym(d_gh);
    float2* p_Wst2  = (float2*)getsym(d_Wst2);
    float2* p_WihT  = (float2*)getsym(d_WihT);
    float2* p_WhhT  = (float2*)getsym(d_WhhT);
    int*    p_deg4  = (int*)   getsym(d_deg4);
    float2* p_cThl  = (float2*)getsym(d_cThl);
    float2* p_w1yhl = (float2*)getsym(d_w1yhl);
    float2* p_w1zhl = (float2*)getsym(d_w1zhl);
    float2* p_w2yhl = (float2*)getsym(d_w2yhl);
    float2* p_w2zhl = (float2*)getsym(d_w2zhl);
    float2* p_wmyhl = (float2*)getsym(d_wmyhl);
    float2* p_wmzhl = (float2*)getsym(d_wmzhl);
    float*  p_y1    = (float*) getsym(d_y1);
    float*  p_z1    = (float*) getsym(d_z1);
    float2* p_yp1hl = (float2*)getsym(d_yp1hl);
    float2* p_zp1hl = (float2*)getsym(d_zp1hl);
    float*  p_y2    = (float*) getsym(d_y2);
    float*  p_z2    = (float*) getsym(d_z2);
    float2* p_yp2hl = (float2*)getsym(d_yp2hl);
    float2* p_zp2hl = (float2*)getsym(d_zp2hl);
    float*  p_ly    = (float*) getsym(d_ly);
    float*  p_lz    = (float*) getsym(d_lz);

    const int T = 256;

    // ---- first launches: gh GEMM at profiler slot 3 ----
    init_h_k<<<(NTOT * ODIM + T - 1) / T, T>>>(features);                    // 0
    pack_T_hl_k<<<(ODIM * H3 + T - 1) / T, T>>>(W_hh, p_WhhT);               // 1
    pack_T_hl_k<<<(ODIM * H3 + T - 1) / T, T>>>(W_ih, p_WihT);               // 2
    launch_gemm<1,1,0>(p_h0, p_WhhT, p_gh, b_hh, NTOT, H3, ODIM, ODIM, H3, H3, 0); // 3

    // ---- rest of setup ----
    zero_int_k<<<(NTOT * 4 + T - 1) / T, T>>>(p_deg4, NTOT * 4);
    hist_k<<<(EDGES + T - 1) / T, T>>>(edst, etyp);
    scan_k<<<1, 1024>>>();
    chunk_hist_k<<<dim3(NCHK, BATCH), 512>>>(edst);
    chunk_scan_k<<<(NTOT + T - 1) / T, T>>>();
    scatter_k<<<dim3(NCHK, BATCH), 512>>>(esrc, edst, etyp);
    pack_wstack2_k<<<(4 * ODIM * ODIM + T - 1) / T, T>>>(etype_W);
    pack_conv_hl_k<<<(3 * ODIM * ODIM + T - 1) / T, T>>>(conv1_w, p_w1yhl, ODIM);
    pack_conv_hl_k<<<(3 * CDIM * CDIM + T - 1) / T, T>>>(convc1_w, p_w1zhl, CDIM);
    split_mat_k<<<(ODIM * ODIM + T - 1) / T, T>>>(conv2_w, p_w2yhl, ODIM * ODIM);
    split_mat_k<<<(CDIM * CDIM + T - 1) / T, T>>>(convc2_w, p_w2zhl, CDIM * CDIM);
    split_mat_k<<<(NCLS * ODIM + T - 1) / T, T>>>(mlp_y_w, p_wmyhl, NCLS * ODIM);
    split_mat_k<<<(NCLS * CDIM + T - 1) / T, T>>>(mlp_z_w, p_wmzhl, NCLS * CDIM);
    nodebias_k<<<(NTOT * ODIM + T - 1) / T, T>>>(etype_b);

    // ---- GGNN: 8 steps ----
    for (int s = 0; s < 8; s++) {
        const float* hin  = (s & 1) ? p_h1 : p_h0;
        float*       hout = (s & 1) ? p_h0 : p_h1;
        // Ht[n][t*200+o] = sum_d h[n][d] W_t[o][d]
        launch_gemm<0,1,0>(hin, p_Wst2, p_Ht, nullptr, NTOT, 4 * ODIM, ODIM, ODIM, 4 * ODIM, 4 * ODIM, 0);
        spmm_k<<<NTOT, 256>>>(p_Ht);
        launch_gemm<1,1,0>(p_a, p_WihT, p_gi, b_ih, NTOT, H3, ODIM, ODIM, H3, H3, 0);
        if (s > 0)
            launch_gemm<1,1,0>(hin, p_WhhT, p_gh, b_hh, NTOT, H3, ODIM, ODIM, H3, H3, 0);
        gates_k<<<(NTOT * 50 + T - 1) / T, T>>>(hin, hout);
    }
    float* p_hf = p_h0;

    // ---- readout ----
    transpose_hl_k<<<dim3((ODIM + 31) / 32, NTOT / 32), dim3(32, 8)>>>(p_hf, p_cThl, NTOT, ODIM);
    transpose_hl_k<<<dim3((IDIM + 31) / 32, NTOT / 32), dim3(32, 8)>>>(features, p_cThl + (size_t)ODIM * NTOT, NTOT, IDIM);

    launch_gemm<3,3,1>(p_w1yhl, p_cThl, p_y1, conv1_b, ODIM, NTOT, ODIM, ODIM, NTOT, NTOT, ODIM * ODIM);
    pool3_k<<<(ODIM * GP1 + T - 1) / T, T>>>(p_y1, p_yp1hl, ODIM);
    launch_gemm<3,1,1>(p_w2yhl, p_yp1hl, p_y2, conv2_b, ODIM, GP1, ODIM, ODIM, GP1, GP1, 0);
    pool2_k<<<(ODIM * GP2 + T - 1) / T, T>>>(p_y2, p_yp2hl, ODIM);

    launch_gemm<3,3,1>(p_w1zhl, p_cThl, p_z1, convc1_b, CDIM, NTOT, CDIM, CDIM, NTOT, NTOT, CDIM * CDIM);
    pool3_k<<<(CDIM * GP1 + T - 1) / T, T>>>(p_z1, p_zp1hl, CDIM);
    launch_gemm<3,1,1>(p_w2zhl, p_zp1hl, p_z2, convc2_b, CDIM, GP1, CDIM, CDIM, GP1, GP1, 0);
    pool2_k<<<(CDIM * GP2 + T - 1) / T, T>>>(p_z2, p_zp2hl, CDIM);

    launch_gemm<0,1,1>(p_wmyhl, p_yp2hl, p_ly, nullptr, NCLS, GP2, ODIM, ODIM, GP2, GP2, 0);
    launch_gemm<0,1,1>(p_wmzhl, p_zp2hl, p_lz, nullptr, NCLS, GP2, CDIM, CDIM, GP2, GP2, 0);

    final_k<<<BATCH, 128>>>(mlp_y_b, mlp_z_b, (float*)d_out);
}

// round 8
// speedup vs baseline: 1.5977x; 1.1007x over previous
#include <cuda_runtime.h>

#define BATCH  64
#define NPG    512
#define NTOT   32768
#define EDGES  524288
#define EPG    8192
#define NCHK   16
#define ODIM   200
#define IDIM   100
#define H3     600
#define CDIM   300
#define P1     254
#define P2     127
#define GP1    16256
#define GP2    8128
#define NCLS   7
#define KT13   13                        /* 208 padded K / 16 */
#define HPACK_FLOATS (256*KT13*2048)     /* 256 row-tiles x 13 ktiles x 512 vec x 4 */

// ----------------------------- device scratch -----------------------------
__device__ float  d_h0[NTOT*ODIM];
__device__ float  d_h1[NTOT*ODIM];
__device__ float  d_hpack0[HPACK_FLOATS];
__device__ float  d_hpack1[HPACK_FLOATS];
__device__ float  d_apack[HPACK_FLOATS];
__device__ float  d_Ht[NTOT*4*ODIM];
__device__ float  d_gi[NTOT*H3];
__device__ float  d_gh[NTOT*H3];
__device__ float  d_Wstp[7*KT13*4096];   // packed B: 7 col-tiles (N=800 pad 896)
__device__ float  d_Wihp[5*KT13*4096];   // packed B: 5 col-tiles (N=600 pad 640)
__device__ float  d_Whhp[5*KT13*4096];
__device__ float  d_nbias[NTOT*ODIM];
__device__ int    d_deg4[NTOT*4];
__device__ int    d_indptr[NTOT+1];
__device__ int    d_ccnt[NTOT*NCHK];
__device__ int    d_srcs[EDGES];
__device__ int    d_typs[EDGES];
__device__ float2 d_cThl[CDIM*NTOT + 64];
__device__ float2 d_w1yhl[3*ODIM*ODIM];
__device__ float2 d_w1zhl[3*CDIM*CDIM];
__device__ float2 d_w2yhl[ODIM*ODIM];
__device__ float2 d_w2zhl[CDIM*CDIM];
__device__ float2 d_wmyhl[NCLS*ODIM];
__device__ float2 d_wmzhl[NCLS*CDIM];
__device__ float  d_y1[ODIM*NTOT];
__device__ float  d_z1[CDIM*NTOT];
__device__ float2 d_yp1hl[ODIM*GP1];
__device__ float2 d_zp1hl[CDIM*GP1];
__device__ float  d_y2[ODIM*GP1];
__device__ float  d_z2[CDIM*GP1];
__device__ float2 d_yp2hl[ODIM*GP2];
__device__ float2 d_zp2hl[CDIM*GP2];
__device__ float  d_ly[NCLS*GP2];
__device__ float  d_lz[NCLS*GP2];

// ----------------------------- helpers ------------------------------------
__device__ __forceinline__ unsigned f2tf32(float f) {
    unsigned u;
    asm("cvt.rna.tf32.f32 %0, %1;" : "=r"(u) : "f"(f));
    return u;
}
__device__ __forceinline__ float2 spl(float f) {
    unsigned h = f2tf32(f);
    float hf = __uint_as_float(h);
    unsigned l = f2tf32(f - hf);
    return make_float2(hf, __uint_as_float(l));
}
// fragment-packed A index (float index): vec16B = {(r,k),(r+8,k),(r,k+4),(r+8,k+4)}
__device__ __forceinline__ int apack_idx(int n, int k) {
    int rt = n >> 7, mb = (n >> 4) & 7, r = n & 7, hr = (n >> 3) & 1;
    int k8 = k >> 3, kt = k8 >> 1, k2 = k8 & 1, cc = k & 3, hk = (k >> 2) & 1;
    return (((rt * KT13 + kt) * 512) + (mb * 2 + k2) * 32 + r * 4 + cc) * 4 + hk * 2 + hr;
}

// ----------------------------- setup kernels ------------------------------
__global__ void zero_int_k(int* p, int n) {
    int i = blockIdx.x * blockDim.x + threadIdx.x;
    if (i < n) p[i] = 0;
}

// zero the padding ktile (kt=12) of the three packed-A buffers
__global__ void zero_pack_k() {
    int i = blockIdx.x * blockDim.x + threadIdx.x;
    const int per = 256 * 2048;
    if (i < 3 * per) {
        int b = i / per, r = i % per;
        int rt = r / 2048, off = r % 2048;
        float* p = (b == 0) ? d_hpack0 : (b == 1) ? d_hpack1 : d_apack;
        p[(rt * KT13 + 12) * 2048 + off] = 0.f;
    }
}

__global__ void hist_k(const int* __restrict__ edst, const int* __restrict__ etyp) {
    int e = blockIdx.x * blockDim.x + threadIdx.x;
    if (e < EDGES) atomicAdd(&d_deg4[edst[e] * 4 + etyp[e]], 1);
}

__global__ void scan_k() {
    __shared__ int ssum[1024];
    int t = threadIdx.x;
    int loc[32];
    int s = 0;
#pragma unroll
    for (int i = 0; i < 32; i++) {
        int n = t * 32 + i;
        int d = d_deg4[n*4] + d_deg4[n*4+1] + d_deg4[n*4+2] + d_deg4[n*4+3];
        loc[i] = s; s += d;
    }
    ssum[t] = s;
    __syncthreads();
    if (t == 0) {
        int acc = 0;
        for (int i = 0; i < 1024; i++) { int v = ssum[i]; ssum[i] = acc; acc += v; }
        d_indptr[NTOT] = acc;
    }
    __syncthreads();
    int off = ssum[t];
#pragma unroll
    for (int i = 0; i < 32; i++) d_indptr[t * 32 + i] = off + loc[i];
}

__global__ void chunk_hist_k(const int* __restrict__ edst) {
    __shared__ int h[NPG];
    int g = blockIdx.y, c = blockIdx.x;
    h[threadIdx.x] = 0;
    __syncthreads();
    int e = g * EPG + c * 512 + threadIdx.x;
    atomicAdd(&h[edst[e] - g * NPG], 1);
    __syncthreads();
    d_ccnt[(g * NPG + threadIdx.x) * NCHK + c] = h[threadIdx.x];
}

__global__ void chunk_scan_k() {
    int n = blockIdx.x * blockDim.x + threadIdx.x;
    if (n < NTOT) {
        int base = d_indptr[n];
#pragma unroll
        for (int c = 0; c < NCHK; c++) {
            int v = d_ccnt[n * NCHK + c];
            d_ccnt[n * NCHK + c] = base;
            base += v;
        }
    }
}

__global__ void scatter_k(const int* __restrict__ esrc, const int* __restrict__ edst,
                          const int* __restrict__ etyp) {
    __shared__ int sd[512];
    int g = blockIdx.y, c = blockIdx.x;
    int e = g * EPG + c * 512 + threadIdx.x;
    int dl = edst[e] - g * NPG;
    sd[threadIdx.x] = dl;
    __syncthreads();
    int rank = 0;
    for (int i = 0; i < threadIdx.x; i++) rank += (sd[i] == dl);
    int pos = d_ccnt[(g * NPG + dl) * NCHK + c] + rank;
    d_srcs[pos] = esrc[e];
    d_typs[pos] = etyp[e];
}

// pack B weights into fragment-vec layout. W row-major [Nreal][200], B[k][c] = W[c][k].
// vec(ct,kt,c,j) 16B = {hi(k),lo(k),hi(k+4),lo(k+4)}, k = kt*16+(j>>2)*8+(j&3),
// swizzled position c*8 + ((j + 4c) & 7).
__global__ void packB_k(const float* __restrict__ W, float* __restrict__ out,
                        int Nreal, int nct) {
    int t = blockIdx.x * blockDim.x + threadIdx.x;
    if (t >= nct * KT13 * 1024) return;
    int j  = t & 7;
    int c  = (t >> 3) & 127;
    int kt = (t >> 10) % KT13;
    int ct = t / (KT13 * 1024);
    int k  = kt * 16 + ((j >> 2) << 3) + (j & 3);
    int cg = ct * 128 + c;
    float v0 = (k < 200 && cg < Nreal) ? W[cg * 200 + k] : 0.f;
    float v4 = (k + 4 < 200 && cg < Nreal) ? W[cg * 200 + k + 4] : 0.f;
    float2 s0 = spl(v0), s4 = spl(v4);
    int vi = (ct * KT13 + kt) * 1024 + c * 8 + ((j + (c << 2)) & 7);
    ((float4*)out)[vi] = make_float4(s0.x, s0.y, s4.x, s4.y);
}

// conv weight [C][C][3] -> [k][co][ci] hi/lo  (readout path)
__global__ void pack_conv_hl_k(const float* __restrict__ W, float2* __restrict__ out, int C) {
    int idx = blockIdx.x * blockDim.x + threadIdx.x;
    if (idx < 3 * C * C) {
        int ci = idx % C;
        int co = (idx / C) % C;
        int k  = idx / (C * C);
        out[idx] = spl(W[(co * C + ci) * 3 + k]);
    }
}

__global__ void split_mat_k(const float* __restrict__ in, float2* __restrict__ out, int n) {
    int i = blockIdx.x * blockDim.x + threadIdx.x;
    if (i < n) out[i] = spl(in[i]);
}

__global__ void init_h_k(const float* __restrict__ feat) {
    int idx = blockIdx.x * blockDim.x + threadIdx.x;
    if (idx < NTOT * ODIM) {
        int d = idx % ODIM;
        int n = idx / ODIM;
        float v = (d < IDIM) ? feat[n * IDIM + d] : 0.f;
        d_h0[idx] = v;
        d_hpack0[apack_idx(n, d)] = __uint_as_float(f2tf32(v));
    }
}

__global__ void nodebias_k(const float* __restrict__ eb) {
    int idx = blockIdx.x * blockDim.x + threadIdx.x;
    if (idx < NTOT * ODIM) {
        int o = idx % ODIM;
        int n = idx / ODIM;
        float s = 0.f;
#pragma unroll
        for (int t = 0; t < 4; t++) s += (float)d_deg4[n * 4 + t] * eb[t * ODIM + o];
        d_nbias[idx] = s;
    }
}

// a[n][o] = nbias + sum edges Ht[src][t*200+o]; writes fragment-packed tf32 a
__global__ void spmm_k(const float* __restrict__ Ht) {
    __shared__ int so[128];
    int n = blockIdx.x;
    int tid = threadIdx.x;
    int beg = d_indptr[n], end = d_indptr[n + 1];
    float a = 0.f;
    for (int base = beg; base < end; base += 128) {
        int cnt = min(128, end - base);
        if (tid < cnt) so[tid] = d_srcs[base + tid] * (4 * ODIM) + d_typs[base + tid] * ODIM;
        __syncthreads();
        if (tid < ODIM) {
            for (int e = 0; e < cnt; e++) a += Ht[so[e] + tid];
        }
        __syncthreads();
    }
    if (tid < ODIM) {
        float v = a + d_nbias[n * ODIM + tid];
        d_apack[apack_idx(n, tid)] = __uint_as_float(f2tf32(v));
    }
}

// ----------------------------- MMA helpers --------------------------------
__device__ __forceinline__ void mma_tf32(float* d, const unsigned* a, const unsigned* b) {
    asm volatile(
        "mma.sync.aligned.m16n8k8.row.col.f32.tf32.tf32.f32 "
        "{%0,%1,%2,%3}, {%4,%5,%6,%7}, {%8,%9}, {%0,%1,%2,%3};"
        : "+f"(d[0]), "+f"(d[1]), "+f"(d[2]), "+f"(d[3])
        : "r"(a[0]), "r"(a[1]), "r"(a[2]), "r"(a[3]), "r"(b[0]), "r"(b[1]));
}
__device__ __forceinline__ void cpa16(void* dst, const void* src, int sb) {
    unsigned sa = (unsigned)__cvta_generic_to_shared(dst);
    asm volatile("cp.async.cg.shared.global [%0], [%1], 16, %2;" :: "r"(sa), "l"(src), "r"(sb));
}
__device__ __forceinline__ void cpa16u(void* dst, const void* src) {
    unsigned sa = (unsigned)__cvta_generic_to_shared(dst);
    asm volatile("cp.async.cg.shared.global [%0], [%1], 16;" :: "r"(sa), "l"(src));
}
__device__ __forceinline__ void cpa8(void* dst, const void* src, int sb) {
    unsigned sa = (unsigned)__cvta_generic_to_shared(dst);
    asm volatile("cp.async.ca.shared.global [%0], [%1], 8, %2;" :: "r"(sa), "l"(src), "r"(sb));
}

// --------------------- fast GEMM (GGNN loop): packed A + packed B ----------
// M = 32768 fixed, K = 208 padded (13 ktiles). A: fragment-packed tf32 hi.
// B: fragment-vec hi/lo. C = ah*bl + ah*bh. 3-stage cp.async pipeline.
#define SMEM_FAST (3 * 6144 * 4)

template<int BMODE>
__global__ __launch_bounds__(256, 2) void gemm_fast(
    const float* __restrict__ Ap, const float* __restrict__ Bp,
    float* __restrict__ C, const float* __restrict__ bias, int Nreal)
{
    extern __shared__ float sm[];
    uint4* smv = (uint4*)sm;
    const int tid  = threadIdx.x;
    const int lane = tid & 31;
    const int w    = tid >> 5;
    const int wm   = w & 3;
    const int wn   = w >> 2;
    const int r_   = lane >> 2;
    const int cc_  = lane & 3;
    const int rt13 = blockIdx.y * KT13;
    const int ct13 = blockIdx.x * KT13;
    const int row0 = blockIdx.y * 128;
    const int col0 = blockIdx.x * 128;

    float acc[2][8][4] = {};

    int aoff[2][2];
#pragma unroll
    for (int mt = 0; mt < 2; mt++)
#pragma unroll
        for (int k2 = 0; k2 < 2; k2++)
            aoff[mt][k2] = ((wm * 2 + mt) * 2 + k2) * 32 + r_ * 4 + cc_;
    const int swA = (cc_ + ((r_ & 1) << 2)) & 7;
    const int swB = swA ^ 4;
    int c8[8];
#pragma unroll
    for (int nt = 0; nt < 8; nt++) c8[nt] = (wn * 64 + nt * 8 + r_) * 8;

    auto stage = [&](int kt, int b) {
        uint4* d = smv + b * 1536;
        const uint4* sa = (const uint4*)Ap + (size_t)(rt13 + kt) * 512;
        cpa16u(&d[tid], &sa[tid]);
        cpa16u(&d[tid + 256], &sa[tid + 256]);
        uint4* db = d + 512;
        const uint4* sb = (const uint4*)Bp + (size_t)(ct13 + kt) * 1024;
        cpa16u(&db[tid],       &sb[tid]);
        cpa16u(&db[tid + 256], &sb[tid + 256]);
        cpa16u(&db[tid + 512], &sb[tid + 512]);
        cpa16u(&db[tid + 768], &sb[tid + 768]);
        asm volatile("cp.async.commit_group;");
    };

    stage(0, 0);
    stage(1, 1);

#pragma unroll 1
    for (int t = 0; t < KT13; t++) {
        if (t < KT13 - 1) asm volatile("cp.async.wait_group 1;");
        else              asm volatile("cp.async.wait_group 0;");
        __syncthreads();
        if (t + 2 < KT13) stage(t + 2, (t + 2) % 3);

        const uint4* Ab = smv + (t % 3) * 1536;
        const uint4* Bb = Ab + 512;
#pragma unroll
        for (int k2 = 0; k2 < 2; k2++) {
            unsigned ah[2][4];
#pragma unroll
            for (int mt = 0; mt < 2; mt++) {
                uint4 v = Ab[aoff[mt][k2]];
                ah[mt][0] = v.x; ah[mt][1] = v.y; ah[mt][2] = v.z; ah[mt][3] = v.w;
            }
            const int sw = k2 ? swB : swA;
#pragma unroll
            for (int nt = 0; nt < 8; nt++) {
                uint4 bv = Bb[c8[nt] + sw];
                unsigned bh[2] = {bv.x, bv.z};
                unsigned bl[2] = {bv.y, bv.w};
#pragma unroll
                for (int mt = 0; mt < 2; mt++) {
                    mma_tf32(acc[mt][nt], ah[mt], bl);
                    mma_tf32(acc[mt][nt], ah[mt], bh);
                }
            }
        }
    }

    const int gid = lane >> 2, tig = lane & 3;
#pragma unroll
    for (int mt = 0; mt < 2; mt++) {
#pragma unroll
        for (int half = 0; half < 2; half++) {
            int r = row0 + wm * 32 + mt * 16 + half * 8 + gid;
#pragma unroll
            for (int nt = 0; nt < 8; nt++) {
                int c = col0 + wn * 64 + nt * 8 + tig * 2;
                if (c >= Nreal) continue;
                float v0 = acc[mt][nt][half * 2 + 0];
                float v1 = acc[mt][nt][half * 2 + 1];
                if (BMODE == 1) { v0 += bias[c]; v1 += bias[c + 1]; }
                float2 o; o.x = v0; o.y = v1;
                *(float2*)(C + (size_t)r * Nreal + c) = o;
            }
        }
    }
}

static void launch_fast(int bmode, const float* Ap, const float* Bp, float* C,
                        const float* bias, int nct, int Nreal)
{
    dim3 grid(nct, 256);
    if (bmode == 0) {
        cudaFuncSetAttribute(gemm_fast<0>, cudaFuncAttributeMaxDynamicSharedMemorySize, SMEM_FAST);
        gemm_fast<0><<<grid, 256, SMEM_FAST>>>(Ap, Bp, C, bias, Nreal);
    } else {
        cudaFuncSetAttribute(gemm_fast<1>, cudaFuncAttributeMaxDynamicSharedMemorySize, SMEM_FAST);
        gemm_fast<1><<<grid, 256, SMEM_FAST>>>(Ap, Bp, C, bias, Nreal);
    }
}

// --------------------- general GEMM (readout path, R7) ---------------------
#define APAD   20
#define BPADF2 132

template<int BMODE, int NSPLIT, int ASPL>
__global__ __launch_bounds__(256, 2) void gemm_tc(
    const void* __restrict__ Av, const float2* __restrict__ B,
    float* __restrict__ C, const float* __restrict__ bias,
    int M, int N, int K, int lda, int ldb, int ldc, int aStep)
{
    extern __shared__ char smraw[];
    constexpr int AELT = ASPL ? 8 : 4;
    constexpr int ABUF = 128 * APAD * AELT;
    float*  Af  = (float*)smraw;
    float2* Af2 = (float2*)smraw;
    float2* Bb  = (float2*)(smraw + 2 * ABUF);

    const int tid  = threadIdx.x;
    const int lane = tid & 31;
    const int w    = tid >> 5;
    const int wm   = w & 3;
    const int wn   = w >> 2;
    const int row0 = blockIdx.y * 128;
    const int col0 = blockIdx.x * 128;

    const int ktiles = (K + 15) >> 4;
    const int total  = ktiles * NSPLIT;

    float acc[2][8][4] = {};

    auto stage = [&](int t, int b) {
        const int sI = (NSPLIT == 1) ? 0 : (t / ktiles);
        const int kt = (NSPLIT == 1) ? t : (t % ktiles);
        const int k0 = kt << 4;
        if (ASPL == 0) {
            const float* Ap = (const float*)Av + (size_t)sI * aStep;
#pragma unroll
            for (int i = 0; i < 2; i++) {
                int ch = tid + (i << 8);
                int row = ch >> 2, part = (ch & 3) << 2;
                int gr = row0 + row, gk = k0 + part;
                int sb = (gr < M && gk < K) ? 16 : 0;
                const float* src = sb ? (Ap + (size_t)gr * lda + gk) : Ap;
                cpa16(&Af[(size_t)b * (ABUF / 4) + row * APAD + part], src, sb);
            }
        } else {
            const float2* Ap = (const float2*)Av + (size_t)sI * aStep;
#pragma unroll
            for (int i = 0; i < 4; i++) {
                int ch = tid + (i << 8);
                int row = ch >> 3, kp = (ch & 7) << 1;
                int gr = row0 + row, gk = k0 + kp;
                int sb = (gr < M && gk < K) ? 16 : 0;
                const float2* src = sb ? (Ap + (size_t)gr * lda + gk) : Ap;
                cpa16(&Af2[(size_t)b * (ABUF / 8) + row * APAD + kp], src, sb);
            }
        }
        if (NSPLIT == 1) {
#pragma unroll
            for (int i = 0; i < 4; i++) {
                int ch = tid + (i << 8);
                int krow = ch >> 6, cp = (ch & 63) << 1;
                int gk = k0 + krow, gc = col0 + cp;
                int sb = (gk < K && gc < N) ? 16 : 0;
                const float2* src = sb ? (B + (size_t)gk * ldb + gc) : B;
                cpa16(&Bb[(b * 16 + krow) * BPADF2 + cp], src, sb);
            }
        } else {
#pragma unroll
            for (int i = 0; i < 8; i++) {
                int ch = tid + (i << 8);
                int krow = ch >> 7, c = ch & 127;
                int gk = k0 + krow, gc = col0 + c;
                int sb = (gk < K && gc < N) ? 8 : 0;
                const float2* src = sb ? (B + (size_t)gk * ldb + gc + sI) : B;
                cpa8(&Bb[(b * 16 + krow) * BPADF2 + c], src, sb);
            }
        }
        asm volatile("cp.async.commit_group;");
    };

    stage(0, 0);
    asm volatile("cp.async.wait_group 0;");
    __syncthreads();

    int buf = 0;
    const int r_  = lane >> 2;
    const int cc_ = lane & 3;

    for (int t = 0; t < total; t++) {
        if (t + 1 < total) stage(t + 1, buf ^ 1);

#pragma unroll
        for (int k2 = 0; k2 < 2; k2++) {
            unsigned ah[2][4];
#pragma unroll
            for (int mt = 0; mt < 2; mt++) {
                int rb = wm * 32 + mt * 16;
                if (ASPL == 0) {
                    const float* Ar = Af + (size_t)buf * (ABUF / 4);
                    ah[mt][0] = f2tf32(Ar[(rb + r_    ) * APAD + k2 * 8 + cc_]);
                    ah[mt][1] = f2tf32(Ar[(rb + r_ + 8) * APAD + k2 * 8 + cc_]);
                    ah[mt][2] = f2tf32(Ar[(rb + r_    ) * APAD + k2 * 8 + cc_ + 4]);
                    ah[mt][3] = f2tf32(Ar[(rb + r_ + 8) * APAD + k2 * 8 + cc_ + 4]);
                } else {
                    const float2* Ar = Af2 + (size_t)buf * (ABUF / 8);
                    ah[mt][0] = __float_as_uint(Ar[(rb + r_    ) * APAD + k2 * 8 + cc_].x);
                    ah[mt][1] = __float_as_uint(Ar[(rb + r_ + 8) * APAD + k2 * 8 + cc_].x);
                    ah[mt][2] = __float_as_uint(Ar[(rb + r_    ) * APAD + k2 * 8 + cc_ + 4].x);
                    ah[mt][3] = __float_as_uint(Ar[(rb + r_ + 8) * APAD + k2 * 8 + cc_ + 4].x);
                }
            }
#pragma unroll
            for (int nt = 0; nt < 8; nt++) {
                int cb = wn * 64 + nt * 8 + r_;
                int kb = k2 * 8 + cc_;
                float2 g0 = Bb[(buf * 16 + kb    ) * BPADF2 + cb];
                float2 g1 = Bb[(buf * 16 + kb + 4) * BPADF2 + cb];
                unsigned bh[2], bl[2];
                bh[0] = __float_as_uint(g0.x); bl[0] = __float_as_uint(g0.y);
                bh[1] = __float_as_uint(g1.x); bl[1] = __float_as_uint(g1.y);
#pragma unroll
                for (int mt = 0; mt < 2; mt++) {
                    mma_tf32(acc[mt][nt], ah[mt], bl);
                    mma_tf32(acc[mt][nt], ah[mt], bh);
                }
            }
        }

        if (t + 1 < total) asm volatile("cp.async.wait_group 0;");
        __syncthreads();
        buf ^= 1;
    }

    const int gid = lane >> 2, tig = lane & 3;
#pragma unroll
    for (int mt = 0; mt < 2; mt++) {
#pragma unroll
        for (int half = 0; half < 2; half++) {
            int r = row0 + wm * 32 + mt * 16 + half * 8 + gid;
            if (r >= M) continue;
            float rb = (BMODE == 3) ? bias[r] : 0.f;
#pragma unroll
            for (int nt = 0; nt < 8; nt++) {
                int c = col0 + wn * 64 + nt * 8 + tig * 2;
                if (c >= N) continue;
                float v0 = acc[mt][nt][half * 2 + 0];
                float v1 = acc[mt][nt][half * 2 + 1];
                if (BMODE == 1)      { v0 += bias[c]; v1 += bias[c + 1]; }
                else if (BMODE == 3) { v0 += rb; v1 += rb; }
                float2 o; o.x = v0; o.y = v1;
                *(float2*)(C + (size_t)r * ldc + c) = o;
            }
        }
    }
}

#define SMEM_A0 (2 * 128 * APAD * 4 + 2 * 16 * BPADF2 * 8)
#define SMEM_A1 (2 * 128 * APAD * 8 + 2 * 16 * BPADF2 * 8)

template<int BMODE, int NSPLIT, int ASPL>
static void launch_gemm(const void* A, const float2* B, float* C, const float* bias,
                        int M, int N, int K, int lda, int ldb, int ldc, int aStep)
{
    constexpr int SM = ASPL ? SMEM_A1 : SMEM_A0;
    cudaFuncSetAttribute(gemm_tc<BMODE, NSPLIT, ASPL>,
                         cudaFuncAttributeMaxDynamicSharedMemorySize, SM);
    dim3 grid((N + 127) / 128, (M + 127) / 128);
    gemm_tc<BMODE, NSPLIT, ASPL><<<grid, 256, SM>>>(A, B, C, bias, M, N, K, lda, ldb, ldc, aStep);
}

// GRU gates: raw out + fragment-packed tf32 out
__global__ void gates_k(const float* __restrict__ hin, float* __restrict__ hout,
                        float* __restrict__ hp) {
    int idx = blockIdx.x * blockDim.x + threadIdx.x;
    if (idx < NTOT * 50) {
        int n = idx / 50, q = idx % 50;
        size_t g4 = (size_t)n * 150 + q;
        const float4* gi4 = (const float4*)d_gi;
        const float4* gh4 = (const float4*)d_gh;
        float4 ir4 = gi4[g4],        hr4 = gh4[g4];
        float4 iz4 = gi4[g4 + 50],   hz4 = gh4[g4 + 50];
        float4 in4 = gi4[g4 + 100],  hn4 = gh4[g4 + 100];
        float4 h4  = ((const float4*)hin)[(size_t)n * 50 + q];
        float4 o;
        {
            float r = 1.f / (1.f + __expf(-(ir4.x + hr4.x)));
            float z = 1.f / (1.f + __expf(-(iz4.x + hz4.x)));
            float nn = tanhf(in4.x + r * hn4.x);
            o.x = (1.f - z) * nn + z * h4.x;
        }
        {
            float r = 1.f / (1.f + __expf(-(ir4.y + hr4.y)));
            float z = 1.f / (1.f + __expf(-(iz4.y + hz4.y)));
            float nn = tanhf(in4.y + r * hn4.y);
            o.y = (1.f - z) * nn + z * h4.y;
        }
        {
            float r = 1.f / (1.f + __expf(-(ir4.z + hr4.z)));
            float z = 1.f / (1.f + __expf(-(iz4.z + hz4.z)));
            float nn = tanhf(in4.z + r * hn4.z);
            o.z = (1.f - z) * nn + z * h4.z;
        }
        {
            float r = 1.f / (1.f + __expf(-(ir4.w + hr4.w)));
            float z = 1.f / (1.f + __expf(-(iz4.w + hz4.w)));
            float nn = tanhf(in4.w + r * hn4.w);
            o.w = (1.f - z) * nn + z * h4.w;
        }
        ((float4*)hout)[(size_t)n * 50 + q] = o;
        int k0 = q * 4;
        hp[apack_idx(n, k0    )] = __uint_as_float(f2tf32(o.x));
        hp[apack_idx(n, k0 + 1)] = __uint_as_float(f2tf32(o.y));
        hp[apack_idx(n, k0 + 2)] = __uint_as_float(f2tf32(o.z));
        hp[apack_idx(n, k0 + 3)] = __uint_as_float(f2tf32(o.w));
    }
}

// in [G][C] raw -> out [C][G] hi/lo  (readout)
__global__ void transpose_hl_k(const float* __restrict__ in, float2* __restrict__ out,
                               int G, int C) {
    __shared__ float tile[32][33];
    int c0 = blockIdx.x * 32;
    int g0 = blockIdx.y * 32;
    int c = c0 + threadIdx.x;
#pragma unroll
    for (int j = 0; j < 32; j += 8) {
        int g = g0 + threadIdx.y + j;
        tile[threadIdx.y + j][threadIdx.x] = (c < C && g < G) ? in[(size_t)g * C + c] : 0.f;
    }
    __syncthreads();
    int g = g0 + threadIdx.x;
#pragma unroll
    for (int j = 0; j < 32; j += 8) {
        int cc = c0 + threadIdx.y + j;
        if (cc < C && g < G) out[(size_t)cc * G + g] = spl(tile[threadIdx.x][threadIdx.y + j]);
    }
}

__global__ void pool3_k(const float* __restrict__ in, float2* __restrict__ out, int C) {
    int idx = blockIdx.x * blockDim.x + threadIdx.x;
    if (idx < C * GP1) {
        int co = idx / GP1;
        int r = idx % GP1;
        int b = r / P1, p = r % P1;
        int base = co * NTOT + b * NPG + 2 * p;
        float m = fmaxf(fmaxf(in[base], in[base + 1]), in[base + 2]);
        out[idx] = spl(fmaxf(m, 0.f));
    }
}

__global__ void pool2_k(const float* __restrict__ in, float2* __restrict__ out, int C) {
    int idx = blockIdx.x * blockDim.x + threadIdx.x;
    if (idx < C * GP2) {
        int co = idx / GP2;
        int r = idx % GP2;
        int b = r / P2, p = r % P2;
        int base = co * GP1 + b * P1 + 2 * p;
        out[idx] = spl(fmaxf(fmaxf(in[base], in[base + 1]), 0.f));
    }
}

__global__ void final_k(const float* __restrict__ by, const float* __restrict__ bz,
                        float* __restrict__ out) {
    __shared__ float red[NCLS][128];
    int b = blockIdx.x;
    int tid = threadIdx.x;
    float part[NCLS] = {};
    for (int p = tid; p < P2; p += blockDim.x) {
        int base = b * P2 + p;
#pragma unroll
        for (int cl = 0; cl < NCLS; cl++) {
            float y = d_ly[cl * GP2 + base] + by[cl];
            float z = d_lz[cl * GP2 + base] + bz[cl];
            part[cl] += y * z;
        }
    }
#pragma unroll
    for (int cl = 0; cl < NCLS; cl++) red[cl][tid] = part[cl];
    __syncthreads();
    if (tid == 0) {
        float v[NCLS];
        for (int cl = 0; cl < NCLS; cl++) {
            float s = 0.f;
            for (int i = 0; i < 128; i++) s += red[cl][i];
            v[cl] = s / (float)P2;
        }
        float mx = v[0];
        for (int cl = 1; cl < NCLS; cl++) mx = fmaxf(mx, v[cl]);
        float se = 0.f;
        for (int cl = 0; cl < NCLS; cl++) { v[cl] = __expf(v[cl] - mx); se += v[cl]; }
        for (int cl = 0; cl < NCLS; cl++) out[b * NCLS + cl] = v[cl] / se;
    }
}

// ----------------------------- host side ----------------------------------
static void* getsym(const void* s) {
    void* p = nullptr;
    cudaGetSymbolAddress(&p, s);
    return p;
}

extern "C" void kernel_launch(void* const* d_in, const int* in_sizes, int n_in,
                              void* d_out, int out_size)
{
    const float* features = (const float*)d_in[0];
    const int*   esrc     = (const int*)  d_in[1];
    const int*   edst     = (const int*)  d_in[2];
    const int*   etyp     = (const int*)  d_in[3];
    const float* etype_W  = (const float*)d_in[4];
    const float* etype_b  = (const float*)d_in[5];
    const float* W_ih     = (const float*)d_in[6];
    const float* b_ih     = (const float*)d_in[7];
    const float* W_hh     = (const float*)d_in[8];
    const float* b_hh     = (const float*)d_in[9];
    const float* conv1_w  = (const float*)d_in[10];
    const float* conv1_b  = (const float*)d_in[11];
    const float* conv2_w  = (const float*)d_in[12];
    const float* conv2_b  = (const float*)d_in[13];
    const float* convc1_w = (const float*)d_in[14];
    const float* convc1_b = (const float*)d_in[15];
    const float* convc2_w = (const float*)d_in[16];
    const float* convc2_b = (const float*)d_in[17];
    const float* mlp_y_w  = (const float*)d_in[18];
    const float* mlp_y_b  = (const float*)d_in[19];
    const float* mlp_z_w  = (const float*)d_in[20];
    const float* mlp_z_b  = (const float*)d_in[21];

    float*  p_h0    = (float*) getsym(d_h0);
    float*  p_h1    = (float*) getsym(d_h1);
    float*  p_hp0   = (float*) getsym(d_hpack0);
    float*  p_hp1   = (float*) getsym(d_hpack1);
    float*  p_ap    = (float*) getsym(d_apack);
    float*  p_Ht    = (float*) getsym(d_Ht);
    float*  p_gi    = (float*) getsym(d_gi);
    float*  p_gh    = (float*) getsym(d_gh);
    float*  p_Wstp  = (float*) getsym(d_Wstp);
    float*  p_Wihp  = (float*) getsym(d_Wihp);
    float*  p_Whhp  = (float*) getsym(d_Whhp);
    int*    p_deg4  = (int*)   getsym(d_deg4);
    float2* p_cThl  = (float2*)getsym(d_cThl);
    float2* p_w1yhl = (float2*)getsym(d_w1yhl);
    float2* p_w1zhl = (float2*)getsym(d_w1zhl);
    float2* p_w2yhl = (float2*)getsym(d_w2yhl);
    float2* p_w2zhl = (float2*)getsym(d_w2zhl);
    float2* p_wmyhl = (float2*)getsym(d_wmyhl);
    float2* p_wmzhl = (float2*)getsym(d_wmzhl);
    float*  p_y1    = (float*) getsym(d_y1);
    float*  p_z1    = (float*) getsym(d_z1);
    float2* p_yp1hl = (float2*)getsym(d_yp1hl);
    float2* p_zp1hl = (float2*)getsym(d_zp1hl);
    float*  p_y2    = (float*) getsym(d_y2);
    float*  p_z2    = (float*) getsym(d_z2);
    float2* p_yp2hl = (float2*)getsym(d_yp2hl);
    float2* p_zp2hl = (float2*)getsym(d_zp2hl);
    float*  p_ly    = (float*) getsym(d_ly);
    float*  p_lz    = (float*) getsym(d_lz);

    const int T = 256;

    // ---- first launches: step-0 gh GEMM at profiler slot 3 ----
    zero_pack_k<<<(3 * 256 * 2048 + T - 1) / T, T>>>();                          // 0
    init_h_k<<<(NTOT * ODIM + T - 1) / T, T>>>(features);                        // 1
    packB_k<<<(5 * KT13 * 1024 + T - 1) / T, T>>>(W_hh, p_Whhp, H3, 5);          // 2
    launch_fast(1, p_hp0, p_Whhp, p_gh, b_hh, 5, H3);                            // 3

    // ---- rest of setup ----
    packB_k<<<(5 * KT13 * 1024 + T - 1) / T, T>>>(W_ih, p_Wihp, H3, 5);
    packB_k<<<(7 * KT13 * 1024 + T - 1) / T, T>>>(etype_W, p_Wstp, 4 * ODIM, 7);
    zero_int_k<<<(NTOT * 4 + T - 1) / T, T>>>(p_deg4, NTOT * 4);
    hist_k<<<(EDGES + T - 1) / T, T>>>(edst, etyp);
    scan_k<<<1, 1024>>>();
    chunk_hist_k<<<dim3(NCHK, BATCH), 512>>>(edst);
    chunk_scan_k<<<(NTOT + T - 1) / T, T>>>();
    scatter_k<<<dim3(NCHK, BATCH), 512>>>(esrc, edst, etyp);
    pack_conv_hl_k<<<(3 * ODIM * ODIM + T - 1) / T, T>>>(conv1_w, p_w1yhl, ODIM);
    pack_conv_hl_k<<<(3 * CDIM * CDIM + T - 1) / T, T>>>(convc1_w, p_w1zhl, CDIM);
    split_mat_k<<<(ODIM * ODIM + T - 1) / T, T>>>(conv2_w, p_w2yhl, ODIM * ODIM);
    split_mat_k<<<(CDIM * CDIM + T - 1) / T, T>>>(convc2_w, p_w2zhl, CDIM * CDIM);
    split_mat_k<<<(NCLS * ODIM + T - 1) / T, T>>>(mlp_y_w, p_wmyhl, NCLS * ODIM);
    split_mat_k<<<(NCLS * CDIM + T - 1) / T, T>>>(mlp_z_w, p_wmzhl, NCLS * CDIM);
    nodebias_k<<<(NTOT * ODIM + T - 1) / T, T>>>(etype_b);

    // ---- GGNN: 8 steps ----
    for (int s = 0; s < 8; s++) {
        const float* hin  = (s & 1) ? p_h1 : p_h0;
        float*       hout = (s & 1) ? p_h0 : p_h1;
        const float* hpin = (s & 1) ? p_hp1 : p_hp0;
        float*       hpout= (s & 1) ? p_hp0 : p_hp1;
        launch_fast(0, hpin, p_Wstp, p_Ht, nullptr, 7, 4 * ODIM);
        spmm_k<<<NTOT, 256>>>(p_Ht);
        launch_fast(1, p_ap, p_Wihp, p_gi, b_ih, 5, H3);
        if (s > 0)
            launch_fast(1, hpin, p_Whhp, p_gh, b_hh, 5, H3);
        gates_k<<<(NTOT * 50 + T - 1) / T, T>>>(hin, hout, hpout);
    }
    float* p_hf = p_h0;

    // ---- readout (R7 path) ----
    transpose_hl_k<<<dim3((ODIM + 31) / 32, NTOT / 32), dim3(32, 8)>>>(p_hf, p_cThl, NTOT, ODIM);
    transpose_hl_k<<<dim3((IDIM + 31) / 32, NTOT / 32), dim3(32, 8)>>>(features, p_cThl + (size_t)ODIM * NTOT, NTOT, IDIM);

    launch_gemm<3,3,1>(p_w1yhl, p_cThl, p_y1, conv1_b, ODIM, NTOT, ODIM, ODIM, NTOT, NTOT, ODIM * ODIM);
    pool3_k<<<(ODIM * GP1 + T - 1) / T, T>>>(p_y1, p_yp1hl, ODIM);
    launch_gemm<3,1,1>(p_w2yhl, p_yp1hl, p_y2, conv2_b, ODIM, GP1, ODIM, ODIM, GP1, GP1, 0);
    pool2_k<<<(ODIM * GP2 + T - 1) / T, T>>>(p_y2, p_yp2hl, ODIM);

    launch_gemm<3,3,1>(p_w1zhl, p_cThl, p_z1, convc1_b, CDIM, NTOT, CDIM, CDIM, NTOT, NTOT, CDIM * CDIM);
    pool3_k<<<(CDIM * GP1 + T - 1) / T, T>>>(p_z1, p_zp1hl, CDIM);
    launch_gemm<3,1,1>(p_w2zhl, p_zp1hl, p_z2, convc2_b, CDIM, GP1, CDIM, CDIM, GP1, GP1, 0);
    pool2_k<<<(CDIM * GP2 + T - 1) / T, T>>>(p_z2, p_zp2hl, CDIM);

    launch_gemm<0,1,1>(p_wmyhl, p_yp2hl, p_ly, nullptr, NCLS, GP2, ODIM, ODIM, GP2, GP2, 0);
    launch_gemm<0,1,1>(p_wmzhl, p_zp2hl, p_lz, nullptr, NCLS, GP2, CDIM, CDIM, GP2, GP2, 0);

    final_k<<<BATCH, 128>>>(mlp_y_b, mlp_z_b, (float*)d_out);
}

// round 9
// speedup vs baseline: 2.1415x; 1.3404x over previous
#include <cuda_runtime.h>

#define BATCH  64
#define NPG    512
#define NTOT   32768
#define EDGES  524288
#define EPG    8192
#define NCHK   16
#define ODIM   200
#define IDIM   100
#define H3     600
#define CDIM   300
#define P1     254
#define P2     127
#define GP1    16256
#define GP2    8128
#define NCLS   7
#define KT13   13                        /* 208 padded K / 16 */
#define HPACK_FLOATS (256*KT13*2048)

// ----------------------------- device scratch -----------------------------
__device__ float  d_h0[NTOT*ODIM];
__device__ float  d_h1[NTOT*ODIM];
__device__ float  d_hpack0[HPACK_FLOATS];
__device__ float  d_hpack1[HPACK_FLOATS];
__device__ float  d_apack[HPACK_FLOATS];
__device__ float  d_Ht[NTOT*4*ODIM];
__device__ float  d_gi[NTOT*H3];
__device__ float  d_gh[NTOT*H3];
__device__ float  d_Wstp[7*KT13*2048];   // packed B hi-only: 7 col-tiles
__device__ float  d_Wihp[5*KT13*2048];
__device__ float  d_Whhp[5*KT13*2048];
__device__ float  d_nbias[NTOT*ODIM];
__device__ int    d_deg4[NTOT*4];
__device__ int    d_indptr[NTOT+1];
__device__ int    d_ccnt[NTOT*NCHK];
__device__ int    d_srcs[EDGES];
__device__ int    d_typs[EDGES];
__device__ float2 d_cThl[CDIM*NTOT + 64];
__device__ float2 d_w1yhl[3*ODIM*ODIM];
__device__ float2 d_w1zhl[3*CDIM*CDIM];
__device__ float2 d_w2yhl[ODIM*ODIM];
__device__ float2 d_w2zhl[CDIM*CDIM];
__device__ float2 d_wmyhl[NCLS*ODIM];
__device__ float2 d_wmzhl[NCLS*CDIM];
__device__ float  d_y1[ODIM*NTOT];
__device__ float  d_z1[CDIM*NTOT];
__device__ float2 d_yp1hl[ODIM*GP1];
__device__ float2 d_zp1hl[CDIM*GP1];
__device__ float  d_y2[ODIM*GP1];
__device__ float  d_z2[CDIM*GP1];
__device__ float2 d_yp2hl[ODIM*GP2];
__device__ float2 d_zp2hl[CDIM*GP2];
__device__ float  d_ly[NCLS*GP2];
__device__ float  d_lz[NCLS*GP2];

// ----------------------------- helpers ------------------------------------
__device__ __forceinline__ unsigned f2tf32(float f) {
    unsigned u;
    asm("cvt.rna.tf32.f32 %0, %1;" : "=r"(u) : "f"(f));
    return u;
}
__device__ __forceinline__ float2 spl(float f) {
    unsigned h = f2tf32(f);
    float hf = __uint_as_float(h);
    unsigned l = f2tf32(f - hf);
    return make_float2(hf, __uint_as_float(l));
}
// fragment-packed A index (float index): vec16B = {(r,k),(r+8,k),(r,k+4),(r+8,k+4)}
__device__ __forceinline__ int apack_idx(int n, int k) {
    int rt = n >> 7, mb = (n >> 4) & 7, r = n & 7, hr = (n >> 3) & 1;
    int k8 = k >> 3, kt = k8 >> 1, k2 = k8 & 1, cc = k & 3, hk = (k >> 2) & 1;
    return (((rt * KT13 + kt) * 512) + (mb * 2 + k2) * 32 + r * 4 + cc) * 4 + hk * 2 + hr;
}

// ----------------------------- setup kernels ------------------------------
__global__ void zero_int_k(int* p, int n) {
    int i = blockIdx.x * blockDim.x + threadIdx.x;
    if (i < n) p[i] = 0;
}

__global__ void zero_pack_k() {
    int i = blockIdx.x * blockDim.x + threadIdx.x;
    const int per = 256 * 2048;
    if (i < 3 * per) {
        int b = i / per, r = i % per;
        int rt = r / 2048, off = r % 2048;
        float* p = (b == 0) ? d_hpack0 : (b == 1) ? d_hpack1 : d_apack;
        p[(rt * KT13 + 12) * 2048 + off] = 0.f;
    }
}

__global__ void hist_k(const int* __restrict__ edst, const int* __restrict__ etyp) {
    int e = blockIdx.x * blockDim.x + threadIdx.x;
    if (e < EDGES) atomicAdd(&d_deg4[edst[e] * 4 + etyp[e]], 1);
}

__global__ void scan_k() {
    __shared__ int ssum[1024];
    int t = threadIdx.x;
    int loc[32];
    int s = 0;
#pragma unroll
    for (int i = 0; i < 32; i++) {
        int n = t * 32 + i;
        int d = d_deg4[n*4] + d_deg4[n*4+1] + d_deg4[n*4+2] + d_deg4[n*4+3];
        loc[i] = s; s += d;
    }
    ssum[t] = s;
    __syncthreads();
    if (t == 0) {
        int acc = 0;
        for (int i = 0; i < 1024; i++) { int v = ssum[i]; ssum[i] = acc; acc += v; }
        d_indptr[NTOT] = acc;
    }
    __syncthreads();
    int off = ssum[t];
#pragma unroll
    for (int i = 0; i < 32; i++) d_indptr[t * 32 + i] = off + loc[i];
}

__global__ void chunk_hist_k(const int* __restrict__ edst) {
    __shared__ int h[NPG];
    int g = blockIdx.y, c = blockIdx.x;
    h[threadIdx.x] = 0;
    __syncthreads();
    int e = g * EPG + c * 512 + threadIdx.x;
    atomicAdd(&h[edst[e] - g * NPG], 1);
    __syncthreads();
    d_ccnt[(g * NPG + threadIdx.x) * NCHK + c] = h[threadIdx.x];
}

__global__ void chunk_scan_k() {
    int n = blockIdx.x * blockDim.x + threadIdx.x;
    if (n < NTOT) {
        int base = d_indptr[n];
#pragma unroll
        for (int c = 0; c < NCHK; c++) {
            int v = d_ccnt[n * NCHK + c];
            d_ccnt[n * NCHK + c] = base;
            base += v;
        }
    }
}

__global__ void scatter_k(const int* __restrict__ esrc, const int* __restrict__ edst,
                          const int* __restrict__ etyp) {
    __shared__ int sd[512];
    int g = blockIdx.y, c = blockIdx.x;
    int e = g * EPG + c * 512 + threadIdx.x;
    int dl = edst[e] - g * NPG;
    sd[threadIdx.x] = dl;
    __syncthreads();
    int rank = 0;
    for (int i = 0; i < threadIdx.x; i++) rank += (sd[i] == dl);
    int pos = d_ccnt[(g * NPG + dl) * NCHK + c] + rank;
    d_srcs[pos] = esrc[e];
    d_typs[pos] = etyp[e];
}

// pack B hi-only: vec(ct,kt,c,j) 16B = {hi(k),hi(k+4),hi(k+8),hi(k+12)}, k=kt*16+j
// linear vec position (ct*KT13+kt)*512 + c*4 + j  (conflict-free fragment loads)
__global__ void packB_k(const float* __restrict__ W, float* __restrict__ out,
                        int Nreal, int nct) {
    int t = blockIdx.x * blockDim.x + threadIdx.x;
    if (t >= nct * KT13 * 512) return;
    int j  = t & 3;
    int c  = (t >> 2) & 127;
    int kt = (t >> 9) % KT13;
    int ct = t / (KT13 * 512);
    int cg = ct * 128 + c;
    float4 v = make_float4(0.f, 0.f, 0.f, 0.f);
    if (cg < Nreal) {
        int k = kt * 16 + j;
        v.x = (k      < 200) ? __uint_as_float(f2tf32(W[cg * 200 + k     ])) : 0.f;
        v.y = (k + 4  < 200) ? __uint_as_float(f2tf32(W[cg * 200 + k + 4 ])) : 0.f;
        v.z = (k + 8  < 200) ? __uint_as_float(f2tf32(W[cg * 200 + k + 8 ])) : 0.f;
        v.w = (k + 12 < 200) ? __uint_as_float(f2tf32(W[cg * 200 + k + 12])) : 0.f;
    }
    ((float4*)out)[(ct * KT13 + kt) * 512 + c * 4 + j] = v;
}

// conv weight [C][C][3] -> [k][co][ci] hi/lo  (readout path)
__global__ void pack_conv_hl_k(const float* __restrict__ W, float2* __restrict__ out, int C) {
    int idx = blockIdx.x * blockDim.x + threadIdx.x;
    if (idx < 3 * C * C) {
        int ci = idx % C;
        int co = (idx / C) % C;
        int k  = idx / (C * C);
        out[idx] = spl(W[(co * C + ci) * 3 + k]);
    }
}

__global__ void split_mat_k(const float* __restrict__ in, float2* __restrict__ out, int n) {
    int i = blockIdx.x * blockDim.x + threadIdx.x;
    if (i < n) out[i] = spl(in[i]);
}

__global__ void init_h_k(const float* __restrict__ feat) {
    int idx = blockIdx.x * blockDim.x + threadIdx.x;
    if (idx < NTOT * ODIM) {
        int d = idx % ODIM;
        int n = idx / ODIM;
        float v = (d < IDIM) ? feat[n * IDIM + d] : 0.f;
        d_h0[idx] = v;
        d_hpack0[apack_idx(n, d)] = __uint_as_float(f2tf32(v));
    }
}

__global__ void nodebias_k(const float* __restrict__ eb) {
    int idx = blockIdx.x * blockDim.x + threadIdx.x;
    if (idx < NTOT * ODIM) {
        int o = idx % ODIM;
        int n = idx / ODIM;
        float s = 0.f;
#pragma unroll
        for (int t = 0; t < 4; t++) s += (float)d_deg4[n * 4 + t] * eb[t * ODIM + o];
        d_nbias[idx] = s;
    }
}

// a[n][o] = nbias + sum edges Ht[src][t*200+o]; writes fragment-packed tf32 a
__global__ void spmm_k(const float* __restrict__ Ht) {
    __shared__ int so[128];
    int n = blockIdx.x;
    int tid = threadIdx.x;
    int beg = d_indptr[n], end = d_indptr[n + 1];
    float a = 0.f;
    for (int base = beg; base < end; base += 128) {
        int cnt = min(128, end - base);
        if (tid < cnt) so[tid] = d_srcs[base + tid] * (4 * ODIM) + d_typs[base + tid] * ODIM;
        __syncthreads();
        if (tid < ODIM) {
            for (int e = 0; e < cnt; e++) a += Ht[so[e] + tid];
        }
        __syncthreads();
    }
    if (tid < ODIM) {
        float v = a + d_nbias[n * ODIM + tid];
        d_apack[apack_idx(n, tid)] = __uint_as_float(f2tf32(v));
    }
}

// ----------------------------- MMA helpers --------------------------------
__device__ __forceinline__ void mma_tf32(float* d, const unsigned* a, const unsigned* b) {
    asm volatile(
        "mma.sync.aligned.m16n8k8.row.col.f32.tf32.tf32.f32 "
        "{%0,%1,%2,%3}, {%4,%5,%6,%7}, {%8,%9}, {%0,%1,%2,%3};"
        : "+f"(d[0]), "+f"(d[1]), "+f"(d[2]), "+f"(d[3])
        : "r"(a[0]), "r"(a[1]), "r"(a[2]), "r"(a[3]), "r"(b[0]), "r"(b[1]));
}
__device__ __forceinline__ void cpa16(void* dst, const void* src, int sb) {
    unsigned sa = (unsigned)__cvta_generic_to_shared(dst);
    asm volatile("cp.async.cg.shared.global [%0], [%1], 16, %2;" :: "r"(sa), "l"(src), "r"(sb));
}
__device__ __forceinline__ void cpa16u(void* dst, const void* src) {
    unsigned sa = (unsigned)__cvta_generic_to_shared(dst);
    asm volatile("cp.async.cg.shared.global [%0], [%1], 16;" :: "r"(sa), "l"(src));
}
__device__ __forceinline__ void cpa8(void* dst, const void* src, int sb) {
    unsigned sa = (unsigned)__cvta_generic_to_shared(dst);
    asm volatile("cp.async.ca.shared.global [%0], [%1], 8, %2;" :: "r"(sa), "l"(src), "r"(sb));
}

// --------------------- fast GEMM (GGNN loop): 1xTF32 -----------------------
// M=32768, K=208 padded. A fragment-packed tf32; B hi-only fragment vecs.
// Per ktile: 4 A LDS.128 + 8 B LDS.128 + 32 MMA. 3-stage cp.async pipeline.
#define SMEM_FAST (3 * 1024 * 16)

template<int BMODE>
__global__ __launch_bounds__(256, 2) void gemm_fast(
    const float* __restrict__ Ap, const float* __restrict__ Bp,
    float* __restrict__ C, const float* __restrict__ bias, int Nreal)
{
    extern __shared__ float sm[];
    uint4* smv = (uint4*)sm;
    const int tid  = threadIdx.x;
    const int lane = tid & 31;
    const int w    = tid >> 5;
    const int wm   = w & 3;
    const int wn   = w >> 2;
    const int r_   = lane >> 2;
    const int cc_  = lane & 3;
    const int rt13 = blockIdx.y * KT13;
    const int ct13 = blockIdx.x * KT13;
    const int row0 = blockIdx.y * 128;
    const int col0 = blockIdx.x * 128;

    float acc[2][8][4] = {};

    int aoff[2][2];
#pragma unroll
    for (int mt = 0; mt < 2; mt++)
#pragma unroll
        for (int k2 = 0; k2 < 2; k2++)
            aoff[mt][k2] = ((wm * 2 + mt) * 2 + k2) * 32 + r_ * 4 + cc_;
    int c4[8];
#pragma unroll
    for (int nt = 0; nt < 8; nt++) c4[nt] = (wn * 64 + nt * 8 + r_) * 4 + cc_;

    auto stage = [&](int kt, int b) {
        uint4* d = smv + b * 1024;
        const uint4* sa = (const uint4*)Ap + (size_t)(rt13 + kt) * 512;
        cpa16u(&d[tid],       &sa[tid]);
        cpa16u(&d[tid + 256], &sa[tid + 256]);
        uint4* db = d + 512;
        const uint4* sb = (const uint4*)Bp + (size_t)(ct13 + kt) * 512;
        cpa16u(&db[tid],       &sb[tid]);
        cpa16u(&db[tid + 256], &sb[tid + 256]);
        asm volatile("cp.async.commit_group;");
    };

    stage(0, 0);
    stage(1, 1);

#pragma unroll 1
    for (int t = 0; t < KT13; t++) {
        if (t < KT13 - 1) asm volatile("cp.async.wait_group 1;");
        else              asm volatile("cp.async.wait_group 0;");
        __syncthreads();
        if (t + 2 < KT13) stage(t + 2, (t + 2) % 3);

        const uint4* Ab = smv + (t % 3) * 1024;
        const uint4* Bb = Ab + 512;

        unsigned ah[2][2][4];   // [k2][mt]
#pragma unroll
        for (int k2 = 0; k2 < 2; k2++)
#pragma unroll
            for (int mt = 0; mt < 2; mt++) {
                uint4 v = Ab[aoff[mt][k2]];
                ah[k2][mt][0] = v.x; ah[k2][mt][1] = v.y;
                ah[k2][mt][2] = v.z; ah[k2][mt][3] = v.w;
            }
#pragma unroll
        for (int nt = 0; nt < 8; nt++) {
            uint4 bv = Bb[c4[nt]];
            unsigned b0[2] = {bv.x, bv.y};
            unsigned b1[2] = {bv.z, bv.w};
#pragma unroll
            for (int mt = 0; mt < 2; mt++) {
                mma_tf32(acc[mt][nt], ah[0][mt], b0);
                mma_tf32(acc[mt][nt], ah[1][mt], b1);
            }
        }
    }

    const int gid = lane >> 2, tig = lane & 3;
#pragma unroll
    for (int mt = 0; mt < 2; mt++) {
#pragma unroll
        for (int half = 0; half < 2; half++) {
            int r = row0 + wm * 32 + mt * 16 + half * 8 + gid;
#pragma unroll
            for (int nt = 0; nt < 8; nt++) {
                int c = col0 + wn * 64 + nt * 8 + tig * 2;
                if (c >= Nreal) continue;
                float v0 = acc[mt][nt][half * 2 + 0];
                float v1 = acc[mt][nt][half * 2 + 1];
                if (BMODE == 1) { v0 += bias[c]; v1 += bias[c + 1]; }
                float2 o; o.x = v0; o.y = v1;
                *(float2*)(C + (size_t)r * Nreal + c) = o;
            }
        }
    }
}

static void launch_fast(int bmode, const float* Ap, const float* Bp, float* C,
                        const float* bias, int nct, int Nreal)
{
    dim3 grid(nct, 256);
    if (bmode == 0) {
        cudaFuncSetAttribute(gemm_fast<0>, cudaFuncAttributeMaxDynamicSharedMemorySize, SMEM_FAST);
        gemm_fast<0><<<grid, 256, SMEM_FAST>>>(Ap, Bp, C, bias, Nreal);
    } else {
        cudaFuncSetAttribute(gemm_fast<1>, cudaFuncAttributeMaxDynamicSharedMemorySize, SMEM_FAST);
        gemm_fast<1><<<grid, 256, SMEM_FAST>>>(Ap, Bp, C, bias, Nreal);
    }
}

// --------------------- general GEMM (readout path, 1xTF32) -----------------
#define APAD   20
#define BPADF2 132

template<int BMODE, int NSPLIT, int ASPL>
__global__ __launch_bounds__(256, 2) void gemm_tc(
    const void* __restrict__ Av, const float2* __restrict__ B,
    float* __restrict__ C, const float* __restrict__ bias,
    int M, int N, int K, int lda, int ldb, int ldc, int aStep)
{
    extern __shared__ char smraw[];
    constexpr int AELT = ASPL ? 8 : 4;
    constexpr int ABUF = 128 * APAD * AELT;
    float*  Af  = (float*)smraw;
    float2* Af2 = (float2*)smraw;
    float2* Bb  = (float2*)(smraw + 2 * ABUF);

    const int tid  = threadIdx.x;
    const int lane = tid & 31;
    const int w    = tid >> 5;
    const int wm   = w & 3;
    const int wn   = w >> 2;
    const int row0 = blockIdx.y * 128;
    const int col0 = blockIdx.x * 128;

    const int ktiles = (K + 15) >> 4;
    const int total  = ktiles * NSPLIT;

    float acc[2][8][4] = {};

    auto stage = [&](int t, int b) {
        const int sI = (NSPLIT == 1) ? 0 : (t / ktiles);
        const int kt = (NSPLIT == 1) ? t : (t % ktiles);
        const int k0 = kt << 4;
        if (ASPL == 0) {
            const float* Ap = (const float*)Av + (size_t)sI * aStep;
#pragma unroll
            for (int i = 0; i < 2; i++) {
                int ch = tid + (i << 8);
                int row = ch >> 2, part = (ch & 3) << 2;
                int gr = row0 + row, gk = k0 + part;
                int sb = (gr < M && gk < K) ? 16 : 0;
                const float* src = sb ? (Ap + (size_t)gr * lda + gk) : Ap;
                cpa16(&Af[(size_t)b * (ABUF / 4) + row * APAD + part], src, sb);
            }
        } else {
            const float2* Ap = (const float2*)Av + (size_t)sI * aStep;
#pragma unroll
            for (int i = 0; i < 4; i++) {
                int ch = tid + (i << 8);
                int row = ch >> 3, kp = (ch & 7) << 1;
                int gr = row0 + row, gk = k0 + kp;
                int sb = (gr < M && gk < K) ? 16 : 0;
                const float2* src = sb ? (Ap + (size_t)gr * lda + gk) : Ap;
                cpa16(&Af2[(size_t)b * (ABUF / 8) + row * APAD + kp], src, sb);
            }
        }
        if (NSPLIT == 1) {
#pragma unroll
            for (int i = 0; i < 4; i++) {
                int ch = tid + (i << 8);
                int krow = ch >> 6, cp = (ch & 63) << 1;
                int gk = k0 + krow, gc = col0 + cp;
                int sb = (gk < K && gc < N) ? 16 : 0;
                const float2* src = sb ? (B + (size_t)gk * ldb + gc) : B;
                cpa16(&Bb[(b * 16 + krow) * BPADF2 + cp], src, sb);
            }
        } else {
#pragma unroll
            for (int i = 0; i < 8; i++) {
                int ch = tid + (i << 8);
                int krow = ch >> 7, c = ch & 127;
                int gk = k0 + krow, gc = col0 + c;
                int sb = (gk < K && gc < N) ? 8 : 0;
                const float2* src = sb ? (B + (size_t)gk * ldb + gc + sI) : B;
                cpa8(&Bb[(b * 16 + krow) * BPADF2 + c], src, sb);
            }
        }
        asm volatile("cp.async.commit_group;");
    };

    stage(0, 0);
    asm volatile("cp.async.wait_group 0;");
    __syncthreads();

    int buf = 0;
    const int r_  = lane >> 2;
    const int cc_ = lane & 3;

    for (int t = 0; t < total; t++) {
        if (t + 1 < total) stage(t + 1, buf ^ 1);

#pragma unroll
        for (int k2 = 0; k2 < 2; k2++) {
            unsigned ah[2][4];
#pragma unroll
            for (int mt = 0; mt < 2; mt++) {
                int rb = wm * 32 + mt * 16;
                if (ASPL == 0) {
                    const float* Ar = Af + (size_t)buf * (ABUF / 4);
                    ah[mt][0] = f2tf32(Ar[(rb + r_    ) * APAD + k2 * 8 + cc_]);
                    ah[mt][1] = f2tf32(Ar[(rb + r_ + 8) * APAD + k2 * 8 + cc_]);
                    ah[mt][2] = f2tf32(Ar[(rb + r_    ) * APAD + k2 * 8 + cc_ + 4]);
                    ah[mt][3] = f2tf32(Ar[(rb + r_ + 8) * APAD + k2 * 8 + cc_ + 4]);
                } else {
                    const float2* Ar = Af2 + (size_t)buf * (ABUF / 8);
                    ah[mt][0] = __float_as_uint(Ar[(rb + r_    ) * APAD + k2 * 8 + cc_].x);
                    ah[mt][1] = __float_as_uint(Ar[(rb + r_ + 8) * APAD + k2 * 8 + cc_].x);
                    ah[mt][2] = __float_as_uint(Ar[(rb + r_    ) * APAD + k2 * 8 + cc_ + 4].x);
                    ah[mt][3] = __float_as_uint(Ar[(rb + r_ + 8) * APAD + k2 * 8 + cc_ + 4].x);
                }
            }
#pragma unroll
            for (int nt = 0; nt < 8; nt++) {
                int cb = wn * 64 + nt * 8 + r_;
                int kb = k2 * 8 + cc_;
                float2 g0 = Bb[(buf * 16 + kb    ) * BPADF2 + cb];
                float2 g1 = Bb[(buf * 16 + kb + 4) * BPADF2 + cb];
                unsigned bh[2];
                bh[0] = __float_as_uint(g0.x);
                bh[1] = __float_as_uint(g1.x);
#pragma unroll
                for (int mt = 0; mt < 2; mt++) {
                    mma_tf32(acc[mt][nt], ah[mt], bh);
                }
            }
        }

        if (t + 1 < total) asm volatile("cp.async.wait_group 0;");
        __syncthreads();
        buf ^= 1;
    }

    const int gid = lane >> 2, tig = lane & 3;
#pragma unroll
    for (int mt = 0; mt < 2; mt++) {
#pragma unroll
        for (int half = 0; half < 2; half++) {
            int r = row0 + wm * 32 + mt * 16 + half * 8 + gid;
            if (r >= M) continue;
            float rb = (BMODE == 3) ? bias[r] : 0.f;
#pragma unroll
            for (int nt = 0; nt < 8; nt++) {
                int c = col0 + wn * 64 + nt * 8 + tig * 2;
                if (c >= N) continue;
                float v0 = acc[mt][nt][half * 2 + 0];
                float v1 = acc[mt][nt][half * 2 + 1];
                if (BMODE == 1)      { v0 += bias[c]; v1 += bias[c + 1]; }
                else if (BMODE == 3) { v0 += rb; v1 += rb; }
                float2 o; o.x = v0; o.y = v1;
                *(float2*)(C + (size_t)r * ldc + c) = o;
            }
        }
    }
}

#define SMEM_A0 (2 * 128 * APAD * 4 + 2 * 16 * BPADF2 * 8)
#define SMEM_A1 (2 * 128 * APAD * 8 + 2 * 16 * BPADF2 * 8)

template<int BMODE, int NSPLIT, int ASPL>
static void launch_gemm(const void* A, const float2* B, float* C, const float* bias,
                        int M, int N, int K, int lda, int ldb, int ldc, int aStep)
{
    constexpr int SM = ASPL ? SMEM_A1 : SMEM_A0;
    cudaFuncSetAttribute(gemm_tc<BMODE, NSPLIT, ASPL>,
                         cudaFuncAttributeMaxDynamicSharedMemorySize, SM);
    dim3 grid((N + 127) / 128, (M + 127) / 128);
    gemm_tc<BMODE, NSPLIT, ASPL><<<grid, 256, SM>>>(A, B, C, bias, M, N, K, lda, ldb, ldc, aStep);
}

// GRU gates: raw out + fragment-packed tf32 out
__global__ void gates_k(const float* __restrict__ hin, float* __restrict__ hout,
                        float* __restrict__ hp) {
    int idx = blockIdx.x * blockDim.x + threadIdx.x;
    if (idx < NTOT * 50) {
        int n = idx / 50, q = idx % 50;
        size_t g4 = (size_t)n * 150 + q;
        const float4* gi4 = (const float4*)d_gi;
        const float4* gh4 = (const float4*)d_gh;
        float4 ir4 = gi4[g4],        hr4 = gh4[g4];
        float4 iz4 = gi4[g4 + 50],   hz4 = gh4[g4 + 50];
        float4 in4 = gi4[g4 + 100],  hn4 = gh4[g4 + 100];
        float4 h4  = ((const float4*)hin)[(size_t)n * 50 + q];
        float4 o;
        {
            float r = 1.f / (1.f + __expf(-(ir4.x + hr4.x)));
            float z = 1.f / (1.f + __expf(-(iz4.x + hz4.x)));
            float nn = tanhf(in4.x + r * hn4.x);
            o.x = (1.f - z) * nn + z * h4.x;
        }
        {
            float r = 1.f / (1.f + __expf(-(ir4.y + hr4.y)));
            float z = 1.f / (1.f + __expf(-(iz4.y + hz4.y)));
            float nn = tanhf(in4.y + r * hn4.y);
            o.y = (1.f - z) * nn + z * h4.y;
        }
        {
            float r = 1.f / (1.f + __expf(-(ir4.z + hr4.z)));
            float z = 1.f / (1.f + __expf(-(iz4.z + hz4.z)));
            float nn = tanhf(in4.z + r * hn4.z);
            o.z = (1.f - z) * nn + z * h4.z;
        }
        {
            float r = 1.f / (1.f + __expf(-(ir4.w + hr4.w)));
            float z = 1.f / (1.f + __expf(-(iz4.w + hz4.w)));
            float nn = tanhf(in4.w + r * hn4.w);
            o.w = (1.f - z) * nn + z * h4.w;
        }
        ((float4*)hout)[(size_t)n * 50 + q] = o;
        int k0 = q * 4;
        hp[apack_idx(n, k0    )] = __uint_as_float(f2tf32(o.x));
        hp[apack_idx(n, k0 + 1)] = __uint_as_float(f2tf32(o.y));
        hp[apack_idx(n, k0 + 2)] = __uint_as_float(f2tf32(o.z));
        hp[apack_idx(n, k0 + 3)] = __uint_as_float(f2tf32(o.w));
    }
}

// in [G][C] raw -> out [C][G] hi/lo  (readout)
__global__ void transpose_hl_k(const float* __restrict__ in, float2* __restrict__ out,
                               int G, int C) {
    __shared__ float tile[32][33];
    int c0 = blockIdx.x * 32;
    int g0 = blockIdx.y * 32;
    int c = c0 + threadIdx.x;
#pragma unroll
    for (int j = 0; j < 32; j += 8) {
        int g = g0 + threadIdx.y + j;
        tile[threadIdx.y + j][threadIdx.x] = (c < C && g < G) ? in[(size_t)g * C + c] : 0.f;
    }
    __syncthreads();
    int g = g0 + threadIdx.x;
#pragma unroll
    for (int j = 0; j < 32; j += 8) {
        int cc = c0 + threadIdx.y + j;
        if (cc < C && g < G) out[(size_t)cc * G + g] = spl(tile[threadIdx.x][threadIdx.y + j]);
    }
}

__global__ void pool3_k(const float* __restrict__ in, float2* __restrict__ out, int C) {
    int idx = blockIdx.x * blockDim.x + threadIdx.x;
    if (idx < C * GP1) {
        int co = idx / GP1;
        int r = idx % GP1;
        int b = r / P1, p = r % P1;
        int base = co * NTOT + b * NPG + 2 * p;
        float m = fmaxf(fmaxf(in[base], in[base + 1]), in[base + 2]);
        out[idx] = spl(fmaxf(m, 0.f));
    }
}

__global__ void pool2_k(const float* __restrict__ in, float2* __restrict__ out, int C) {
    int idx = blockIdx.x * blockDim.x + threadIdx.x;
    if (idx < C * GP2) {
        int co = idx / GP2;
        int r = idx % GP2;
        int b = r / P2, p = r % P2;
        int base = co * GP1 + b * P1 + 2 * p;
        out[idx] = spl(fmaxf(fmaxf(in[base], in[base + 1]), 0.f));
    }
}

__global__ void final_k(const float* __restrict__ by, const float* __restrict__ bz,
                        float* __restrict__ out) {
    __shared__ float red[NCLS][128];
    int b = blockIdx.x;
    int tid = threadIdx.x;
    float part[NCLS] = {};
    for (int p = tid; p < P2; p += blockDim.x) {
        int base = b * P2 + p;
#pragma unroll
        for (int cl = 0; cl < NCLS; cl++) {
            float y = d_ly[cl * GP2 + base] + by[cl];
            float z = d_lz[cl * GP2 + base] + bz[cl];
            part[cl] += y * z;
        }
    }
#pragma unroll
    for (int cl = 0; cl < NCLS; cl++) red[cl][tid] = part[cl];
    __syncthreads();
    if (tid == 0) {
        float v[NCLS];
        for (int cl = 0; cl < NCLS; cl++) {
            float s = 0.f;
            for (int i = 0; i < 128; i++) s += red[cl][i];
            v[cl] = s / (float)P2;
        }
        float mx = v[0];
        for (int cl = 1; cl < NCLS; cl++) mx = fmaxf(mx, v[cl]);
        float se = 0.f;
        for (int cl = 0; cl < NCLS; cl++) { v[cl] = __expf(v[cl] - mx); se += v[cl]; }
        for (int cl = 0; cl < NCLS; cl++) out[b * NCLS + cl] = v[cl] / se;
    }
}

// ----------------------------- host side ----------------------------------
static void* getsym(const void* s) {
    void* p = nullptr;
    cudaGetSymbolAddress(&p, s);
    return p;
}

extern "C" void kernel_launch(void* const* d_in, const int* in_sizes, int n_in,
                              void* d_out, int out_size)
{
    const float* features = (const float*)d_in[0];
    const int*   esrc     = (const int*)  d_in[1];
    const int*   edst     = (const int*)  d_in[2];
    const int*   etyp     = (const int*)  d_in[3];
    const float* etype_W  = (const float*)d_in[4];
    const float* etype_b  = (const float*)d_in[5];
    const float* W_ih     = (const float*)d_in[6];
    const float* b_ih     = (const float*)d_in[7];
    const float* W_hh     = (const float*)d_in[8];
    const float* b_hh     = (const float*)d_in[9];
    const float* conv1_w  = (const float*)d_in[10];
    const float* conv1_b  = (const float*)d_in[11];
    const float* conv2_w  = (const float*)d_in[12];
    const float* conv2_b  = (const float*)d_in[13];
    const float* convc1_w = (const float*)d_in[14];
    const float* convc1_b = (const float*)d_in[15];
    const float* convc2_w = (const float*)d_in[16];
    const float* convc2_b = (const float*)d_in[17];
    const float* mlp_y_w  = (const float*)d_in[18];
    const float* mlp_y_b  = (const float*)d_in[19];
    const float* mlp_z_w  = (const float*)d_in[20];
    const float* mlp_z_b  = (const float*)d_in[21];

    float*  p_h0    = (float*) getsym(d_h0);
    float*  p_h1    = (float*) getsym(d_h1);
    float*  p_hp0   = (float*) getsym(d_hpack0);
    float*  p_hp1   = (float*) getsym(d_hpack1);
    float*  p_ap    = (float*) getsym(d_apack);
    float*  p_Ht    = (float*) getsym(d_Ht);
    float*  p_gi    = (float*) getsym(d_gi);
    float*  p_gh    = (float*) getsym(d_gh);
    float*  p_Wstp  = (float*) getsym(d_Wstp);
    float*  p_Wihp  = (float*) getsym(d_Wihp);
    float*  p_Whhp  = (float*) getsym(d_Whhp);
    int*    p_deg4  = (int*)   getsym(d_deg4);
    float2* p_cThl  = (float2*)getsym(d_cThl);
    float2* p_w1yhl = (float2*)getsym(d_w1yhl);
    float2* p_w1zhl = (float2*)getsym(d_w1zhl);
    float2* p_w2yhl = (float2*)getsym(d_w2yhl);
    float2* p_w2zhl = (float2*)getsym(d_w2zhl);
    float2* p_wmyhl = (float2*)getsym(d_wmyhl);
    float2* p_wmzhl = (float2*)getsym(d_wmzhl);
    float*  p_y1    = (float*) getsym(d_y1);
    float*  p_z1    = (float*) getsym(d_z1);
    float2* p_yp1hl = (float2*)getsym(d_yp1hl);
    float2* p_zp1hl = (float2*)getsym(d_zp1hl);
    float*  p_y2    = (float*) getsym(d_y2);
    float*  p_z2    = (float*) getsym(d_z2);
    float2* p_yp2hl = (float2*)getsym(d_yp2hl);
    float2* p_zp2hl = (float2*)getsym(d_zp2hl);
    float*  p_ly    = (float*) getsym(d_ly);
    float*  p_lz    = (float*) getsym(d_lz);

    const int T = 256;

    // ---- first launches: step-0 gh GEMM at profiler slot 3 ----
    zero_pack_k<<<(3 * 256 * 2048 + T - 1) / T, T>>>();                          // 0
    init_h_k<<<(NTOT * ODIM + T - 1) / T, T>>>(features);                        // 1
    packB_k<<<(5 * KT13 * 512 + T - 1) / T, T>>>(W_hh, p_Whhp, H3, 5);           // 2
    launch_fast(1, p_hp0, p_Whhp, p_gh, b_hh, 5, H3);                            // 3

    // ---- rest of setup ----
    packB_k<<<(5 * KT13 * 512 + T - 1) / T, T>>>(W_ih, p_Wihp, H3, 5);
    packB_k<<<(7 * KT13 * 512 + T - 1) / T, T>>>(etype_W, p_Wstp, 4 * ODIM, 7);
    zero_int_k<<<(NTOT * 4 + T - 1) / T, T>>>(p_deg4, NTOT * 4);
    hist_k<<<(EDGES + T - 1) / T, T>>>(edst, etyp);
    scan_k<<<1, 1024>>>();
    chunk_hist_k<<<dim3(NCHK, BATCH), 512>>>(edst);
    chunk_scan_k<<<(NTOT + T - 1) / T, T>>>();
    scatter_k<<<dim3(NCHK, BATCH), 512>>>(esrc, edst, etyp);
    pack_conv_hl_k<<<(3 * ODIM * ODIM + T - 1) / T, T>>>(conv1_w, p_w1yhl, ODIM);
    pack_conv_hl_k<<<(3 * CDIM * CDIM + T - 1) / T, T>>>(convc1_w, p_w1zhl, CDIM);
    split_mat_k<<<(ODIM * ODIM + T - 1) / T, T>>>(conv2_w, p_w2yhl, ODIM * ODIM);
    split_mat_k<<<(CDIM * CDIM + T - 1) / T, T>>>(convc2_w, p_w2zhl, CDIM * CDIM);
    split_mat_k<<<(NCLS * ODIM + T - 1) / T, T>>>(mlp_y_w, p_wmyhl, NCLS * ODIM);
    split_mat_k<<<(NCLS * CDIM + T - 1) / T, T>>>(mlp_z_w, p_wmzhl, NCLS * CDIM);
    nodebias_k<<<(NTOT * ODIM + T - 1) / T, T>>>(etype_b);

    // ---- GGNN: 8 steps ----
    for (int s = 0; s < 8; s++) {
        const float* hin  = (s & 1) ? p_h1 : p_h0;
        float*       hout = (s & 1) ? p_h0 : p_h1;
        const float* hpin = (s & 1) ? p_hp1 : p_hp0;
        float*       hpout= (s & 1) ? p_hp0 : p_hp1;
        launch_fast(0, hpin, p_Wstp, p_Ht, nullptr, 7, 4 * ODIM);
        spmm_k<<<NTOT, 256>>>(p_Ht);
        launch_fast(1, p_ap, p_Wihp, p_gi, b_ih, 5, H3);
        if (s > 0)
            launch_fast(1, hpin, p_Whhp, p_gh, b_hh, 5, H3);
        gates_k<<<(NTOT * 50 + T - 1) / T, T>>>(hin, hout, hpout);
    }
    float* p_hf = p_h0;

    // ---- readout ----
    transpose_hl_k<<<dim3((ODIM + 31) / 32, NTOT / 32), dim3(32, 8)>>>(p_hf, p_cThl, NTOT, ODIM);
    transpose_hl_k<<<dim3((IDIM + 31) / 32, NTOT / 32), dim3(32, 8)>>>(features, p_cThl + (size_t)ODIM * NTOT, NTOT, IDIM);

    launch_gemm<3,3,1>(p_w1yhl, p_cThl, p_y1, conv1_b, ODIM, NTOT, ODIM, ODIM, NTOT, NTOT, ODIM * ODIM);
    pool3_k<<<(ODIM * GP1 + T - 1) / T, T>>>(p_y1, p_yp1hl, ODIM);
    launch_gemm<3,1,1>(p_w2yhl, p_yp1hl, p_y2, conv2_b, ODIM, GP1, ODIM, ODIM, GP1, GP1, 0);
    pool2_k<<<(ODIM * GP2 + T - 1) / T, T>>>(p_y2, p_yp2hl, ODIM);

    launch_gemm<3,3,1>(p_w1zhl, p_cThl, p_z1, convc1_b, CDIM, NTOT, CDIM, CDIM, NTOT, NTOT, CDIM * CDIM);
    pool3_k<<<(CDIM * GP1 + T - 1) / T, T>>>(p_z1, p_zp1hl, CDIM);
    launch_gemm<3,1,1>(p_w2zhl, p_zp1hl, p_z2, convc2_b, CDIM, GP1, CDIM, CDIM, GP1, GP1, 0);
    pool2_k<<<(CDIM * GP2 + T - 1) / T, T>>>(p_z2, p_zp2hl, CDIM);

    launch_gemm<0,1,1>(p_wmyhl, p_yp2hl, p_ly, nullptr, NCLS, GP2, ODIM, ODIM, GP2, GP2, 0);
    launch_gemm<0,1,1>(p_wmzhl, p_zp2hl, p_lz, nullptr, NCLS, GP2, CDIM, CDIM, GP2, GP2, 0);

    final_k<<<BATCH, 128>>>(mlp_y_b, mlp_z_b, (float*)d_out);
}

// round 11
// speedup vs baseline: 2.2104x; 1.0322x over previous
#include <cuda_runtime.h>
#include <cuda_fp16.h>

#define BATCH  64
#define NPG    512
#define NTOT   32768
#define EDGES  524288
#define EPG    8192
#define NCHK   16
#define ODIM   200
#define IDIM   100
#define H3     600
#define CDIM   300
#define P1     254
#define P2     127
#define GP1    16256
#define GP2    8128
#define NCLS   7
#define KT13   13
#define HPACK_FLOATS (256*KT13*2048)

// ----------------------------- device scratch -----------------------------
__device__ float  d_h0[NTOT*ODIM];
__device__ float  d_h1[NTOT*ODIM];
__device__ float  d_hpack0[HPACK_FLOATS];
__device__ float  d_hpack1[HPACK_FLOATS];
__device__ float  d_apack[HPACK_FLOATS];
__device__ __half d_Hth[NTOT*4*ODIM];
__device__ __half d_gih[NTOT*H3];
__device__ __half d_ghh[NTOT*H3];
__device__ float  d_Wcombp[12*KT13*2048];  // packed B: 7 ct Wstack + 5 ct Whh
__device__ float  d_Wihp[5*KT13*2048];
__device__ float  d_nbias[NTOT*ODIM];
__device__ int    d_deg4[NTOT*4];
__device__ int    d_indptr[NTOT+1];
__device__ int    d_ccnt[NTOT*NCHK];
__device__ int    d_srcs[EDGES];
__device__ int    d_typs[EDGES];
__device__ float2 d_cThl[CDIM*NTOT + 64];
__device__ float2 d_w1yhl[3*ODIM*ODIM];
__device__ float2 d_w1zhl[3*CDIM*CDIM];
__device__ float2 d_w2yhl[ODIM*ODIM];
__device__ float2 d_w2zhl[CDIM*CDIM];
__device__ float2 d_wmyhl[NCLS*ODIM];
__device__ float2 d_wmzhl[NCLS*CDIM];
__device__ float  d_y1[ODIM*NTOT];
__device__ float  d_z1[CDIM*NTOT];
__device__ float2 d_yp1hl[ODIM*GP1];
__device__ float2 d_zp1hl[CDIM*GP1];
__device__ float  d_y2[ODIM*GP1];
__device__ float  d_z2[CDIM*GP1];
__device__ float2 d_yp2hl[ODIM*GP2];
__device__ float2 d_zp2hl[CDIM*GP2];
__device__ float  d_ly[NCLS*GP2];
__device__ float  d_lz[NCLS*GP2];

// ----------------------------- helpers ------------------------------------
__device__ __forceinline__ unsigned f2tf32(float f) {
    unsigned u;
    asm("cvt.rna.tf32.f32 %0, %1;" : "=r"(u) : "f"(f));
    return u;
}
__device__ __forceinline__ float2 spl(float f) {
    unsigned h = f2tf32(f);
    float hf = __uint_as_float(h);
    unsigned l = f2tf32(f - hf);
    return make_float2(hf, __uint_as_float(l));
}
__device__ __forceinline__ int apack_idx(int n, int k) {
    int rt = n >> 7, mb = (n >> 4) & 7, r = n & 7, hr = (n >> 3) & 1;
    int k8 = k >> 3, kt = k8 >> 1, k2 = k8 & 1, cc = k & 3, hk = (k >> 2) & 1;
    return (((rt * KT13 + kt) * 512) + (mb * 2 + k2) * 32 + r * 4 + cc) * 4 + hk * 2 + hr;
}

// ----------------------------- setup kernels ------------------------------
__global__ void zero_int_k(int* p, int n) {
    int i = blockIdx.x * blockDim.x + threadIdx.x;
    if (i < n) p[i] = 0;
}

__global__ void zero_pack_k() {
    int i = blockIdx.x * blockDim.x + threadIdx.x;
    const int per = 256 * 2048;
    if (i < 3 * per) {
        int b = i / per, r = i % per;
        int rt = r / 2048, off = r % 2048;
        float* p = (b == 0) ? d_hpack0 : (b == 1) ? d_hpack1 : d_apack;
        p[(rt * KT13 + 12) * 2048 + off] = 0.f;
    }
}

__global__ void hist_k(const int* __restrict__ edst, const int* __restrict__ etyp) {
    int e = blockIdx.x * blockDim.x + threadIdx.x;
    if (e < EDGES) atomicAdd(&d_deg4[edst[e] * 4 + etyp[e]], 1);
}

__global__ void scan_k() {
    __shared__ int ssum[1024];
    int t = threadIdx.x;
    int loc[32];
    int s = 0;
#pragma unroll
    for (int i = 0; i < 32; i++) {
        int n = t * 32 + i;
        int d = d_deg4[n*4] + d_deg4[n*4+1] + d_deg4[n*4+2] + d_deg4[n*4+3];
        loc[i] = s; s += d;
    }
    ssum[t] = s;
    __syncthreads();
    if (t == 0) {
        int acc = 0;
        for (int i = 0; i < 1024; i++) { int v = ssum[i]; ssum[i] = acc; acc += v; }
        d_indptr[NTOT] = acc;
    }
    __syncthreads();
    int off = ssum[t];
#pragma unroll
    for (int i = 0; i < 32; i++) d_indptr[t * 32 + i] = off + loc[i];
}

__global__ void chunk_hist_k(const int* __restrict__ edst) {
    __shared__ int h[NPG];
    int g = blockIdx.y, c = blockIdx.x;
    h[threadIdx.x] = 0;
    __syncthreads();
    int e = g * EPG + c * 512 + threadIdx.x;
    atomicAdd(&h[edst[e] - g * NPG], 1);
    __syncthreads();
    d_ccnt[(g * NPG + threadIdx.x) * NCHK + c] = h[threadIdx.x];
}

__global__ void chunk_scan_k() {
    int n = blockIdx.x * blockDim.x + threadIdx.x;
    if (n < NTOT) {
        int base = d_indptr[n];
#pragma unroll
        for (int c = 0; c < NCHK; c++) {
            int v = d_ccnt[n * NCHK + c];
            d_ccnt[n * NCHK + c] = base;
            base += v;
        }
    }
}

__global__ void scatter_k(const int* __restrict__ esrc, const int* __restrict__ edst,
                          const int* __restrict__ etyp) {
    __shared__ int sd[512];
    int g = blockIdx.y, c = blockIdx.x;
    int e = g * EPG + c * 512 + threadIdx.x;
    int dl = edst[e] - g * NPG;
    sd[threadIdx.x] = dl;
    __syncthreads();
    int rank = 0;
    for (int i = 0; i < threadIdx.x; i++) rank += (sd[i] == dl);
    int pos = d_ccnt[(g * NPG + dl) * NCHK + c] + rank;
    d_srcs[pos] = esrc[e];
    d_typs[pos] = etyp[e];
}

// combined B pack: ct 0..6 = etype_W as [800][200]; ct 7..11 = W_hh [600][200].
// hi-only 16B vec {hi(k),hi(k+4),hi(k+8),hi(k+12)}, linear position.
__global__ void packB_comb(const float* __restrict__ Wst, const float* __restrict__ Whh) {
    int t = blockIdx.x * blockDim.x + threadIdx.x;
    if (t >= 12 * KT13 * 512) return;
    int j  = t & 3;
    int c  = (t >> 2) & 127;
    int kt = (t >> 9) % KT13;
    int ct = t / (KT13 * 512);
    const float* W; int Nreal, cg;
    if (ct < 7) { W = Wst; Nreal = 800; cg = ct * 128 + c; }
    else        { W = Whh; Nreal = 600; cg = (ct - 7) * 128 + c; }
    float4 v = make_float4(0.f, 0.f, 0.f, 0.f);
    if (cg < Nreal) {
        int k = kt * 16 + j;
        v.x = (k      < 200) ? __uint_as_float(f2tf32(W[cg * 200 + k     ])) : 0.f;
        v.y = (k + 4  < 200) ? __uint_as_float(f2tf32(W[cg * 200 + k + 4 ])) : 0.f;
        v.z = (k + 8  < 200) ? __uint_as_float(f2tf32(W[cg * 200 + k + 8 ])) : 0.f;
        v.w = (k + 12 < 200) ? __uint_as_float(f2tf32(W[cg * 200 + k + 12])) : 0.f;
    }
    ((float4*)d_Wcombp)[(ct * KT13 + kt) * 512 + c * 4 + j] = v;
}

// single-source B pack (Wih)
__global__ void packB_k(const float* __restrict__ W, float* __restrict__ out,
                        int Nreal, int nct) {
    int t = blockIdx.x * blockDim.x + threadIdx.x;
    if (t >= nct * KT13 * 512) return;
    int j  = t & 3;
    int c  = (t >> 2) & 127;
    int kt = (t >> 9) % KT13;
    int ct = t / (KT13 * 512);
    int cg = ct * 128 + c;
    float4 v = make_float4(0.f, 0.f, 0.f, 0.f);
    if (cg < Nreal) {
        int k = kt * 16 + j;
        v.x = (k      < 200) ? __uint_as_float(f2tf32(W[cg * 200 + k     ])) : 0.f;
        v.y = (k + 4  < 200) ? __uint_as_float(f2tf32(W[cg * 200 + k + 4 ])) : 0.f;
        v.z = (k + 8  < 200) ? __uint_as_float(f2tf32(W[cg * 200 + k + 8 ])) : 0.f;
        v.w = (k + 12 < 200) ? __uint_as_float(f2tf32(W[cg * 200 + k + 12])) : 0.f;
    }
    ((float4*)out)[(ct * KT13 + kt) * 512 + c * 4 + j] = v;
}

__global__ void pack_conv_hl_k(const float* __restrict__ W, float2* __restrict__ out, int C) {
    int idx = blockIdx.x * blockDim.x + threadIdx.x;
    if (idx < 3 * C * C) {
        int ci = idx % C;
        int co = (idx / C) % C;
        int k  = idx / (C * C);
        out[idx] = spl(W[(co * C + ci) * 3 + k]);
    }
}

__global__ void split_mat_k(const float* __restrict__ in, float2* __restrict__ out, int n) {
    int i = blockIdx.x * blockDim.x + threadIdx.x;
    if (i < n) out[i] = spl(in[i]);
}

__global__ void init_h_k(const float* __restrict__ feat) {
    int idx = blockIdx.x * blockDim.x + threadIdx.x;
    if (idx < NTOT * ODIM) {
        int d = idx % ODIM;
        int n = idx / ODIM;
        float v = (d < IDIM) ? feat[n * IDIM + d] : 0.f;
        d_h0[idx] = v;
        d_hpack0[apack_idx(n, d)] = __uint_as_float(f2tf32(v));
    }
}

__global__ void nodebias_k(const float* __restrict__ eb) {
    int idx = blockIdx.x * blockDim.x + threadIdx.x;
    if (idx < NTOT * ODIM) {
        int o = idx % ODIM;
        int n = idx / ODIM;
        float s = 0.f;
#pragma unroll
        for (int t = 0; t < 4; t++) s += (float)d_deg4[n * 4 + t] * eb[t * ODIM + o];
        d_nbias[idx] = s;
    }
}

// a[n][o] = nbias + sum edges Ht_h[src][t*200+o]; writes fragment-packed tf32 a
__global__ void spmm_k(const __half* __restrict__ Ht) {
    __shared__ int so[128];
    int n = blockIdx.x;
    int tid = threadIdx.x;
    int beg = d_indptr[n], end = d_indptr[n + 1];
    float a = 0.f;
    for (int base = beg; base < end; base += 128) {
        int cnt = min(128, end - base);
        if (tid < cnt) so[tid] = d_srcs[base + tid] * 800 + d_typs[base + tid] * ODIM;
        __syncthreads();
        if (tid < ODIM) {
            for (int e = 0; e < cnt; e++) a += __half2float(Ht[so[e] + tid]);
        }
        __syncthreads();
    }
    if (tid < ODIM) {
        float v = a + d_nbias[n * ODIM + tid];
        d_apack[apack_idx(n, tid)] = __uint_as_float(f2tf32(v));
    }
}

// ----------------------------- MMA helpers --------------------------------
__device__ __forceinline__ void mma_tf32(float* d, const unsigned* a, const unsigned* b) {
    asm volatile(
        "mma.sync.aligned.m16n8k8.row.col.f32.tf32.tf32.f32 "
        "{%0,%1,%2,%3}, {%4,%5,%6,%7}, {%8,%9}, {%0,%1,%2,%3};"
        : "+f"(d[0]), "+f"(d[1]), "+f"(d[2]), "+f"(d[3])
        : "r"(a[0]), "r"(a[1]), "r"(a[2]), "r"(a[3]), "r"(b[0]), "r"(b[1]));
}
__device__ __forceinline__ void cpa16(void* dst, const void* src, int sb) {
    unsigned sa = (unsigned)__cvta_generic_to_shared(dst);
    asm volatile("cp.async.cg.shared.global [%0], [%1], 16, %2;" :: "r"(sa), "l"(src), "r"(sb));
}
__device__ __forceinline__ void cpa16u(void* dst, const void* src) {
    unsigned sa = (unsigned)__cvta_generic_to_shared(dst);
    asm volatile("cp.async.cg.shared.global [%0], [%1], 16;" :: "r"(sa), "l"(src));
}
__device__ __forceinline__ void cpa8(void* dst, const void* src, int sb) {
    unsigned sa = (unsigned)__cvta_generic_to_shared(dst);
    asm volatile("cp.async.ca.shared.global [%0], [%1], 8, %2;" :: "r"(sa), "l"(src), "r"(sb));
}

// --------------------- fast GEMM (GGNN loop): 1xTF32, fp16 out -------------
// Dual-target: blocks with blockIdx.x < splitCt write C1 (cols N1), rest C2.
#define SMEM_FAST (3 * 1024 * 16)

__global__ __launch_bounds__(256, 2) void gemm_fast2(
    const float* __restrict__ Ap, const float* __restrict__ Bp,
    __half* __restrict__ C1, int N1, const float* __restrict__ bias1,
    __half* __restrict__ C2, int N2, const float* __restrict__ bias2,
    int splitCt)
{
    extern __shared__ float sm[];
    uint4* smv = (uint4*)sm;
    const int tid  = threadIdx.x;
    const int lane = tid & 31;
    const int w    = tid >> 5;
    const int wm   = w & 3;
    const int wn   = w >> 2;
    const int r_   = lane >> 2;
    const int cc_  = lane & 3;
    const int rt13 = blockIdx.y * KT13;
    const int ct13 = blockIdx.x * KT13;
    const int row0 = blockIdx.y * 128;

    float acc[2][8][4] = {};

    int aoff[2][2];
#pragma unroll
    for (int mt = 0; mt < 2; mt++)
#pragma unroll
        for (int k2 = 0; k2 < 2; k2++)
            aoff[mt][k2] = ((wm * 2 + mt) * 2 + k2) * 32 + r_ * 4 + cc_;
    int c4[8];
#pragma unroll
    for (int nt = 0; nt < 8; nt++) c4[nt] = (wn * 64 + nt * 8 + r_) * 4 + cc_;

    auto stage = [&](int kt, int b) {
        uint4* d = smv + b * 1024;
        const uint4* sa = (const uint4*)Ap + (size_t)(rt13 + kt) * 512;
        cpa16u(&d[tid],       &sa[tid]);
        cpa16u(&d[tid + 256], &sa[tid + 256]);
        uint4* db = d + 512;
        const uint4* sb = (const uint4*)Bp + (size_t)(ct13 + kt) * 512;
        cpa16u(&db[tid],       &sb[tid]);
        cpa16u(&db[tid + 256], &sb[tid + 256]);
        asm volatile("cp.async.commit_group;");
    };

    stage(0, 0);
    stage(1, 1);

#pragma unroll 1
    for (int t = 0; t < KT13; t++) {
        if (t < KT13 - 1) asm volatile("cp.async.wait_group 1;");
        else              asm volatile("cp.async.wait_group 0;");
        __syncthreads();
        if (t + 2 < KT13) stage(t + 2, (t + 2) % 3);

        const uint4* Ab = smv + (t % 3) * 1024;
        const uint4* Bb = Ab + 512;

        unsigned ah[2][2][4];
#pragma unroll
        for (int k2 = 0; k2 < 2; k2++)
#pragma unroll
            for (int mt = 0; mt < 2; mt++) {
                uint4 v = Ab[aoff[mt][k2]];
                ah[k2][mt][0] = v.x; ah[k2][mt][1] = v.y;
                ah[k2][mt][2] = v.z; ah[k2][mt][3] = v.w;
            }
#pragma unroll
        for (int nt = 0; nt < 8; nt++) {
            uint4 bv = Bb[c4[nt]];
            unsigned b0[2] = {bv.x, bv.y};
            unsigned b1[2] = {bv.z, bv.w};
#pragma unroll
            for (int mt = 0; mt < 2; mt++) {
                mma_tf32(acc[mt][nt], ah[0][mt], b0);
                mma_tf32(acc[mt][nt], ah[1][mt], b1);
            }
        }
    }

    // ---- dual-target fp16 epilogue ----
    const bool first = (int)blockIdx.x < splitCt;
    __half* C = first ? C1 : C2;
    const int Nreal = first ? N1 : N2;
    const float* bias = first ? bias1 : bias2;
    const int colb = (first ? blockIdx.x : blockIdx.x - splitCt) * 128;

    const int gid = lane >> 2, tig = lane & 3;
#pragma unroll
    for (int mt = 0; mt < 2; mt++) {
#pragma unroll
        for (int half_ = 0; half_ < 2; half_++) {
            int r = row0 + wm * 32 + mt * 16 + half_ * 8 + gid;
#pragma unroll
            for (int nt = 0; nt < 8; nt++) {
                int c = colb + wn * 64 + nt * 8 + tig * 2;
                if (c >= Nreal) continue;
                float v0 = acc[mt][nt][half_ * 2 + 0];
                float v1 = acc[mt][nt][half_ * 2 + 1];
                if (bias) { v0 += bias[c]; v1 += bias[c + 1]; }
                *(__half2*)(C + (size_t)r * Nreal + c) = __floats2half2_rn(v0, v1);
            }
        }
    }
}

static void launch_fast2(const float* Ap, const float* Bp,
                         __half* C1, int N1, const float* bias1,
                         __half* C2, int N2, const float* bias2,
                         int splitCt, int totalCt)
{
    cudaFuncSetAttribute(gemm_fast2, cudaFuncAttributeMaxDynamicSharedMemorySize, SMEM_FAST);
    gemm_fast2<<<dim3(totalCt, 256), 256, SMEM_FAST>>>(Ap, Bp, C1, N1, bias1, C2, N2, bias2, splitCt);
}

// --------------------- general GEMM (readout path, 1xTF32) -----------------
#define APAD   20
#define BPADF2 132

template<int BMODE, int NSPLIT, int ASPL>
__global__ __launch_bounds__(256, 2) void gemm_tc(
    const void* __restrict__ Av, const float2* __restrict__ B,
    float* __restrict__ C, const float* __restrict__ bias,
    int M, int N, int K, int lda, int ldb, int ldc, int aStep)
{
    extern __shared__ char smraw[];
    constexpr int AELT = ASPL ? 8 : 4;
    constexpr int ABUF = 128 * APAD * AELT;
    float*  Af  = (float*)smraw;
    float2* Af2 = (float2*)smraw;
    float2* Bb  = (float2*)(smraw + 2 * ABUF);

    const int tid  = threadIdx.x;
    const int lane = tid & 31;
    const int w    = tid >> 5;
    const int wm   = w & 3;
    const int wn   = w >> 2;
    const int row0 = blockIdx.y * 128;
    const int col0 = blockIdx.x * 128;

    const int ktiles = (K + 15) >> 4;
    const int total  = ktiles * NSPLIT;

    float acc[2][8][4] = {};

    auto stage = [&](int t, int b) {
        const int sI = (NSPLIT == 1) ? 0 : (t / ktiles);
        const int kt = (NSPLIT == 1) ? t : (t % ktiles);
        const int k0 = kt << 4;
        if (ASPL == 0) {
            const float* Ap = (const float*)Av + (size_t)sI * aStep;
#pragma unroll
            for (int i = 0; i < 2; i++) {
                int ch = tid + (i << 8);
                int row = ch >> 2, part = (ch & 3) << 2;
                int gr = row0 + row, gk = k0 + part;
                int sb = (gr < M && gk < K) ? 16 : 0;
                const float* src = sb ? (Ap + (size_t)gr * lda + gk) : Ap;
                cpa16(&Af[(size_t)b * (ABUF / 4) + row * APAD + part], src, sb);
            }
        } else {
            const float2* Ap = (const float2*)Av + (size_t)sI * aStep;
#pragma unroll
            for (int i = 0; i < 4; i++) {
                int ch = tid + (i << 8);
                int row = ch >> 3, kp = (ch & 7) << 1;
                int gr = row0 + row, gk = k0 + kp;
                int sb = (gr < M && gk < K) ? 16 : 0;
                const float2* src = sb ? (Ap + (size_t)gr * lda + gk) : Ap;
                cpa16(&Af2[(size_t)b * (ABUF / 8) + row * APAD + kp], src, sb);
            }
        }
        if (NSPLIT == 1) {
#pragma unroll
            for (int i = 0; i < 4; i++) {
                int ch = tid + (i << 8);
                int krow = ch >> 6, cp = (ch & 63) << 1;
                int gk = k0 + krow, gc = col0 + cp;
                int sb = (gk < K && gc < N) ? 16 : 0;
                const float2* src = sb ? (B + (size_t)gk * ldb + gc) : B;
                cpa16(&Bb[(b * 16 + krow) * BPADF2 + cp], src, sb);
            }
        } else {
#pragma unroll
            for (int i = 0; i < 8; i++) {
                int ch = tid + (i << 8);
                int krow = ch >> 7, c = ch & 127;
                int gk = k0 + krow, gc = col0 + c;
                int sb = (gk < K && gc < N) ? 8 : 0;
                const float2* src = sb ? (B + (size_t)gk * ldb + gc + sI) : B;
                cpa8(&Bb[(b * 16 + krow) * BPADF2 + c], src, sb);
            }
        }
        asm volatile("cp.async.commit_group;");
    };

    stage(0, 0);
    asm volatile("cp.async.wait_group 0;");
    __syncthreads();

    int buf = 0;
    const int r_  = lane >> 2;
    const int cc_ = lane & 3;

    for (int t = 0; t < total; t++) {
        if (t + 1 < total) stage(t + 1, buf ^ 1);

#pragma unroll
        for (int k2 = 0; k2 < 2; k2++) {
            unsigned ah[2][4];
#pragma unroll
            for (int mt = 0; mt < 2; mt++) {
                int rb = wm * 32 + mt * 16;
                if (ASPL == 0) {
                    const float* Ar = Af + (size_t)buf * (ABUF / 4);
                    ah[mt][0] = f2tf32(Ar[(rb + r_    ) * APAD + k2 * 8 + cc_]);
                    ah[mt][1] = f2tf32(Ar[(rb + r_ + 8) * APAD + k2 * 8 + cc_]);
                    ah[mt][2] = f2tf32(Ar[(rb + r_    ) * APAD + k2 * 8 + cc_ + 4]);
                    ah[mt][3] = f2tf32(Ar[(rb + r_ + 8) * APAD + k2 * 8 + cc_ + 4]);
                } else {
                    const float2* Ar = Af2 + (size_t)buf * (ABUF / 8);
                    ah[mt][0] = __float_as_uint(Ar[(rb + r_    ) * APAD + k2 * 8 + cc_].x);
                    ah[mt][1] = __float_as_uint(Ar[(rb + r_ + 8) * APAD + k2 * 8 + cc_].x);
                    ah[mt][2] = __float_as_uint(Ar[(rb + r_    ) * APAD + k2 * 8 + cc_ + 4].x);
                    ah[mt][3] = __float_as_uint(Ar[(rb + r_ + 8) * APAD + k2 * 8 + cc_ + 4].x);
                }
            }
#pragma unroll
            for (int nt = 0; nt < 8; nt++) {
                int cb = wn * 64 + nt * 8 + r_;
                int kb = k2 * 8 + cc_;
                float2 g0 = Bb[(buf * 16 + kb    ) * BPADF2 + cb];
                float2 g1 = Bb[(buf * 16 + kb + 4) * BPADF2 + cb];
                unsigned bh[2];
                bh[0] = __float_as_uint(g0.x);
                bh[1] = __float_as_uint(g1.x);
#pragma unroll
                for (int mt = 0; mt < 2; mt++) {
                    mma_tf32(acc[mt][nt], ah[mt], bh);
                }
            }
        }

        if (t + 1 < total) asm volatile("cp.async.wait_group 0;");
        __syncthreads();
        buf ^= 1;
    }

    const int gid = lane >> 2, tig = lane & 3;
#pragma unroll
    for (int mt = 0; mt < 2; mt++) {
#pragma unroll
        for (int half_ = 0; half_ < 2; half_++) {
            int r = row0 + wm * 32 + mt * 16 + half_ * 8 + gid;
            if (r >= M) continue;
            float rb = (BMODE == 3) ? bias[r] : 0.f;
#pragma unroll
            for (int nt = 0; nt < 8; nt++) {
                int c = col0 + wn * 64 + nt * 8 + tig * 2;
                if (c >= N) continue;
                float v0 = acc[mt][nt][half_ * 2 + 0];
                float v1 = acc[mt][nt][half_ * 2 + 1];
                if (BMODE == 1)      { v0 += bias[c]; v1 += bias[c + 1]; }
                else if (BMODE == 3) { v0 += rb; v1 += rb; }
                float2 o; o.x = v0; o.y = v1;
                *(float2*)(C + (size_t)r * ldc + c) = o;
            }
        }
    }
}

#define SMEM_A0 (2 * 128 * APAD * 4 + 2 * 16 * BPADF2 * 8)
#define SMEM_A1 (2 * 128 * APAD * 8 + 2 * 16 * BPADF2 * 8)

template<int BMODE, int NSPLIT, int ASPL>
static void launch_gemm(const void* A, const float2* B, float* C, const float* bias,
                        int M, int N, int K, int lda, int ldb, int ldc, int aStep)
{
    constexpr int SM = ASPL ? SMEM_A1 : SMEM_A0;
    cudaFuncSetAttribute(gemm_tc<BMODE, NSPLIT, ASPL>,
                         cudaFuncAttributeMaxDynamicSharedMemorySize, SM);
    dim3 grid((N + 127) / 128, (M + 127) / 128);
    gemm_tc<BMODE, NSPLIT, ASPL><<<grid, 256, SM>>>(A, B, C, bias, M, N, K, lda, ldb, ldc, aStep);
}

// GRU gates: half gi/gh inputs; raw + fragment-packed tf32 h out
__global__ void gates_k(const float* __restrict__ hin, float* __restrict__ hout,
                        float* __restrict__ hp) {
    int idx = blockIdx.x * blockDim.x + threadIdx.x;
    if (idx < NTOT * 50) {
        int n = idx / 50, q = idx % 50;
        const __half2* gi2 = (const __half2*)d_gih;
        const __half2* gh2 = (const __half2*)d_ghh;
        size_t b2 = (size_t)n * 300 + q * 2;
        float2 irA = __half22float2(gi2[b2      ]), irB = __half22float2(gi2[b2 + 1  ]);
        float2 hrA = __half22float2(gh2[b2      ]), hrB = __half22float2(gh2[b2 + 1  ]);
        float2 izA = __half22float2(gi2[b2 + 100]), izB = __half22float2(gi2[b2 + 101]);
        float2 hzA = __half22float2(gh2[b2 + 100]), hzB = __half22float2(gh2[b2 + 101]);
        float2 inA = __half22float2(gi2[b2 + 200]), inB = __half22float2(gi2[b2 + 201]);
        float2 hnA = __half22float2(gh2[b2 + 200]), hnB = __half22float2(gh2[b2 + 201]);
        float4 h4  = ((const float4*)hin)[(size_t)n * 50 + q];
        float ir[4] = {irA.x, irA.y, irB.x, irB.y};
        float hr[4] = {hrA.x, hrA.y, hrB.x, hrB.y};
        float iz[4] = {izA.x, izA.y, izB.x, izB.y};
        float hz[4] = {hzA.x, hzA.y, hzB.x, hzB.y};
        float in_[4] = {inA.x, inA.y, inB.x, inB.y};
        float hn[4] = {hnA.x, hnA.y, hnB.x, hnB.y};
        float hv[4] = {h4.x, h4.y, h4.z, h4.w};
        float ov[4];
#pragma unroll
        for (int i = 0; i < 4; i++) {
            float r = 1.f / (1.f + __expf(-(ir[i] + hr[i])));
            float z = 1.f / (1.f + __expf(-(iz[i] + hz[i])));
            float nn = tanhf(in_[i] + r * hn[i]);
            ov[i] = (1.f - z) * nn + z * hv[i];
        }
        float4 o; o.x = ov[0]; o.y = ov[1]; o.z = ov[2]; o.w = ov[3];
        ((float4*)hout)[(size_t)n * 50 + q] = o;
        int k0 = q * 4;
        hp[apack_idx(n, k0    )] = __uint_as_float(f2tf32(ov[0]));
        hp[apack_idx(n, k0 + 1)] = __uint_as_float(f2tf32(ov[1]));
        hp[apack_idx(n, k0 + 2)] = __uint_as_float(f2tf32(ov[2]));
        hp[apack_idx(n, k0 + 3)] = __uint_as_float(f2tf32(ov[3]));
    }
}

// in [G][C] raw -> out [C][G] hi/lo  (readout)
__global__ void transpose_hl_k(const float* __restrict__ in, float2* __restrict__ out,
                               int G, int C) {
    __shared__ float tile[32][33];
    int c0 = blockIdx.x * 32;
    int g0 = blockIdx.y * 32;
    int c = c0 + threadIdx.x;
#pragma unroll
    for (int j = 0; j < 32; j += 8) {
        int g = g0 + threadIdx.y + j;
        tile[threadIdx.y + j][threadIdx.x] = (c < C && g < G) ? in[(size_t)g * C + c] : 0.f;
    }
    __syncthreads();
    int g = g0 + threadIdx.x;
#pragma unroll
    for (int j = 0; j < 32; j += 8) {
        int cc = c0 + threadIdx.y + j;
        if (cc < C && g < G) out[(size_t)cc * G + g] = spl(tile[threadIdx.x][threadIdx.y + j]);
    }
}

__global__ void pool3_k(const float* __restrict__ in, float2* __restrict__ out, int C) {
    int idx = blockIdx.x * blockDim.x + threadIdx.x;
    if (idx < C * GP1) {
        int co = idx / GP1;
        int r = idx % GP1;
        int b = r / P1, p = r % P1;
        int base = co * NTOT + b * NPG + 2 * p;
        float m = fmaxf(fmaxf(in[base], in[base + 1]), in[base + 2]);
        out[idx] = spl(fmaxf(m, 0.f));
    }
}

__global__ void pool2_k(const float* __restrict__ in, float2* __restrict__ out, int C) {
    int idx = blockIdx.x * blockDim.x + threadIdx.x;
    if (idx < C * GP2) {
        int co = idx / GP2;
        int r = idx % GP2;
        int b = r / P2, p = r % P2;
        int base = co * GP1 + b * P1 + 2 * p;
        out[idx] = spl(fmaxf(fmaxf(in[base], in[base + 1]), 0.f));
    }
}

__global__ void final_k(const float* __restrict__ by, const float* __restrict__ bz,
                        float* __restrict__ out) {
    __shared__ float red[NCLS][128];
    int b = blockIdx.x;
    int tid = threadIdx.x;
    float part[NCLS] = {};
    for (int p = tid; p < P2; p += blockDim.x) {
        int base = b * P2 + p;
#pragma unroll
        for (int cl = 0; cl < NCLS; cl++) {
            float y = d_ly[cl * GP2 + base] + by[cl];
            float z = d_lz[cl * GP2 + base] + bz[cl];
            part[cl] += y * z;
        }
    }
#pragma unroll
    for (int cl = 0; cl < NCLS; cl++) red[cl][tid] = part[cl];
    __syncthreads();
    if (tid == 0) {
        float v[NCLS];
        for (int cl = 0; cl < NCLS; cl++) {
            float s = 0.f;
            for (int i = 0; i < 128; i++) s += red[cl][i];
            v[cl] = s / (float)P2;
        }
        float mx = v[0];
        for (int cl = 1; cl < NCLS; cl++) mx = fmaxf(mx, v[cl]);
        float se = 0.f;
        for (int cl = 0; cl < NCLS; cl++) { v[cl] = __expf(v[cl] - mx); se += v[cl]; }
        for (int cl = 0; cl < NCLS; cl++) out[b * NCLS + cl] = v[cl] / se;
    }
}

// ----------------------------- host side ----------------------------------
static void* getsym(const void* s) {
    void* p = nullptr;
    cudaGetSymbolAddress(&p, s);
    return p;
}

extern "C" void kernel_launch(void* const* d_in, const int* in_sizes, int n_in,
                              void* d_out, int out_size)
{
    const float* features = (const float*)d_in[0];
    const int*   esrc     = (const int*)  d_in[1];
    const int*   edst     = (const int*)  d_in[2];
    const int*   etyp     = (const int*)  d_in[3];
    const float* etype_W  = (const float*)d_in[4];
    const float* etype_b  = (const float*)d_in[5];
    const float* W_ih     = (const float*)d_in[6];
    const float* b_ih     = (const float*)d_in[7];
    const float* W_hh     = (const float*)d_in[8];
    const float* b_hh     = (const float*)d_in[9];
    const float* conv1_w  = (const float*)d_in[10];
    const float* conv1_b  = (const float*)d_in[11];
    const float* conv2_w  = (const float*)d_in[12];
    const float* conv2_b  = (const float*)d_in[13];
    const float* convc1_w = (const float*)d_in[14];
    const float* convc1_b = (const float*)d_in[15];
    const float* convc2_w = (const float*)d_in[16];
    const float* convc2_b = (const float*)d_in[17];
    const float* mlp_y_w  = (const float*)d_in[18];
    const float* mlp_y_b  = (const float*)d_in[19];
    const float* mlp_z_w  = (const float*)d_in[20];
    const float* mlp_z_b  = (const float*)d_in[21];

    float*  p_h0    = (float*) getsym(d_h0);
    float*  p_h1    = (float*) getsym(d_h1);
    float*  p_hp0   = (float*) getsym(d_hpack0);
    float*  p_hp1   = (float*) getsym(d_hpack1);
    float*  p_ap    = (float*) getsym(d_apack);
    __half* p_Hth   = (__half*)getsym(d_Hth);
    __half* p_gih   = (__half*)getsym(d_gih);
    __half* p_ghh   = (__half*)getsym(d_ghh);
    float*  p_Wcomb = (float*) getsym(d_Wcombp);
    float*  p_Wihp  = (float*) getsym(d_Wihp);
    int*    p_deg4  = (int*)   getsym(d_deg4);
    float2* p_cThl  = (float2*)getsym(d_cThl);
    float2* p_w1yhl = (float2*)getsym(d_w1yhl);
    float2* p_w1zhl = (float2*)getsym(d_w1zhl);
    float2* p_w2yhl = (float2*)getsym(d_w2yhl);
    float2* p_w2zhl = (float2*)getsym(d_w2zhl);
    float2* p_wmyhl = (float2*)getsym(d_wmyhl);
    float2* p_wmzhl = (float2*)getsym(d_wmzhl);
    float*  p_y1    = (float*) getsym(d_y1);
    float*  p_z1    = (float*) getsym(d_z1);
    float2* p_yp1hl = (float2*)getsym(d_yp1hl);
    float2* p_zp1hl = (float2*)getsym(d_zp1hl);
    float*  p_y2    = (float*) getsym(d_y2);
    float*  p_z2    = (float*) getsym(d_z2);
    float2* p_yp2hl = (float2*)getsym(d_yp2hl);
    float2* p_zp2hl = (float2*)getsym(d_zp2hl);
    float*  p_ly    = (float*) getsym(d_ly);
    float*  p_lz    = (float*) getsym(d_lz);

    const int T = 256;

    // ---- first launches: merged Ht+gh GEMM at profiler slot 3 ----
    zero_pack_k<<<(3 * 256 * 2048 + T - 1) / T, T>>>();                          // 0
    init_h_k<<<(NTOT * ODIM + T - 1) / T, T>>>(features);                        // 1
    packB_comb<<<(12 * KT13 * 512 + T - 1) / T, T>>>(etype_W, W_hh);             // 2
    launch_fast2(p_hp0, p_Wcomb, p_Hth, 800, nullptr, p_ghh, H3, b_hh, 7, 12);   // 3 (step-0 Ht+gh)

    // ---- rest of setup ----
    packB_k<<<(5 * KT13 * 512 + T - 1) / T, T>>>(W_ih, p_Wihp, H3, 5);
    zero_int_k<<<(NTOT * 4 + T - 1) / T, T>>>(p_deg4, NTOT * 4);
    hist_k<<<(EDGES + T - 1) / T, T>>>(edst, etyp);
    scan_k<<<1, 1024>>>();
    chunk_hist_k<<<dim3(NCHK, BATCH), 512>>>(edst);
    chunk_scan_k<<<(NTOT + T - 1) / T, T>>>();
    scatter_k<<<dim3(NCHK, BATCH), 512>>>(esrc, edst, etyp);
    pack_conv_hl_k<<<(3 * ODIM * ODIM + T - 1) / T, T>>>(conv1_w, p_w1yhl, ODIM);
    pack_conv_hl_k<<<(3 * CDIM * CDIM + T - 1) / T, T>>>(convc1_w, p_w1zhl, CDIM);
    split_mat_k<<<(ODIM * ODIM + T - 1) / T, T>>>(conv2_w, p_w2yhl, ODIM * ODIM);
    split_mat_k<<<(CDIM * CDIM + T - 1) / T, T>>>(convc2_w, p_w2zhl, CDIM * CDIM);
    split_mat_k<<<(NCLS * ODIM + T - 1) / T, T>>>(mlp_y_w, p_wmyhl, NCLS * ODIM);
    split_mat_k<<<(NCLS * CDIM + T - 1) / T, T>>>(mlp_z_w, p_wmzhl, NCLS * CDIM);
    nodebias_k<<<(NTOT * ODIM + T - 1) / T, T>>>(etype_b);

    // ---- GGNN: 8 steps ----
    for (int s = 0; s < 8; s++) {
        const float* hin  = (s & 1) ? p_h1 : p_h0;
        float*       hout = (s & 1) ? p_h0 : p_h1;
        const float* hpin = (s & 1) ? p_hp1 : p_hp0;
        float*       hpout= (s & 1) ? p_hp0 : p_hp1;
        if (s > 0)
            launch_fast2(hpin, p_Wcomb, p_Hth, 800, nullptr, p_ghh, H3, b_hh, 7, 12);
        spmm_k<<<NTOT, 256>>>(p_Hth);
        launch_fast2(p_ap, p_Wihp, p_gih, H3, b_ih, nullptr, 0, nullptr, 5, 5);
        gates_k<<<(NTOT * 50 + T - 1) / T, T>>>(hin, hout, hpout);
    }
    float* p_hf = p_h0;

    // ---- readout ----
    transpose_hl_k<<<dim3((ODIM + 31) / 32, NTOT / 32), dim3(32, 8)>>>(p_hf, p_cThl, NTOT, ODIM);
    transpose_hl_k<<<dim3((IDIM + 31) / 32, NTOT / 32), dim3(32, 8)>>>(features, p_cThl + (size_t)ODIM * NTOT, NTOT, IDIM);

    launch_gemm<3,3,1>(p_w1yhl, p_cThl, p_y1, conv1_b, ODIM, NTOT, ODIM, ODIM, NTOT, NTOT, ODIM * ODIM);
    pool3_k<<<(ODIM * GP1 + T - 1) / T, T>>>(p_y1, p_yp1hl, ODIM);
    launch_gemm<3,1,1>(p_w2yhl, p_yp1hl, p_y2, conv2_b, ODIM, GP1, ODIM, ODIM, GP1, GP1, 0);
    pool2_k<<<(ODIM * GP2 + T - 1) / T, T>>>(p_y2, p_yp2hl, ODIM);

    launch_gemm<3,3,1>(p_w1zhl, p_cThl, p_z1, convc1_b, CDIM, NTOT, CDIM, CDIM, NTOT, NTOT, CDIM * CDIM);
    pool3_k<<<(CDIM * GP1 + T - 1) / T, T>>>(p_z1, p_zp1hl, CDIM);
    launch_gemm<3,1,1>(p_w2zhl, p_zp1hl, p_z2, convc2_b, CDIM, GP1, CDIM, CDIM, GP1, GP1, 0);
    pool2_k<<<(CDIM * GP2 + T - 1) / T, T>>>(p_z2, p_zp2hl, CDIM);

    launch_gemm<0,1,1>(p_wmyhl, p_yp2hl, p_ly, nullptr, NCLS, GP2, ODIM, ODIM, GP2, GP2, 0);
    launch_gemm<0,1,1>(p_wmzhl, p_zp2hl, p_lz, nullptr, NCLS, GP2, CDIM, CDIM, GP2, GP2, 0);

    final_k<<<BATCH, 128>>>(mlp_y_b, mlp_z_b, (float*)d_out);
}

// round 13
// speedup vs baseline: 2.4107x; 1.0906x over previous
#include <cuda_runtime.h>
#include <cuda_fp16.h>

#define BATCH  64
#define NPG    512
#define NTOT   32768
#define EDGES  524288
#define EPG    8192
#define NCHK   16
#define ODIM   200
#define IDIM   100
#define H3     600
#define CDIM   300
#define P1     254
#define P2     127
#define GP1    16256
#define GP2    8128
#define NCLS   7
#define KT13   13
#define HPACK_FLOATS (256*KT13*2048)

// ----------------------------- device scratch -----------------------------
__device__ float  d_h0[NTOT*ODIM];
__device__ float  d_h1[NTOT*ODIM];
__device__ float  d_hpack0[HPACK_FLOATS];
__device__ float  d_hpack1[HPACK_FLOATS];
__device__ float  d_apack[HPACK_FLOATS];
__device__ __half d_Hth[NTOT*4*ODIM];
__device__ __half d_gih[NTOT*H3];
__device__ __half d_ghh[NTOT*H3];
__device__ float  d_Wcombp[12*KT13*2048];
__device__ float  d_Wihp[5*KT13*2048];
__device__ float  d_nbias[NTOT*ODIM];
__device__ int    d_deg4[NTOT*4];
__device__ int    d_indptr[NTOT+1];
__device__ int    d_ccnt[NTOT*NCHK];
__device__ int    d_srcs[EDGES];
__device__ int    d_typs[EDGES];
__device__ float  d_cTt[CDIM*NTOT + 64];
__device__ float  d_w1yt[3*ODIM*ODIM];
__device__ float  d_w1zt[3*CDIM*CDIM];
__device__ float  d_w2yt[ODIM*ODIM];
__device__ float  d_w2zt[CDIM*CDIM];
__device__ float  d_wmyt[NCLS*ODIM];
__device__ float  d_wmzt[NCLS*CDIM];
__device__ float  d_y1[ODIM*NTOT];
__device__ float  d_z1[CDIM*NTOT];
__device__ float  d_yp1t[ODIM*GP1];
__device__ float  d_zp1t[CDIM*GP1];
__device__ float  d_y2[ODIM*GP1];
__device__ float  d_z2[CDIM*GP1];
__device__ float  d_yp2t[ODIM*GP2];
__device__ float  d_zp2t[CDIM*GP2];
__device__ float  d_ly[NCLS*GP2];
__device__ float  d_lz[NCLS*GP2];

// ----------------------------- helpers ------------------------------------
__device__ __forceinline__ unsigned f2tf32(float f) {
    unsigned u;
    asm("cvt.rna.tf32.f32 %0, %1;" : "=r"(u) : "f"(f));
    return u;
}
__device__ __forceinline__ float tfv(float f) { return __uint_as_float(f2tf32(f)); }
__device__ __forceinline__ int apack_idx(int n, int k) {
    int rt = n >> 7, mb = (n >> 4) & 7, r = n & 7, hr = (n >> 3) & 1;
    int k8 = k >> 3, kt = k8 >> 1, k2 = k8 & 1, cc = k & 3, hk = (k >> 2) & 1;
    return (((rt * KT13 + kt) * 512) + (mb * 2 + k2) * 32 + r * 4 + cc) * 4 + hk * 2 + hr;
}

// ----------------------------- setup kernels ------------------------------
__global__ void zero_int_k(int* p, int n) {
    int i = blockIdx.x * blockDim.x + threadIdx.x;
    if (i < n) p[i] = 0;
}

__global__ void zero_pack_k() {
    int i = blockIdx.x * blockDim.x + threadIdx.x;
    const int per = 256 * 2048;
    if (i < 3 * per) {
        int b = i / per, r = i % per;
        int rt = r / 2048, off = r % 2048;
        float* p = (b == 0) ? d_hpack0 : (b == 1) ? d_hpack1 : d_apack;
        p[(rt * KT13 + 12) * 2048 + off] = 0.f;
    }
}

__global__ void hist_k(const int* __restrict__ edst, const int* __restrict__ etyp) {
    int e = blockIdx.x * blockDim.x + threadIdx.x;
    if (e < EDGES) atomicAdd(&d_deg4[edst[e] * 4 + etyp[e]], 1);
}

__global__ void scan_k() {
    __shared__ int ssum[1024];
    int t = threadIdx.x;
    int loc[32];
    int s = 0;
#pragma unroll
    for (int i = 0; i < 32; i++) {
        int n = t * 32 + i;
        int d = d_deg4[n*4] + d_deg4[n*4+1] + d_deg4[n*4+2] + d_deg4[n*4+3];
        loc[i] = s; s += d;
    }
    ssum[t] = s;
    __syncthreads();
    if (t == 0) {
        int acc = 0;
        for (int i = 0; i < 1024; i++) { int v = ssum[i]; ssum[i] = acc; acc += v; }
        d_indptr[NTOT] = acc;
    }
    __syncthreads();
    int off = ssum[t];
#pragma unroll
    for (int i = 0; i < 32; i++) d_indptr[t * 32 + i] = off + loc[i];
}

__global__ void chunk_hist_k(const int* __restrict__ edst) {
    __shared__ int h[NPG];
    int g = blockIdx.y, c = blockIdx.x;
    h[threadIdx.x] = 0;
    __syncthreads();
    int e = g * EPG + c * 512 + threadIdx.x;
    atomicAdd(&h[edst[e] - g * NPG], 1);
    __syncthreads();
    d_ccnt[(g * NPG + threadIdx.x) * NCHK + c] = h[threadIdx.x];
}

__global__ void chunk_scan_k() {
    int n = blockIdx.x * blockDim.x + threadIdx.x;
    if (n < NTOT) {
        int base = d_indptr[n];
#pragma unroll
        for (int c = 0; c < NCHK; c++) {
            int v = d_ccnt[n * NCHK + c];
            d_ccnt[n * NCHK + c] = base;
            base += v;
        }
    }
}

__global__ void scatter_k(const int* __restrict__ esrc, const int* __restrict__ edst,
                          const int* __restrict__ etyp) {
    __shared__ int sd[512];
    int g = blockIdx.y, c = blockIdx.x;
    int e = g * EPG + c * 512 + threadIdx.x;
    int dl = edst[e] - g * NPG;
    sd[threadIdx.x] = dl;
    __syncthreads();
    int rank = 0;
    for (int i = 0; i < threadIdx.x; i++) rank += (sd[i] == dl);
    int pos = d_ccnt[(g * NPG + dl) * NCHK + c] + rank;
    d_srcs[pos] = esrc[e];
    d_typs[pos] = etyp[e];
}

// combined B pack: ct 0..6 = etype_W [800][200]; ct 7..11 = W_hh [600][200].
__global__ void packB_comb(const float* __restrict__ Wst, const float* __restrict__ Whh) {
    int t = blockIdx.x * blockDim.x + threadIdx.x;
    if (t >= 12 * KT13 * 512) return;
    int j  = t & 3;
    int c  = (t >> 2) & 127;
    int kt = (t >> 9) % KT13;
    int ct = t / (KT13 * 512);
    const float* W; int Nreal, cg;
    if (ct < 7) { W = Wst; Nreal = 800; cg = ct * 128 + c; }
    else        { W = Whh; Nreal = 600; cg = (ct - 7) * 128 + c; }
    float4 v = make_float4(0.f, 0.f, 0.f, 0.f);
    if (cg < Nreal) {
        int k = kt * 16 + j;
        v.x = (k      < 200) ? tfv(W[cg * 200 + k     ]) : 0.f;
        v.y = (k + 4  < 200) ? tfv(W[cg * 200 + k + 4 ]) : 0.f;
        v.z = (k + 8  < 200) ? tfv(W[cg * 200 + k + 8 ]) : 0.f;
        v.w = (k + 12 < 200) ? tfv(W[cg * 200 + k + 12]) : 0.f;
    }
    ((float4*)d_Wcombp)[(ct * KT13 + kt) * 512 + c * 4 + j] = v;
}

__global__ void packB_k(const float* __restrict__ W, float* __restrict__ out,
                        int Nreal, int nct) {
    int t = blockIdx.x * blockDim.x + threadIdx.x;
    if (t >= nct * KT13 * 512) return;
    int j  = t & 3;
    int c  = (t >> 2) & 127;
    int kt = (t >> 9) % KT13;
    int ct = t / (KT13 * 512);
    int cg = ct * 128 + c;
    float4 v = make_float4(0.f, 0.f, 0.f, 0.f);
    if (cg < Nreal) {
        int k = kt * 16 + j;
        v.x = (k      < 200) ? tfv(W[cg * 200 + k     ]) : 0.f;
        v.y = (k + 4  < 200) ? tfv(W[cg * 200 + k + 4 ]) : 0.f;
        v.z = (k + 8  < 200) ? tfv(W[cg * 200 + k + 8 ]) : 0.f;
        v.w = (k + 12 < 200) ? tfv(W[cg * 200 + k + 12]) : 0.f;
    }
    ((float4*)out)[(ct * KT13 + kt) * 512 + c * 4 + j] = v;
}

// conv weight [C][C][3] -> [k][co][ci] tf32
__global__ void pack_conv_tf_k(const float* __restrict__ W, float* __restrict__ out, int C) {
    int idx = blockIdx.x * blockDim.x + threadIdx.x;
    if (idx < 3 * C * C) {
        int ci = idx % C;
        int co = (idx / C) % C;
        int k  = idx / (C * C);
        out[idx] = tfv(W[(co * C + ci) * 3 + k]);
    }
}

__global__ void split_tf_k(const float* __restrict__ in, float* __restrict__ out, int n) {
    int i = blockIdx.x * blockDim.x + threadIdx.x;
    if (i < n) out[i] = tfv(in[i]);
}

__global__ void init_h_k(const float* __restrict__ feat) {
    int idx = blockIdx.x * blockDim.x + threadIdx.x;
    if (idx < NTOT * ODIM) {
        int d = idx % ODIM;
        int n = idx / ODIM;
        float v = (d < IDIM) ? feat[n * IDIM + d] : 0.f;
        d_h0[idx] = v;
        d_hpack0[apack_idx(n, d)] = tfv(v);
    }
}

__global__ void nodebias_k(const float* __restrict__ eb) {
    int idx = blockIdx.x * blockDim.x + threadIdx.x;
    if (idx < NTOT * ODIM) {
        int o = idx % ODIM;
        int n = idx / ODIM;
        float s = 0.f;
#pragma unroll
        for (int t = 0; t < 4; t++) s += (float)d_deg4[n * 4 + t] * eb[t * ODIM + o];
        d_nbias[idx] = s;
    }
}

// a[n][o] = nbias + sum edges Ht_h[src][t*200+o]; half2 gather, 128 threads.
__global__ void spmm_k(const __half* __restrict__ Ht) {
    __shared__ int so[128];
    int n = blockIdx.x;
    int tid = threadIdx.x;
    int beg = d_indptr[n], end = d_indptr[n + 1];
    float ax = 0.f, ay = 0.f;
    for (int base = beg; base < end; base += 128) {
        int cnt = min(128, end - base);
        if (tid < cnt) so[tid] = d_srcs[base + tid] * 800 + d_typs[base + tid] * ODIM;
        __syncthreads();
        if (tid < 100) {
            int e = 0;
            for (; e + 1 < cnt; e += 2) {
                float2 f0 = __half22float2(*(const __half2*)&Ht[so[e]     + tid * 2]);
                float2 f1 = __half22float2(*(const __half2*)&Ht[so[e + 1] + tid * 2]);
                ax += f0.x + f1.x;
                ay += f0.y + f1.y;
            }
            if (e < cnt) {
                float2 f0 = __half22float2(*(const __half2*)&Ht[so[e] + tid * 2]);
                ax += f0.x; ay += f0.y;
            }
        }
        __syncthreads();
    }
    if (tid < 100) {
        int o = n * ODIM + tid * 2;
        d_apack[apack_idx(n, tid * 2    )] = tfv(ax + d_nbias[o]);
        d_apack[apack_idx(n, tid * 2 + 1)] = tfv(ay + d_nbias[o + 1]);
    }
}

// ----------------------------- MMA helpers --------------------------------
__device__ __forceinline__ void mma_tf32(float* d, const unsigned* a, const unsigned* b) {
    asm volatile(
        "mma.sync.aligned.m16n8k8.row.col.f32.tf32.tf32.f32 "
        "{%0,%1,%2,%3}, {%4,%5,%6,%7}, {%8,%9}, {%0,%1,%2,%3};"
        : "+f"(d[0]), "+f"(d[1]), "+f"(d[2]), "+f"(d[3])
        : "r"(a[0]), "r"(a[1]), "r"(a[2]), "r"(a[3]), "r"(b[0]), "r"(b[1]));
}
__device__ __forceinline__ void cpa16(void* dst, const void* src, int sb) {
    unsigned sa = (unsigned)__cvta_generic_to_shared(dst);
    asm volatile("cp.async.cg.shared.global [%0], [%1], 16, %2;" :: "r"(sa), "l"(src), "r"(sb));
}
__device__ __forceinline__ void cpa16u(void* dst, const void* src) {
    unsigned sa = (unsigned)__cvta_generic_to_shared(dst);
    asm volatile("cp.async.cg.shared.global [%0], [%1], 16;" :: "r"(sa), "l"(src));
}
__device__ __forceinline__ void cpa4(void* dst, const void* src, int sb) {
    unsigned sa = (unsigned)__cvta_generic_to_shared(dst);
    asm volatile("cp.async.ca.shared.global [%0], [%1], 4, %2;" :: "r"(sa), "l"(src), "r"(sb));
}

// --------------------- fast GEMM (GGNN loop): 1xTF32, fp16 out -------------
#define SMEM_FAST (3 * 1024 * 16)

__global__ __launch_bounds__(256, 2) void gemm_fast2(
    const float* __restrict__ Ap, const float* __restrict__ Bp,
    __half* __restrict__ C1, int N1, const float* __restrict__ bias1,
    __half* __restrict__ C2, int N2, const float* __restrict__ bias2,
    int splitCt)
{
    extern __shared__ float sm[];
    uint4* smv = (uint4*)sm;
    const int tid  = threadIdx.x;
    const int lane = tid & 31;
    const int w    = tid >> 5;
    const int wm   = w & 3;
    const int wn   = w >> 2;
    const int r_   = lane >> 2;
    const int cc_  = lane & 3;
    const int rt13 = blockIdx.y * KT13;
    const int ct13 = blockIdx.x * KT13;
    const int row0 = blockIdx.y * 128;

    float acc[2][8][4] = {};

    int aoff[2][2];
#pragma unroll
    for (int mt = 0; mt < 2; mt++)
#pragma unroll
        for (int k2 = 0; k2 < 2; k2++)
            aoff[mt][k2] = ((wm * 2 + mt) * 2 + k2) * 32 + r_ * 4 + cc_;
    int c4[8];
#pragma unroll
    for (int nt = 0; nt < 8; nt++) c4[nt] = (wn * 64 + nt * 8 + r_) * 4 + cc_;

    auto stage = [&](int kt, int b) {
        uint4* d = smv + b * 1024;
        const uint4* sa = (const uint4*)Ap + (size_t)(rt13 + kt) * 512;
        cpa16u(&d[tid],       &sa[tid]);
        cpa16u(&d[tid + 256], &sa[tid + 256]);
        uint4* db = d + 512;
        const uint4* sb = (const uint4*)Bp + (size_t)(ct13 + kt) * 512;
        cpa16u(&db[tid],       &sb[tid]);
        cpa16u(&db[tid + 256], &sb[tid + 256]);
        asm volatile("cp.async.commit_group;");
    };

    stage(0, 0);
    stage(1, 1);

#pragma unroll 1
    for (int t = 0; t < KT13; t++) {
        if (t < KT13 - 1) asm volatile("cp.async.wait_group 1;");
        else              asm volatile("cp.async.wait_group 0;");
        __syncthreads();
        if (t + 2 < KT13) stage(t + 2, (t + 2) % 3);

        const uint4* Ab = smv + (t % 3) * 1024;
        const uint4* Bb = Ab + 512;

        unsigned ah[2][2][4];
#pragma unroll
        for (int k2 = 0; k2 < 2; k2++)
#pragma unroll
            for (int mt = 0; mt < 2; mt++) {
                uint4 v = Ab[aoff[mt][k2]];
                ah[k2][mt][0] = v.x; ah[k2][mt][1] = v.y;
                ah[k2][mt][2] = v.z; ah[k2][mt][3] = v.w;
            }
#pragma unroll
        for (int nt = 0; nt < 8; nt++) {
            uint4 bv = Bb[c4[nt]];
            unsigned b0[2] = {bv.x, bv.y};
            unsigned b1[2] = {bv.z, bv.w};
#pragma unroll
            for (int mt = 0; mt < 2; mt++) {
                mma_tf32(acc[mt][nt], ah[0][mt], b0);
                mma_tf32(acc[mt][nt], ah[1][mt], b1);
            }
        }
    }

    const bool first = (int)blockIdx.x < splitCt;
    __half* C = first ? C1 : C2;
    const int Nreal = first ? N1 : N2;
    const float* bias = first ? bias1 : bias2;
    const int colb = (first ? blockIdx.x : blockIdx.x - splitCt) * 128;

    const int gid = lane >> 2, tig = lane & 3;
#pragma unroll
    for (int mt = 0; mt < 2; mt++) {
#pragma unroll
        for (int half_ = 0; half_ < 2; half_++) {
            int r = row0 + wm * 32 + mt * 16 + half_ * 8 + gid;
#pragma unroll
            for (int nt = 0; nt < 8; nt++) {
                int c = colb + wn * 64 + nt * 8 + tig * 2;
                if (c >= Nreal) continue;
                float v0 = acc[mt][nt][half_ * 2 + 0];
                float v1 = acc[mt][nt][half_ * 2 + 1];
                if (bias) { v0 += bias[c]; v1 += bias[c + 1]; }
                *(__half2*)(C + (size_t)r * Nreal + c) = __floats2half2_rn(v0, v1);
            }
        }
    }
}

static void launch_fast2(const float* Ap, const float* Bp,
                         __half* C1, int N1, const float* bias1,
                         __half* C2, int N2, const float* bias2,
                         int splitCt, int totalCt)
{
    cudaFuncSetAttribute(gemm_fast2, cudaFuncAttributeMaxDynamicSharedMemorySize, SMEM_FAST);
    gemm_fast2<<<dim3(totalCt, 256), 256, SMEM_FAST>>>(Ap, Bp, C1, N1, bias1, C2, N2, bias2, splitCt);
}

// --------------------- general GEMM (readout, 1xTF32, all-float) -----------
// All operands pre-rounded tf32 floats. B staged hi-only.
#define APAD  20
#define BPADF 132
#define SMEM_TC (2 * 128 * APAD * 4 + 2 * 16 * BPADF * 4)

template<int BMODE, int NSPLIT>
__global__ __launch_bounds__(256, 2) void gemm_tc(
    const float* __restrict__ A, const float* __restrict__ B,
    float* __restrict__ C, const float* __restrict__ bias,
    int M, int N, int K, int lda, int ldb, int ldc, int aStep)
{
    extern __shared__ char smraw[];
    float* Af = (float*)smraw;                           // [2][128][APAD]
    float* Bf = (float*)(smraw + 2 * 128 * APAD * 4);    // [2][16][BPADF]

    const int tid  = threadIdx.x;
    const int lane = tid & 31;
    const int w    = tid >> 5;
    const int wm   = w & 3;
    const int wn   = w >> 2;
    const int row0 = blockIdx.y * 128;
    const int col0 = blockIdx.x * 128;

    const int ktiles = (K + 15) >> 4;
    const int total  = ktiles * NSPLIT;

    float acc[2][8][4] = {};

    auto stage = [&](int t, int b) {
        const int sI = (NSPLIT == 1) ? 0 : (t / ktiles);
        const int kt = (NSPLIT == 1) ? t : (t % ktiles);
        const int k0 = kt << 4;
        const float* Ap = A + (size_t)sI * aStep;
#pragma unroll
        for (int i = 0; i < 2; i++) {
            int ch = tid + (i << 8);
            int row = ch >> 2, part = (ch & 3) << 2;
            int gr = row0 + row, gk = k0 + part;
            int sb = (gr < M && gk < K) ? 16 : 0;
            const float* src = sb ? (Ap + (size_t)gr * lda + gk) : Ap;
            cpa16(&Af[(size_t)b * (128 * APAD) + row * APAD + part], src, sb);
        }
        if (NSPLIT == 1) {
#pragma unroll
            for (int i = 0; i < 2; i++) {
                int ch = tid + (i << 8);
                int krow = ch >> 5, cp = (ch & 31) << 2;
                int gk = k0 + krow, gc = col0 + cp;
                int sb = (gk < K && gc < N) ? 16 : 0;
                const float* src = sb ? (B + (size_t)gk * ldb + gc) : B;
                cpa16(&Bf[(b * 16 + krow) * BPADF + cp], src, sb);
            }
        } else {
#pragma unroll
            for (int i = 0; i < 8; i++) {
                int ch = tid + (i << 8);
                int krow = ch >> 7, c = ch & 127;
                int gk = k0 + krow, gc = col0 + c;
                int sb = (gk < K && gc < N) ? 4 : 0;
                const float* src = sb ? (B + (size_t)gk * ldb + gc + sI) : B;
                cpa4(&Bf[(b * 16 + krow) * BPADF + c], src, sb);
            }
        }
        asm volatile("cp.async.commit_group;");
    };

    stage(0, 0);
    asm volatile("cp.async.wait_group 0;");
    __syncthreads();

    int buf = 0;
    const int r_  = lane >> 2;
    const int cc_ = lane & 3;

    for (int t = 0; t < total; t++) {
        if (t + 1 < total) stage(t + 1, buf ^ 1);

#pragma unroll
        for (int k2 = 0; k2 < 2; k2++) {
            unsigned ah[2][4];
#pragma unroll
            for (int mt = 0; mt < 2; mt++) {
                int rb = wm * 32 + mt * 16;
                const float* Ar = Af + (size_t)buf * (128 * APAD);
                ah[mt][0] = __float_as_uint(Ar[(rb + r_    ) * APAD + k2 * 8 + cc_]);
                ah[mt][1] = __float_as_uint(Ar[(rb + r_ + 8) * APAD + k2 * 8 + cc_]);
                ah[mt][2] = __float_as_uint(Ar[(rb + r_    ) * APAD + k2 * 8 + cc_ + 4]);
                ah[mt][3] = __float_as_uint(Ar[(rb + r_ + 8) * APAD + k2 * 8 + cc_ + 4]);
            }
#pragma unroll
            for (int nt = 0; nt < 8; nt++) {
                int cb = wn * 64 + nt * 8 + r_;
                int kb = k2 * 8 + cc_;
                unsigned bh[2];
                bh[0] = __float_as_uint(Bf[(buf * 16 + kb    ) * BPADF + cb]);
                bh[1] = __float_as_uint(Bf[(buf * 16 + kb + 4) * BPADF + cb]);
#pragma unroll
                for (int mt = 0; mt < 2; mt++) {
                    mma_tf32(acc[mt][nt], ah[mt], bh);
                }
            }
        }

        if (t + 1 < total) asm volatile("cp.async.wait_group 0;");
        __syncthreads();
        buf ^= 1;
    }

    const int gid = lane >> 2, tig = lane & 3;
#pragma unroll
    for (int mt = 0; mt < 2; mt++) {
#pragma unroll
        for (int half_ = 0; half_ < 2; half_++) {
            int r = row0 + wm * 32 + mt * 16 + half_ * 8 + gid;
            if (r >= M) continue;
            float rb = (BMODE == 3) ? bias[r] : 0.f;
#pragma unroll
            for (int nt = 0; nt < 8; nt++) {
                int c = col0 + wn * 64 + nt * 8 + tig * 2;
                if (c >= N) continue;
                float v0 = acc[mt][nt][half_ * 2 + 0];
                float v1 = acc[mt][nt][half_ * 2 + 1];
                if (BMODE == 1)      { v0 += bias[c]; v1 += bias[c + 1]; }
                else if (BMODE == 3) { v0 += rb; v1 += rb; }
                float2 o; o.x = v0; o.y = v1;
                *(float2*)(C + (size_t)r * ldc + c) = o;
            }
        }
    }
}

template<int BMODE, int NSPLIT>
static void launch_gemm(const float* A, const float* B, float* C, const float* bias,
                        int M, int N, int K, int lda, int ldb, int ldc, int aStep)
{
    cudaFuncSetAttribute(gemm_tc<BMODE, NSPLIT>,
                         cudaFuncAttributeMaxDynamicSharedMemorySize, SMEM_TC);
    dim3 grid((N + 127) / 128, (M + 127) / 128);
    gemm_tc<BMODE, NSPLIT><<<grid, 256, SMEM_TC>>>(A, B, C, bias, M, N, K, lda, ldb, ldc, aStep);
}

// GRU gates: half gi/gh inputs; raw + fragment-packed tf32 h out
__global__ void gates_k(const float* __restrict__ hin, float* __restrict__ hout,
                        float* __restrict__ hp) {
    int idx = blockIdx.x * blockDim.x + threadIdx.x;
    if (idx < NTOT * 50) {
        int n = idx / 50, q = idx % 50;
        const __half2* gi2 = (const __half2*)d_gih;
        const __half2* gh2 = (const __half2*)d_ghh;
        size_t b2 = (size_t)n * 300 + q * 2;
        float2 irA = __half22float2(gi2[b2      ]), irB = __half22float2(gi2[b2 + 1  ]);
        float2 hrA = __half22float2(gh2[b2      ]), hrB = __half22float2(gh2[b2 + 1  ]);
        float2 izA = __half22float2(gi2[b2 + 100]), izB = __half22float2(gi2[b2 + 101]);
        float2 hzA = __half22float2(gh2[b2 + 100]), hzB = __half22float2(gh2[b2 + 101]);
        float2 inA = __half22float2(gi2[b2 + 200]), inB = __half22float2(gi2[b2 + 201]);
        float2 hnA = __half22float2(gh2[b2 + 200]), hnB = __half22float2(gh2[b2 + 201]);
        float4 h4  = ((const float4*)hin)[(size_t)n * 50 + q];
        float ir[4] = {irA.x, irA.y, irB.x, irB.y};
        float hr[4] = {hrA.x, hrA.y, hrB.x, hrB.y};
        float iz[4] = {izA.x, izA.y, izB.x, izB.y};
        float hz[4] = {hzA.x, hzA.y, hzB.x, hzB.y};
        float in_[4] = {inA.x, inA.y, inB.x, inB.y};
        float hn[4] = {hnA.x, hnA.y, hnB.x, hnB.y};
        float hv[4] = {h4.x, h4.y, h4.z, h4.w};
        float ov[4];
#pragma unroll
        for (int i = 0; i < 4; i++) {
            float r = 1.f / (1.f + __expf(-(ir[i] + hr[i])));
            float z = 1.f / (1.f + __expf(-(iz[i] + hz[i])));
            float nn = tanhf(in_[i] + r * hn[i]);
            ov[i] = (1.f - z) * nn + z * hv[i];
        }
        float4 o; o.x = ov[0]; o.y = ov[1]; o.z = ov[2]; o.w = ov[3];
        ((float4*)hout)[(size_t)n * 50 + q] = o;
        int k0 = q * 4;
        hp[apack_idx(n, k0    )] = tfv(ov[0]);
        hp[apack_idx(n, k0 + 1)] = tfv(ov[1]);
        hp[apack_idx(n, k0 + 2)] = tfv(ov[2]);
        hp[apack_idx(n, k0 + 3)] = tfv(ov[3]);
    }
}

// in [G][C] raw -> out [C][G] tf32  (readout)
__global__ void transpose_tf_k(const float* __restrict__ in, float* __restrict__ out,
                               int G, int C) {
    __shared__ float tile[32][33];
    int c0 = blockIdx.x * 32;
    int g0 = blockIdx.y * 32;
    int c = c0 + threadIdx.x;
#pragma unroll
    for (int j = 0; j < 32; j += 8) {
        int g = g0 + threadIdx.y + j;
        tile[threadIdx.y + j][threadIdx.x] = (c < C && g < G) ? in[(size_t)g * C + c] : 0.f;
    }
    __syncthreads();
    int g = g0 + threadIdx.x;
#pragma unroll
    for (int j = 0; j < 32; j += 8) {
        int cc = c0 + threadIdx.y + j;
        if (cc < C && g < G) out[(size_t)cc * G + g] = tfv(tile[threadIdx.x][threadIdx.y + j]);
    }
}

__global__ void pool3_k(const float* __restrict__ in, float* __restrict__ out, int C) {
    int idx = blockIdx.x * blockDim.x + threadIdx.x;
    if (idx < C * GP1) {
        int co = idx / GP1;
        int r = idx % GP1;
        int b = r / P1, p = r % P1;
        int base = co * NTOT + b * NPG + 2 * p;
        float m = fmaxf(fmaxf(in[base], in[base + 1]), in[base + 2]);
        out[idx] = tfv(fmaxf(m, 0.f));
    }
}

__global__ void pool2_k(const float* __restrict__ in, float* __restrict__ out, int C) {
    int idx = blockIdx.x * blockDim.x + threadIdx.x;
    if (idx < C * GP2) {
        int co = idx / GP2;
        int r = idx % GP2;
        int b = r / P2, p = r % P2;
        int base = co * GP1 + b * P1 + 2 * p;
        out[idx] = tfv(fmaxf(fmaxf(in[base], in[base + 1]), 0.f));
    }
}

__global__ void final_k(const float* __restrict__ by, const float* __restrict__ bz,
                        float* __restrict__ out) {
    __shared__ float red[NCLS][128];
    int b = blockIdx.x;
    int tid = threadIdx.x;
    float part[NCLS] = {};
    for (int p = tid; p < P2; p += blockDim.x) {
        int base = b * P2 + p;
#pragma unroll
        for (int cl = 0; cl < NCLS; cl++) {
            float y = d_ly[cl * GP2 + base] + by[cl];
            float z = d_lz[cl * GP2 + base] + bz[cl];
            part[cl] += y * z;
        }
    }
#pragma unroll
    for (int cl = 0; cl < NCLS; cl++) red[cl][tid] = part[cl];
    __syncthreads();
    if (tid == 0) {
        float v[NCLS];
        for (int cl = 0; cl < NCLS; cl++) {
            float s = 0.f;
            for (int i = 0; i < 128; i++) s += red[cl][i];
            v[cl] = s / (float)P2;
        }
        float mx = v[0];
        for (int cl = 1; cl < NCLS; cl++) mx = fmaxf(mx, v[cl]);
        float se = 0.f;
        for (int cl = 0; cl < NCLS; cl++) { v[cl] = __expf(v[cl] - mx); se += v[cl]; }
        for (int cl = 0; cl < NCLS; cl++) out[b * NCLS + cl] = v[cl] / se;
    }
}

// ----------------------------- host side ----------------------------------
static void* getsym(const void* s) {
    void* p = nullptr;
    cudaGetSymbolAddress(&p, s);
    return p;
}

extern "C" void kernel_launch(void* const* d_in, const int* in_sizes, int n_in,
                              void* d_out, int out_size)
{
    const float* features = (const float*)d_in[0];
    const int*   esrc     = (const int*)  d_in[1];
    const int*   edst     = (const int*)  d_in[2];
    const int*   etyp     = (const int*)  d_in[3];
    const float* etype_W  = (const float*)d_in[4];
    const float* etype_b  = (const float*)d_in[5];
    const float* W_ih     = (const float*)d_in[6];
    const float* b_ih     = (const float*)d_in[7];
    const float* W_hh     = (const float*)d_in[8];
    const float* b_hh     = (const float*)d_in[9];
    const float* conv1_w  = (const float*)d_in[10];
    const float* conv1_b  = (const float*)d_in[11];
    const float* conv2_w  = (const float*)d_in[12];
    const float* conv2_b  = (const float*)d_in[13];
    const float* convc1_w = (const float*)d_in[14];
    const float* convc1_b = (const float*)d_in[15];
    const float* convc2_w = (const float*)d_in[16];
    const float* convc2_b = (const float*)d_in[17];
    const float* mlp_y_w  = (const float*)d_in[18];
    const float* mlp_y_b  = (const float*)d_in[19];
    const float* mlp_z_w  = (const float*)d_in[20];
    const float* mlp_z_b  = (const float*)d_in[21];

    float*  p_h0    = (float*) getsym(d_h0);
    float*  p_h1    = (float*) getsym(d_h1);
    float*  p_hp0   = (float*) getsym(d_hpack0);
    float*  p_hp1   = (float*) getsym(d_hpack1);
    float*  p_ap    = (float*) getsym(d_apack);
    __half* p_Hth   = (__half*)getsym(d_Hth);
    __half* p_gih   = (__half*)getsym(d_gih);
    __half* p_ghh   = (__half*)getsym(d_ghh);
    float*  p_Wcomb = (float*) getsym(d_Wcombp);
    float*  p_Wihp  = (float*) getsym(d_Wihp);
    int*    p_deg4  = (int*)   getsym(d_deg4);
    float*  p_cTt   = (float*) getsym(d_cTt);
    float*  p_w1yt  = (float*) getsym(d_w1yt);
    float*  p_w1zt  = (float*) getsym(d_w1zt);
    float*  p_w2yt  = (float*) getsym(d_w2yt);
    float*  p_w2zt  = (float*) getsym(d_w2zt);
    float*  p_wmyt  = (float*) getsym(d_wmyt);
    float*  p_wmzt  = (float*) getsym(d_wmzt);
    float*  p_y1    = (float*) getsym(d_y1);
    float*  p_z1    = (float*) getsym(d_z1);
    float*  p_yp1t  = (float*) getsym(d_yp1t);
    float*  p_zp1t  = (float*) getsym(d_zp1t);
    float*  p_y2    = (float*) getsym(d_y2);
    float*  p_z2    = (float*) getsym(d_z2);
    float*  p_yp2t  = (float*) getsym(d_yp2t);
    float*  p_zp2t  = (float*) getsym(d_zp2t);
    float*  p_ly    = (float*) getsym(d_ly);
    float*  p_lz    = (float*) getsym(d_lz);

    const int T = 256;

    // ---- first launches ----
    zero_pack_k<<<(3 * 256 * 2048 + T - 1) / T, T>>>();                          // 0
    init_h_k<<<(NTOT * ODIM + T - 1) / T, T>>>(features);                        // 1
    packB_comb<<<(12 * KT13 * 512 + T - 1) / T, T>>>(etype_W, W_hh);             // 2
    launch_fast2(p_hp0, p_Wcomb, p_Hth, 800, nullptr, p_ghh, H3, b_hh, 7, 12);   // 3 (step-0 Ht+gh)

    // ---- rest of setup ----
    packB_k<<<(5 * KT13 * 512 + T - 1) / T, T>>>(W_ih, p_Wihp, H3, 5);
    zero_int_k<<<(NTOT * 4 + T - 1) / T, T>>>(p_deg4, NTOT * 4);
    hist_k<<<(EDGES + T - 1) / T, T>>>(edst, etyp);
    scan_k<<<1, 1024>>>();
    chunk_hist_k<<<dim3(NCHK, BATCH), 512>>>(edst);
    chunk_scan_k<<<(NTOT + T - 1) / T, T>>>();
    scatter_k<<<dim3(NCHK, BATCH), 512>>>(esrc, edst, etyp);
    pack_conv_tf_k<<<(3 * ODIM * ODIM + T - 1) / T, T>>>(conv1_w, p_w1yt, ODIM);
    pack_conv_tf_k<<<(3 * CDIM * CDIM + T - 1) / T, T>>>(convc1_w, p_w1zt, CDIM);
    split_tf_k<<<(ODIM * ODIM + T - 1) / T, T>>>(conv2_w, p_w2yt, ODIM * ODIM);
    split_tf_k<<<(CDIM * CDIM + T - 1) / T, T>>>(convc2_w, p_w2zt, CDIM * CDIM);
    split_tf_k<<<(NCLS * ODIM + T - 1) / T, T>>>(mlp_y_w, p_wmyt, NCLS * ODIM);
    split_tf_k<<<(NCLS * CDIM + T - 1) / T, T>>>(mlp_z_w, p_wmzt, NCLS * CDIM);
    nodebias_k<<<(NTOT * ODIM + T - 1) / T, T>>>(etype_b);

    // ---- GGNN: 8 steps ----
    for (int s = 0; s < 8; s++) {
        const float* hin  = (s & 1) ? p_h1 : p_h0;
        float*       hout = (s & 1) ? p_h0 : p_h1;
        const float* hpin = (s & 1) ? p_hp1 : p_hp0;
        float*       hpout= (s & 1) ? p_hp0 : p_hp1;
        if (s > 0)
            launch_fast2(hpin, p_Wcomb, p_Hth, 800, nullptr, p_ghh, H3, b_hh, 7, 12);
        spmm_k<<<NTOT, 128>>>(p_Hth);
        launch_fast2(p_ap, p_Wihp, p_gih, H3, b_ih, nullptr, 0, nullptr, 5, 5);
        gates_k<<<(NTOT * 50 + T - 1) / T, T>>>(hin, hout, hpout);
    }
    float* p_hf = p_h0;

    // ---- readout ----
    transpose_tf_k<<<dim3((ODIM + 31) / 32, NTOT / 32), dim3(32, 8)>>>(p_hf, p_cTt, NTOT, ODIM);
    transpose_tf_k<<<dim3((IDIM + 31) / 32, NTOT / 32), dim3(32, 8)>>>(features, p_cTt + (size_t)ODIM * NTOT, NTOT, IDIM);

    launch_gemm<3,3>(p_w1yt, p_cTt, p_y1, conv1_b, ODIM, NTOT, ODIM, ODIM, NTOT, NTOT, ODIM * ODIM);
    pool3_k<<<(ODIM * GP1 + T - 1) / T, T>>>(p_y1, p_yp1t, ODIM);
    launch_gemm<3,1>(p_w2yt, p_yp1t, p_y2, conv2_b, ODIM, GP1, ODIM, ODIM, GP1, GP1, 0);
    pool2_k<<<(ODIM * GP2 + T - 1) / T, T>>>(p_y2, p_yp2t, ODIM);

    launch_gemm<3,3>(p_w1zt, p_cTt, p_z1, convc1_b, CDIM, NTOT, CDIM, CDIM, NTOT, NTOT, CDIM * CDIM);
    pool3_k<<<(CDIM * GP1 + T - 1) / T, T>>>(p_z1, p_zp1t, CDIM);
    launch_gemm<3,1>(p_w2zt, p_zp1t, p_z2, convc2_b, CDIM, GP1, CDIM, CDIM, GP1, GP1, 0);
    pool2_k<<<(CDIM * GP2 + T - 1) / T, T>>>(p_z2, p_zp2t, CDIM);

    launch_gemm<0,1>(p_wmyt, p_yp2t, p_ly, nullptr, NCLS, GP2, ODIM, ODIM, GP2, GP2, 0);
    launch_gemm<0,1>(p_wmzt, p_zp2t, p_lz, nullptr, NCLS, GP2, CDIM, CDIM, GP2, GP2, 0);

    final_k<<<BATCH, 128>>>(mlp_y_b, mlp_z_b, (float*)d_out);
}

// round 14
// speedup vs baseline: 2.6212x; 1.0874x over previous
#include <cuda_runtime.h>
#include <cuda_fp16.h>

#define BATCH  64
#define NPG    512
#define NTOT   32768
#define EDGES  524288
#define EPG    8192
#define NCHK   16
#define ODIM   200
#define IDIM   100
#define H3     600
#define CDIM   300
#define P1     254
#define P2     127
#define GP1    16256
#define GP2    8128
#define NCLS   7
#define KT     14                        /* 224 padded K / 16 */
#define KHALF  7
#define HPACK_FLOATS (256*KT*2048)

// ----------------------------- device scratch -----------------------------
__device__ float  d_h0[NTOT*ODIM];
__device__ float  d_h1[NTOT*ODIM];
__device__ float  d_hpack0[HPACK_FLOATS];
__device__ float  d_hpack1[HPACK_FLOATS];
__device__ float  d_apack[HPACK_FLOATS];
__device__ __half d_Hth[NTOT*4*ODIM];
__device__ __half d_gih[NTOT*H3];
__device__ __half d_ghh[NTOT*H3];
__device__ float  d_Wcombp[12*KT*2048];
__device__ float  d_Wihp[5*KT*2048];
__device__ float  d_nbias[NTOT*ODIM];
__device__ int    d_deg4[NTOT*4];
__device__ int    d_indptr[NTOT+1];
__device__ int    d_ccnt[NTOT*NCHK];
__device__ int    d_srcs[EDGES];
__device__ int    d_typs[EDGES];
__device__ float  d_cTt[CDIM*NTOT + 64];
__device__ float  d_w1yt[3*ODIM*ODIM];
__device__ float  d_w1zt[3*CDIM*CDIM];
__device__ float  d_w2yt[ODIM*ODIM];
__device__ float  d_w2zt[CDIM*CDIM];
__device__ float  d_wmyt[NCLS*ODIM];
__device__ float  d_wmzt[NCLS*CDIM];
__device__ float  d_y1[ODIM*NTOT];
__device__ float  d_z1[CDIM*NTOT];
__device__ float  d_yp1t[ODIM*GP1];
__device__ float  d_zp1t[CDIM*GP1];
__device__ float  d_y2[ODIM*GP1];
__device__ float  d_z2[CDIM*GP1];
__device__ float  d_yp2t[ODIM*GP2];
__device__ float  d_zp2t[CDIM*GP2];
__device__ float  d_ly[NCLS*GP2];
__device__ float  d_lz[NCLS*GP2];

// ----------------------------- helpers ------------------------------------
__device__ __forceinline__ unsigned f2tf32(float f) {
    unsigned u;
    asm("cvt.rna.tf32.f32 %0, %1;" : "=r"(u) : "f"(f));
    return u;
}
__device__ __forceinline__ float tfv(float f) { return __uint_as_float(f2tf32(f)); }
__device__ __forceinline__ int apack_idx(int n, int k) {
    int rt = n >> 7, mb = (n >> 4) & 7, r = n & 7, hr = (n >> 3) & 1;
    int k8 = k >> 3, kt = k8 >> 1, k2 = k8 & 1, cc = k & 3, hk = (k >> 2) & 1;
    return (((rt * KT + kt) * 512) + (mb * 2 + k2) * 32 + r * 4 + cc) * 4 + hk * 2 + hr;
}

// ----------------------------- setup kernels ------------------------------
__global__ void zero_int_k(int* p, int n) {
    int i = blockIdx.x * blockDim.x + threadIdx.x;
    if (i < n) p[i] = 0;
}

// zero the two padding ktiles (12,13) of the three packed-A buffers
__global__ void zero_pack_k() {
    int i = blockIdx.x * blockDim.x + threadIdx.x;
    const int per = 256 * 2 * 2048;
    if (i < 3 * per) {
        int b = i / per, r = i % per;
        int rt = r / (2 * 2048), rem = r % (2 * 2048);
        int kt = 12 + rem / 2048, off = rem % 2048;
        float* p = (b == 0) ? d_hpack0 : (b == 1) ? d_hpack1 : d_apack;
        p[(rt * KT + kt) * 2048 + off] = 0.f;
    }
}

__global__ void hist_k(const int* __restrict__ edst, const int* __restrict__ etyp) {
    int e = blockIdx.x * blockDim.x + threadIdx.x;
    if (e < EDGES) atomicAdd(&d_deg4[edst[e] * 4 + etyp[e]], 1);
}

__global__ void scan_k() {
    __shared__ int ssum[1024];
    int t = threadIdx.x;
    int loc[32];
    int s = 0;
#pragma unroll
    for (int i = 0; i < 32; i++) {
        int n = t * 32 + i;
        int d = d_deg4[n*4] + d_deg4[n*4+1] + d_deg4[n*4+2] + d_deg4[n*4+3];
        loc[i] = s; s += d;
    }
    ssum[t] = s;
    __syncthreads();
    if (t == 0) {
        int acc = 0;
        for (int i = 0; i < 1024; i++) { int v = ssum[i]; ssum[i] = acc; acc += v; }
        d_indptr[NTOT] = acc;
    }
    __syncthreads();
    int off = ssum[t];
#pragma unroll
    for (int i = 0; i < 32; i++) d_indptr[t * 32 + i] = off + loc[i];
}

__global__ void chunk_hist_k(const int* __restrict__ edst) {
    __shared__ int h[NPG];
    int g = blockIdx.y, c = blockIdx.x;
    h[threadIdx.x] = 0;
    __syncthreads();
    int e = g * EPG + c * 512 + threadIdx.x;
    atomicAdd(&h[edst[e] - g * NPG], 1);
    __syncthreads();
    d_ccnt[(g * NPG + threadIdx.x) * NCHK + c] = h[threadIdx.x];
}

__global__ void chunk_scan_k() {
    int n = blockIdx.x * blockDim.x + threadIdx.x;
    if (n < NTOT) {
        int base = d_indptr[n];
#pragma unroll
        for (int c = 0; c < NCHK; c++) {
            int v = d_ccnt[n * NCHK + c];
            d_ccnt[n * NCHK + c] = base;
            base += v;
        }
    }
}

__global__ void scatter_k(const int* __restrict__ esrc, const int* __restrict__ edst,
                          const int* __restrict__ etyp) {
    __shared__ int sd[512];
    int g = blockIdx.y, c = blockIdx.x;
    int e = g * EPG + c * 512 + threadIdx.x;
    int dl = edst[e] - g * NPG;
    sd[threadIdx.x] = dl;
    __syncthreads();
    int rank = 0;
    for (int i = 0; i < threadIdx.x; i++) rank += (sd[i] == dl);
    int pos = d_ccnt[(g * NPG + dl) * NCHK + c] + rank;
    d_srcs[pos] = esrc[e];
    d_typs[pos] = etyp[e];
}

// combined B pack: ct 0..6 = etype_W [800][200]; ct 7..11 = W_hh [600][200].
__global__ void packB_comb(const float* __restrict__ Wst, const float* __restrict__ Whh) {
    int t = blockIdx.x * blockDim.x + threadIdx.x;
    if (t >= 12 * KT * 512) return;
    int j  = t & 3;
    int c  = (t >> 2) & 127;
    int kt = (t >> 9) % KT;
    int ct = t / (KT * 512);
    const float* W; int Nreal, cg;
    if (ct < 7) { W = Wst; Nreal = 800; cg = ct * 128 + c; }
    else        { W = Whh; Nreal = 600; cg = (ct - 7) * 128 + c; }
    float4 v = make_float4(0.f, 0.f, 0.f, 0.f);
    if (cg < Nreal) {
        int k = kt * 16 + j;
        v.x = (k      < 200) ? tfv(W[cg * 200 + k     ]) : 0.f;
        v.y = (k + 4  < 200) ? tfv(W[cg * 200 + k + 4 ]) : 0.f;
        v.z = (k + 8  < 200) ? tfv(W[cg * 200 + k + 8 ]) : 0.f;
        v.w = (k + 12 < 200) ? tfv(W[cg * 200 + k + 12]) : 0.f;
    }
    ((float4*)d_Wcombp)[(ct * KT + kt) * 512 + c * 4 + j] = v;
}

__global__ void packB_k(const float* __restrict__ W, float* __restrict__ out,
                        int Nreal, int nct) {
    int t = blockIdx.x * blockDim.x + threadIdx.x;
    if (t >= nct * KT * 512) return;
    int j  = t & 3;
    int c  = (t >> 2) & 127;
    int kt = (t >> 9) % KT;
    int ct = t / (KT * 512);
    int cg = ct * 128 + c;
    float4 v = make_float4(0.f, 0.f, 0.f, 0.f);
    if (cg < Nreal) {
        int k = kt * 16 + j;
        v.x = (k      < 200) ? tfv(W[cg * 200 + k     ]) : 0.f;
        v.y = (k + 4  < 200) ? tfv(W[cg * 200 + k + 4 ]) : 0.f;
        v.z = (k + 8  < 200) ? tfv(W[cg * 200 + k + 8 ]) : 0.f;
        v.w = (k + 12 < 200) ? tfv(W[cg * 200 + k + 12]) : 0.f;
    }
    ((float4*)out)[(ct * KT + kt) * 512 + c * 4 + j] = v;
}

// conv weight [C][C][3] -> [k][co][ci] tf32
__global__ void pack_conv_tf_k(const float* __restrict__ W, float* __restrict__ out, int C) {
    int idx = blockIdx.x * blockDim.x + threadIdx.x;
    if (idx < 3 * C * C) {
        int ci = idx % C;
        int co = (idx / C) % C;
        int k  = idx / (C * C);
        out[idx] = tfv(W[(co * C + ci) * 3 + k]);
    }
}

__global__ void split_tf_k(const float* __restrict__ in, float* __restrict__ out, int n) {
    int i = blockIdx.x * blockDim.x + threadIdx.x;
    if (i < n) out[i] = tfv(in[i]);
}

__global__ void init_h_k(const float* __restrict__ feat) {
    int idx = blockIdx.x * blockDim.x + threadIdx.x;
    if (idx < NTOT * ODIM) {
        int d = idx % ODIM;
        int n = idx / ODIM;
        float v = (d < IDIM) ? feat[n * IDIM + d] : 0.f;
        d_h0[idx] = v;
        d_hpack0[apack_idx(n, d)] = tfv(v);
    }
}

__global__ void nodebias_k(const float* __restrict__ eb) {
    int idx = blockIdx.x * blockDim.x + threadIdx.x;
    if (idx < NTOT * ODIM) {
        int o = idx % ODIM;
        int n = idx / ODIM;
        float s = 0.f;
#pragma unroll
        for (int t = 0; t < 4; t++) s += (float)d_deg4[n * 4 + t] * eb[t * ODIM + o];
        d_nbias[idx] = s;
    }
}

// warp-per-node SPMM: a[n][o] = nbias + sum edges Ht_h[src][t*200+o].
// Lanes hold edge offsets, broadcast via shfl; each lane owns 4 half2 columns.
__global__ void spmm_k(const __half* __restrict__ Ht) {
    int warp = threadIdx.x >> 5, lane = threadIdx.x & 31;
    int n = blockIdx.x * 4 + warp;
    int beg = d_indptr[n], end = d_indptr[n + 1];
    float ax[4] = {}, ay[4] = {};
    for (int base = beg; base < end; base += 32) {
        int cnt = min(32, end - base);
        int off = 0;
        if (lane < cnt) off = d_srcs[base + lane] * 800 + d_typs[base + lane] * ODIM;
        for (int e = 0; e < cnt; e++) {
            int o = __shfl_sync(0xffffffffu, off, e);
#pragma unroll
            for (int q = 0; q < 4; q++) {
                int c = lane + q * 32;
                if (q < 3 || lane < 4) {
                    float2 f = __half22float2(*(const __half2*)&Ht[o + 2 * c]);
                    ax[q] += f.x; ay[q] += f.y;
                }
            }
        }
    }
#pragma unroll
    for (int q = 0; q < 4; q++) {
        int c = lane + q * 32;
        if (q < 3 || lane < 4) {
            int o = n * ODIM + 2 * c;
            d_apack[apack_idx(n, 2 * c    )] = tfv(ax[q] + d_nbias[o]);
            d_apack[apack_idx(n, 2 * c + 1)] = tfv(ay[q] + d_nbias[o + 1]);
        }
    }
}

// ----------------------------- MMA helpers --------------------------------
__device__ __forceinline__ void mma_tf32(float* d, const unsigned* a, const unsigned* b) {
    asm volatile(
        "mma.sync.aligned.m16n8k8.row.col.f32.tf32.tf32.f32 "
        "{%0,%1,%2,%3}, {%4,%5,%6,%7}, {%8,%9}, {%0,%1,%2,%3};"
        : "+f"(d[0]), "+f"(d[1]), "+f"(d[2]), "+f"(d[3])
        : "r"(a[0]), "r"(a[1]), "r"(a[2]), "r"(a[3]), "r"(b[0]), "r"(b[1]));
}
__device__ __forceinline__ void cpa16(void* dst, const void* src, int sb) {
    unsigned sa = (unsigned)__cvta_generic_to_shared(dst);
    asm volatile("cp.async.cg.shared.global [%0], [%1], 16, %2;" :: "r"(sa), "l"(src), "r"(sb));
}
__device__ __forceinline__ void cpa16u(void* dst, const void* src) {
    unsigned sa = (unsigned)__cvta_generic_to_shared(dst);
    asm volatile("cp.async.cg.shared.global [%0], [%1], 16;" :: "r"(sa), "l"(src));
}
__device__ __forceinline__ void cpa4(void* dst, const void* src, int sb) {
    unsigned sa = (unsigned)__cvta_generic_to_shared(dst);
    asm volatile("cp.async.ca.shared.global [%0], [%1], 4, %2;" :: "r"(sa), "l"(src), "r"(sb));
}

// --------------------- fast GEMM (GGNN loop): 1xTF32, fp16 out -------------
// 2 ktiles per pipeline stage (7 barriers for K=224). 3-stage cp.async.
#define SMEM_FAST (3 * 2048 * 16)

__global__ __launch_bounds__(256, 2) void gemm_fast2(
    const float* __restrict__ Ap, const float* __restrict__ Bp,
    __half* __restrict__ C1, int N1, const float* __restrict__ bias1,
    __half* __restrict__ C2, int N2, const float* __restrict__ bias2,
    int splitCt)
{
    extern __shared__ float sm[];
    uint4* smv = (uint4*)sm;
    const int tid  = threadIdx.x;
    const int lane = tid & 31;
    const int w    = tid >> 5;
    const int wm   = w & 3;
    const int wn   = w >> 2;
    const int r_   = lane >> 2;
    const int cc_  = lane & 3;
    const int rt   = blockIdx.y * KT;
    const int ct   = blockIdx.x * KT;
    const int row0 = blockIdx.y * 128;

    float acc[2][8][4] = {};

    int aoff[2][2];
#pragma unroll
    for (int mt = 0; mt < 2; mt++)
#pragma unroll
        for (int k2 = 0; k2 < 2; k2++)
            aoff[mt][k2] = ((wm * 2 + mt) * 2 + k2) * 32 + r_ * 4 + cc_;
    int c4[8];
#pragma unroll
    for (int nt = 0; nt < 8; nt++) c4[nt] = (wn * 64 + nt * 8 + r_) * 4 + cc_;

    auto stage = [&](int it, int b) {
        uint4* d = smv + b * 2048;
        const uint4* sa = (const uint4*)Ap + (size_t)(rt + 2 * it) * 512;
        cpa16u(&d[tid],       &sa[tid]);
        cpa16u(&d[tid + 256], &sa[tid + 256]);
        cpa16u(&d[tid + 512], &sa[tid + 512]);
        cpa16u(&d[tid + 768], &sa[tid + 768]);
        uint4* db = d + 1024;
        const uint4* sb = (const uint4*)Bp + (size_t)(ct + 2 * it) * 512;
        cpa16u(&db[tid],       &sb[tid]);
        cpa16u(&db[tid + 256], &sb[tid + 256]);
        cpa16u(&db[tid + 512], &sb[tid + 512]);
        cpa16u(&db[tid + 768], &sb[tid + 768]);
        asm volatile("cp.async.commit_group;");
    };

    stage(0, 0);
    stage(1, 1);

#pragma unroll 1
    for (int it = 0; it < KHALF; it++) {
        if (it < KHALF - 1) asm volatile("cp.async.wait_group 1;");
        else                asm volatile("cp.async.wait_group 0;");
        __syncthreads();
        if (it + 2 < KHALF) stage(it + 2, (it + 2) % 3);

        const uint4* base = smv + (it % 3) * 2048;
#pragma unroll
        for (int sub = 0; sub < 2; sub++) {
            const uint4* Ab = base + sub * 512;
            const uint4* Bb = base + 1024 + sub * 512;

            unsigned ah[2][2][4];
#pragma unroll
            for (int k2 = 0; k2 < 2; k2++)
#pragma unroll
                for (int mt = 0; mt < 2; mt++) {
                    uint4 v = Ab[aoff[mt][k2]];
                    ah[k2][mt][0] = v.x; ah[k2][mt][1] = v.y;
                    ah[k2][mt][2] = v.z; ah[k2][mt][3] = v.w;
                }
#pragma unroll
            for (int nt = 0; nt < 8; nt++) {
                uint4 bv = Bb[c4[nt]];
                unsigned b0[2] = {bv.x, bv.y};
                unsigned b1[2] = {bv.z, bv.w};
#pragma unroll
                for (int mt = 0; mt < 2; mt++) {
                    mma_tf32(acc[mt][nt], ah[0][mt], b0);
                    mma_tf32(acc[mt][nt], ah[1][mt], b1);
                }
            }
        }
    }

    const bool first = (int)blockIdx.x < splitCt;
    __half* C = first ? C1 : C2;
    const int Nreal = first ? N1 : N2;
    const float* bias = first ? bias1 : bias2;
    const int colb = (first ? blockIdx.x : blockIdx.x - splitCt) * 128;

    const int gid = lane >> 2, tig = lane & 3;
#pragma unroll
    for (int mt = 0; mt < 2; mt++) {
#pragma unroll
        for (int half_ = 0; half_ < 2; half_++) {
            int r = row0 + wm * 32 + mt * 16 + half_ * 8 + gid;
#pragma unroll
            for (int nt = 0; nt < 8; nt++) {
                int c = colb + wn * 64 + nt * 8 + tig * 2;
                if (c >= Nreal) continue;
                float v0 = acc[mt][nt][half_ * 2 + 0];
                float v1 = acc[mt][nt][half_ * 2 + 1];
                if (bias) { v0 += bias[c]; v1 += bias[c + 1]; }
                *(__half2*)(C + (size_t)r * Nreal + c) = __floats2half2_rn(v0, v1);
            }
        }
    }
}

static void launch_fast2(const float* Ap, const float* Bp,
                         __half* C1, int N1, const float* bias1,
                         __half* C2, int N2, const float* bias2,
                         int splitCt, int totalCt)
{
    cudaFuncSetAttribute(gemm_fast2, cudaFuncAttributeMaxDynamicSharedMemorySize, SMEM_FAST);
    gemm_fast2<<<dim3(totalCt, 256), 256, SMEM_FAST>>>(Ap, Bp, C1, N1, bias1, C2, N2, bias2, splitCt);
}

// --------------------- general GEMM (readout, 1xTF32, all-float) -----------
#define APAD  20
#define BPADF 132
#define SMEM_TC (2 * 128 * APAD * 4 + 2 * 16 * BPADF * 4)

template<int BMODE, int NSPLIT>
__global__ __launch_bounds__(256, 2) void gemm_tc(
    const float* __restrict__ A, const float* __restrict__ B,
    float* __restrict__ C, const float* __restrict__ bias,
    int M, int N, int K, int lda, int ldb, int ldc, int aStep)
{
    extern __shared__ char smraw[];
    float* Af = (float*)smraw;
    float* Bf = (float*)(smraw + 2 * 128 * APAD * 4);

    const int tid  = threadIdx.x;
    const int lane = tid & 31;
    const int w    = tid >> 5;
    const int wm   = w & 3;
    const int wn   = w >> 2;
    const int row0 = blockIdx.y * 128;
    const int col0 = blockIdx.x * 128;

    const int ktiles = (K + 15) >> 4;
    const int total  = ktiles * NSPLIT;

    float acc[2][8][4] = {};

    auto stage = [&](int t, int b) {
        const int sI = (NSPLIT == 1) ? 0 : (t / ktiles);
        const int kt = (NSPLIT == 1) ? t : (t % ktiles);
        const int k0 = kt << 4;
        const float* Ap = A + (size_t)sI * aStep;
#pragma unroll
        for (int i = 0; i < 2; i++) {
            int ch = tid + (i << 8);
            int row = ch >> 2, part = (ch & 3) << 2;
            int gr = row0 + row, gk = k0 + part;
            int sb = (gr < M && gk < K) ? 16 : 0;
            const float* src = sb ? (Ap + (size_t)gr * lda + gk) : Ap;
            cpa16(&Af[(size_t)b * (128 * APAD) + row * APAD + part], src, sb);
        }
        if (NSPLIT == 1) {
#pragma unroll
            for (int i = 0; i < 2; i++) {
                int ch = tid + (i << 8);
                int krow = ch >> 5, cp = (ch & 31) << 2;
                int gk = k0 + krow, gc = col0 + cp;
                int sb = (gk < K && gc < N) ? 16 : 0;
                const float* src = sb ? (B + (size_t)gk * ldb + gc) : B;
                cpa16(&Bf[(b * 16 + krow) * BPADF + cp], src, sb);
            }
        } else {
#pragma unroll
            for (int i = 0; i < 8; i++) {
                int ch = tid + (i << 8);
                int krow = ch >> 7, c = ch & 127;
                int gk = k0 + krow, gc = col0 + c;
                int sb = (gk < K && gc < N) ? 4 : 0;
                const float* src = sb ? (B + (size_t)gk * ldb + gc + sI) : B;
                cpa4(&Bf[(b * 16 + krow) * BPADF + c], src, sb);
            }
        }
        asm volatile("cp.async.commit_group;");
    };

    stage(0, 0);
    asm volatile("cp.async.wait_group 0;");
    __syncthreads();

    int buf = 0;
    const int r_  = lane >> 2;
    const int cc_ = lane & 3;

    for (int t = 0; t < total; t++) {
        if (t + 1 < total) stage(t + 1, buf ^ 1);

#pragma unroll
        for (int k2 = 0; k2 < 2; k2++) {
            unsigned ah[2][4];
#pragma unroll
            for (int mt = 0; mt < 2; mt++) {
                int rb = wm * 32 + mt * 16;
                const float* Ar = Af + (size_t)buf * (128 * APAD);
                ah[mt][0] = __float_as_uint(Ar[(rb + r_    ) * APAD + k2 * 8 + cc_]);
                ah[mt][1] = __float_as_uint(Ar[(rb + r_ + 8) * APAD + k2 * 8 + cc_]);
                ah[mt][2] = __float_as_uint(Ar[(rb + r_    ) * APAD + k2 * 8 + cc_ + 4]);
                ah[mt][3] = __float_as_uint(Ar[(rb + r_ + 8) * APAD + k2 * 8 + cc_ + 4]);
            }
#pragma unroll
            for (int nt = 0; nt < 8; nt++) {
                int cb = wn * 64 + nt * 8 + r_;
                int kb = k2 * 8 + cc_;
                unsigned bh[2];
                bh[0] = __float_as_uint(Bf[(buf * 16 + kb    ) * BPADF + cb]);
                bh[1] = __float_as_uint(Bf[(buf * 16 + kb + 4) * BPADF + cb]);
#pragma unroll
                for (int mt = 0; mt < 2; mt++) {
                    mma_tf32(acc[mt][nt], ah[mt], bh);
                }
            }
        }

        if (t + 1 < total) asm volatile("cp.async.wait_group 0;");
        __syncthreads();
        buf ^= 1;
    }

    const int gid = lane >> 2, tig = lane & 3;
#pragma unroll
    for (int mt = 0; mt < 2; mt++) {
#pragma unroll
        for (int half_ = 0; half_ < 2; half_++) {
            int r = row0 + wm * 32 + mt * 16 + half_ * 8 + gid;
            if (r >= M) continue;
            float rb = (BMODE == 3) ? bias[r] : 0.f;
#pragma unroll
            for (int nt = 0; nt < 8; nt++) {
                int c = col0 + wn * 64 + nt * 8 + tig * 2;
                if (c >= N) continue;
                float v0 = acc[mt][nt][half_ * 2 + 0];
                float v1 = acc[mt][nt][half_ * 2 + 1];
                if (BMODE == 1)      { v0 += bias[c]; v1 += bias[c + 1]; }
                else if (BMODE == 3) { v0 += rb; v1 += rb; }
                float2 o; o.x = v0; o.y = v1;
                *(float2*)(C + (size_t)r * ldc + c) = o;
            }
        }
    }
}

template<int BMODE, int NSPLIT>
static void launch_gemm(const float* A, const float* B, float* C, const float* bias,
                        int M, int N, int K, int lda, int ldb, int ldc, int aStep)
{
    cudaFuncSetAttribute(gemm_tc<BMODE, NSPLIT>,
                         cudaFuncAttributeMaxDynamicSharedMemorySize, SMEM_TC);
    dim3 grid((N + 127) / 128, (M + 127) / 128);
    gemm_tc<BMODE, NSPLIT><<<grid, 256, SMEM_TC>>>(A, B, C, bias, M, N, K, lda, ldb, ldc, aStep);
}

// GRU gates: half gi/gh inputs; raw + fragment-packed tf32 h out
__global__ void gates_k(const float* __restrict__ hin, float* __restrict__ hout,
                        float* __restrict__ hp) {
    int idx = blockIdx.x * blockDim.x + threadIdx.x;
    if (idx < NTOT * 50) {
        int n = idx / 50, q = idx % 50;
        const __half2* gi2 = (const __half2*)d_gih;
        const __half2* gh2 = (const __half2*)d_ghh;
        size_t b2 = (size_t)n * 300 + q * 2;
        float2 irA = __half22float2(gi2[b2      ]), irB = __half22float2(gi2[b2 + 1  ]);
        float2 hrA = __half22float2(gh2[b2      ]), hrB = __half22float2(gh2[b2 + 1  ]);
        float2 izA = __half22float2(gi2[b2 + 100]), izB = __half22float2(gi2[b2 + 101]);
        float2 hzA = __half22float2(gh2[b2 + 100]), hzB = __half22float2(gh2[b2 + 101]);
        float2 inA = __half22float2(gi2[b2 + 200]), inB = __half22float2(gi2[b2 + 201]);
        float2 hnA = __half22float2(gh2[b2 + 200]), hnB = __half22float2(gh2[b2 + 201]);
        float4 h4  = ((const float4*)hin)[(size_t)n * 50 + q];
        float ir[4] = {irA.x, irA.y, irB.x, irB.y};
        float hr[4] = {hrA.x, hrA.y, hrB.x, hrB.y};
        float iz[4] = {izA.x, izA.y, izB.x, izB.y};
        float hz[4] = {hzA.x, hzA.y, hzB.x, hzB.y};
        float in_[4] = {inA.x, inA.y, inB.x, inB.y};
        float hn[4] = {hnA.x, hnA.y, hnB.x, hnB.y};
        float hv[4] = {h4.x, h4.y, h4.z, h4.w};
        float ov[4];
#pragma unroll
        for (int i = 0; i < 4; i++) {
            float r = 1.f / (1.f + __expf(-(ir[i] + hr[i])));
            float z = 1.f / (1.f + __expf(-(iz[i] + hz[i])));
            float nn = tanhf(in_[i] + r * hn[i]);
            ov[i] = (1.f - z) * nn + z * hv[i];
        }
        float4 o; o.x = ov[0]; o.y = ov[1]; o.z = ov[2]; o.w = ov[3];
        ((float4*)hout)[(size_t)n * 50 + q] = o;
        int k0 = q * 4;
        hp[apack_idx(n, k0    )] = tfv(ov[0]);
        hp[apack_idx(n, k0 + 1)] = tfv(ov[1]);
        hp[apack_idx(n, k0 + 2)] = tfv(ov[2]);
        hp[apack_idx(n, k0 + 3)] = tfv(ov[3]);
    }
}

// in [G][C] raw -> out [C][G] tf32  (readout)
__global__ void transpose_tf_k(const float* __restrict__ in, float* __restrict__ out,
                               int G, int C) {
    __shared__ float tile[32][33];
    int c0 = blockIdx.x * 32;
    int g0 = blockIdx.y * 32;
    int c = c0 + threadIdx.x;
#pragma unroll
    for (int j = 0; j < 32; j += 8) {
        int g = g0 + threadIdx.y + j;
        tile[threadIdx.y + j][threadIdx.x] = (c < C && g < G) ? in[(size_t)g * C + c] : 0.f;
    }
    __syncthreads();
    int g = g0 + threadIdx.x;
#pragma unroll
    for (int j = 0; j < 32; j += 8) {
        int cc = c0 + threadIdx.y + j;
        if (cc < C && g < G) out[(size_t)cc * G + g] = tfv(tile[threadIdx.x][threadIdx.y + j]);
    }
}

__global__ void pool3_k(const float* __restrict__ in, float* __restrict__ out, int C) {
    int idx = blockIdx.x * blockDim.x + threadIdx.x;
    if (idx < C * GP1) {
        int co = idx / GP1;
        int r = idx % GP1;
        int b = r / P1, p = r % P1;
        int base = co * NTOT + b * NPG + 2 * p;
        float m = fmaxf(fmaxf(in[base], in[base + 1]), in[base + 2]);
        out[idx] = tfv(fmaxf(m, 0.f));
    }
}

__global__ void pool2_k(const float* __restrict__ in, float* __restrict__ out, int C) {
    int idx = blockIdx.x * blockDim.x + threadIdx.x;
    if (idx < C * GP2) {
        int co = idx / GP2;
        int r = idx % GP2;
        int b = r / P2, p = r % P2;
        int base = co * GP1 + b * P1 + 2 * p;
        out[idx] = tfv(fmaxf(fmaxf(in[base], in[base + 1]), 0.f));
    }
}

__global__ void final_k(const float* __restrict__ by, const float* __restrict__ bz,
                        float* __restrict__ out) {
    __shared__ float red[NCLS][128];
    int b = blockIdx.x;
    int tid = threadIdx.x;
    float part[NCLS] = {};
    for (int p = tid; p < P2; p += blockDim.x) {
        int base = b * P2 + p;
#pragma unroll
        for (int cl = 0; cl < NCLS; cl++) {
            float y = d_ly[cl * GP2 + base] + by[cl];
            float z = d_lz[cl * GP2 + base] + bz[cl];
            part[cl] += y * z;
        }
    }
#pragma unroll
    for (int cl = 0; cl < NCLS; cl++) red[cl][tid] = part[cl];
    __syncthreads();
    if (tid == 0) {
        float v[NCLS];
        for (int cl = 0; cl < NCLS; cl++) {
            float s = 0.f;
            for (int i = 0; i < 128; i++) s += red[cl][i];
            v[cl] = s / (float)P2;
        }
        float mx = v[0];
        for (int cl = 1; cl < NCLS; cl++) mx = fmaxf(mx, v[cl]);
        float se = 0.f;
        for (int cl = 0; cl < NCLS; cl++) { v[cl] = __expf(v[cl] - mx); se += v[cl]; }
        for (int cl = 0; cl < NCLS; cl++) out[b * NCLS + cl] = v[cl] / se;
    }
}

// ----------------------------- host side ----------------------------------
static void* getsym(const void* s) {
    void* p = nullptr;
    cudaGetSymbolAddress(&p, s);
    return p;
}

extern "C" void kernel_launch(void* const* d_in, const int* in_sizes, int n_in,
                              void* d_out, int out_size)
{
    const float* features = (const float*)d_in[0];
    const int*   esrc     = (const int*)  d_in[1];
    const int*   edst     = (const int*)  d_in[2];
    const int*   etyp     = (const int*)  d_in[3];
    const float* etype_W  = (const float*)d_in[4];
    const float* etype_b  = (const float*)d_in[5];
    const float* W_ih     = (const float*)d_in[6];
    const float* b_ih     = (const float*)d_in[7];
    const float* W_hh     = (const float*)d_in[8];
    const float* b_hh     = (const float*)d_in[9];
    const float* conv1_w  = (const float*)d_in[10];
    const float* conv1_b  = (const float*)d_in[11];
    const float* conv2_w  = (const float*)d_in[12];
    const float* conv2_b  = (const float*)d_in[13];
    const float* convc1_w = (const float*)d_in[14];
    const float* convc1_b = (const float*)d_in[15];
    const float* convc2_w = (const float*)d_in[16];
    const float* convc2_b = (const float*)d_in[17];
    const float* mlp_y_w  = (const float*)d_in[18];
    const float* mlp_y_b  = (const float*)d_in[19];
    const float* mlp_z_w  = (const float*)d_in[20];
    const float* mlp_z_b  = (const float*)d_in[21];

    float*  p_h0    = (float*) getsym(d_h0);
    float*  p_h1    = (float*) getsym(d_h1);
    float*  p_hp0   = (float*) getsym(d_hpack0);
    float*  p_hp1   = (float*) getsym(d_hpack1);
    float*  p_ap    = (float*) getsym(d_apack);
    __half* p_Hth   = (__half*)getsym(d_Hth);
    __half* p_gih   = (__half*)getsym(d_gih);
    __half* p_ghh   = (__half*)getsym(d_ghh);
    float*  p_Wcomb = (float*) getsym(d_Wcombp);
    float*  p_Wihp  = (float*) getsym(d_Wihp);
    int*    p_deg4  = (int*)   getsym(d_deg4);
    float*  p_cTt   = (float*) getsym(d_cTt);
    float*  p_w1yt  = (float*) getsym(d_w1yt);
    float*  p_w1zt  = (float*) getsym(d_w1zt);
    float*  p_w2yt  = (float*) getsym(d_w2yt);
    float*  p_w2zt  = (float*) getsym(d_w2zt);
    float*  p_wmyt  = (float*) getsym(d_wmyt);
    float*  p_wmzt  = (float*) getsym(d_wmzt);
    float*  p_y1    = (float*) getsym(d_y1);
    float*  p_z1    = (float*) getsym(d_z1);
    float*  p_yp1t  = (float*) getsym(d_yp1t);
    float*  p_zp1t  = (float*) getsym(d_zp1t);
    float*  p_y2    = (float*) getsym(d_y2);
    float*  p_z2    = (float*) getsym(d_z2);
    float*  p_yp2t  = (float*) getsym(d_yp2t);
    float*  p_zp2t  = (float*) getsym(d_zp2t);
    float*  p_ly    = (float*) getsym(d_ly);
    float*  p_lz    = (float*) getsym(d_lz);

    const int T = 256;

    // ---- first launches ----
    zero_pack_k<<<(3 * 256 * 2 * 2048 + T - 1) / T, T>>>();                      // 0
    init_h_k<<<(NTOT * ODIM + T - 1) / T, T>>>(features);                        // 1
    packB_comb<<<(12 * KT * 512 + T - 1) / T, T>>>(etype_W, W_hh);               // 2
    launch_fast2(p_hp0, p_Wcomb, p_Hth, 800, nullptr, p_ghh, H3, b_hh, 7, 12);   // 3 (step-0 Ht+gh)

    // ---- rest of setup ----
    packB_k<<<(5 * KT * 512 + T - 1) / T, T>>>(W_ih, p_Wihp, H3, 5);
    zero_int_k<<<(NTOT * 4 + T - 1) / T, T>>>(p_deg4, NTOT * 4);
    hist_k<<<(EDGES + T - 1) / T, T>>>(edst, etyp);
    scan_k<<<1, 1024>>>();
    chunk_hist_k<<<dim3(NCHK, BATCH), 512>>>(edst);
    chunk_scan_k<<<(NTOT + T - 1) / T, T>>>();
    scatter_k<<<dim3(NCHK, BATCH), 512>>>(esrc, edst, etyp);
    pack_conv_tf_k<<<(3 * ODIM * ODIM + T - 1) / T, T>>>(conv1_w, p_w1yt, ODIM);
    pack_conv_tf_k<<<(3 * CDIM * CDIM + T - 1) / T, T>>>(convc1_w, p_w1zt, CDIM);
    split_tf_k<<<(ODIM * ODIM + T - 1) / T, T>>>(conv2_w, p_w2yt, ODIM * ODIM);
    split_tf_k<<<(CDIM * CDIM + T - 1) / T, T>>>(convc2_w, p_w2zt, CDIM * CDIM);
    split_tf_k<<<(NCLS * ODIM + T - 1) / T, T>>>(mlp_y_w, p_wmyt, NCLS * ODIM);
    split_tf_k<<<(NCLS * CDIM + T - 1) / T, T>>>(mlp_z_w, p_wmzt, NCLS * CDIM);
    nodebias_k<<<(NTOT * ODIM + T - 1) / T, T>>>(etype_b);

    // ---- GGNN: 8 steps ----
    for (int s = 0; s < 8; s++) {
        const float* hin  = (s & 1) ? p_h1 : p_h0;
        float*       hout = (s & 1) ? p_h0 : p_h1;
        const float* hpin = (s & 1) ? p_hp1 : p_hp0;
        float*       hpout= (s & 1) ? p_hp0 : p_hp1;
        if (s > 0)
            launch_fast2(hpin, p_Wcomb, p_Hth, 800, nullptr, p_ghh, H3, b_hh, 7, 12);
        spmm_k<<<NTOT / 4, 128>>>(p_Hth);
        launch_fast2(p_ap, p_Wihp, p_gih, H3, b_ih, nullptr, 0, nullptr, 5, 5);
        gates_k<<<(NTOT * 50 + T - 1) / T, T>>>(hin, hout, hpout);
    }
    float* p_hf = p_h0;

    // ---- readout ----
    transpose_tf_k<<<dim3((ODIM + 31) / 32, NTOT / 32), dim3(32, 8)>>>(p_hf, p_cTt, NTOT, ODIM);
    transpose_tf_k<<<dim3((IDIM + 31) / 32, NTOT / 32), dim3(32, 8)>>>(features, p_cTt + (size_t)ODIM * NTOT, NTOT, IDIM);

    launch_gemm<3,3>(p_w1yt, p_cTt, p_y1, conv1_b, ODIM, NTOT, ODIM, ODIM, NTOT, NTOT, ODIM * ODIM);
    pool3_k<<<(ODIM * GP1 + T - 1) / T, T>>>(p_y1, p_yp1t, ODIM);
    launch_gemm<3,1>(p_w2yt, p_yp1t, p_y2, conv2_b, ODIM, GP1, ODIM, ODIM, GP1, GP1, 0);
    pool2_k<<<(ODIM * GP2 + T - 1) / T, T>>>(p_y2, p_yp2t, ODIM);

    launch_gemm<3,3>(p_w1zt, p_cTt, p_z1, convc1_b, CDIM, NTOT, CDIM, CDIM, NTOT, NTOT, CDIM * CDIM);
    pool3_k<<<(CDIM * GP1 + T - 1) / T, T>>>(p_z1, p_zp1t, CDIM);
    launch_gemm<3,1>(p_w2zt, p_zp1t, p_z2, convc2_b, CDIM, GP1, CDIM, CDIM, GP1, GP1, 0);
    pool2_k<<<(CDIM * GP2 + T - 1) / T, T>>>(p_z2, p_zp2t, CDIM);

    launch_gemm<0,1>(p_wmyt, p_yp2t, p_ly, nullptr, NCLS, GP2, ODIM, ODIM, GP2, GP2, 0);
    launch_gemm<0,1>(p_wmzt, p_zp2t, p_lz, nullptr, NCLS, GP2, CDIM, CDIM, GP2, GP2, 0);

    final_k<<<BATCH, 128>>>(mlp_y_b, mlp_z_b, (float*)d_out);
}

// round 15
// speedup vs baseline: 3.2680x; 1.2467x over previous
#include <cuda_runtime.h>
#include <cuda_fp16.h>

#define BATCH  64
#define NPG    512
#define NTOT   32768
#define EDGES  524288
#define EPG    8192
#define NCHK   16
#define ODIM   200
#define IDIM   100
#define H3     600
#define CDIM   300
#define P1     254
#define P2     127
#define GP1    16256
#define GP2    8128
#define NCLS   7
#define KT     14                        /* 224 padded K / 16 */
#define KHALF  7
#define HPACK_HALFS (256*KT*2048)

// ----------------------------- device scratch -----------------------------
__device__ float  d_h0[NTOT*ODIM];
__device__ float  d_h1[NTOT*ODIM];
__device__ __half d_hpack0[HPACK_HALFS];
__device__ __half d_hpack1[HPACK_HALFS];
__device__ __half d_apack[HPACK_HALFS];
__device__ __half d_Hth[NTOT*4*ODIM];
__device__ __half d_gih[NTOT*H3];
__device__ __half d_ghh[NTOT*H3];
__device__ __half d_Wcombp[12*KT*2048];
__device__ __half d_Wihp[5*KT*2048];
__device__ float  d_nbias[NTOT*ODIM];
__device__ int    d_deg4[NTOT*4];
__device__ int    d_indptr[NTOT+1];
__device__ int    d_ccnt[NTOT*NCHK];
__device__ int    d_srcs[EDGES];
__device__ int    d_typs[EDGES];
__device__ float  d_cTt[CDIM*NTOT + 64];
__device__ float  d_w1yt[3*ODIM*ODIM];
__device__ float  d_w1zt[3*CDIM*CDIM];
__device__ float  d_w2yt[ODIM*ODIM];
__device__ float  d_w2zt[CDIM*CDIM];
__device__ float  d_wmyt[NCLS*ODIM];
__device__ float  d_wmzt[NCLS*CDIM];
__device__ float  d_y1[ODIM*NTOT];
__device__ float  d_z1[CDIM*NTOT];
__device__ float  d_yp1t[ODIM*GP1];
__device__ float  d_zp1t[CDIM*GP1];
__device__ float  d_y2[ODIM*GP1];
__device__ float  d_z2[CDIM*GP1];
__device__ float  d_yp2t[ODIM*GP2];
__device__ float  d_zp2t[CDIM*GP2];
__device__ float  d_ly[NCLS*GP2];
__device__ float  d_lz[NCLS*GP2];

// ----------------------------- helpers ------------------------------------
__device__ __forceinline__ unsigned f2tf32(float f) {
    unsigned u;
    asm("cvt.rna.tf32.f32 %0, %1;" : "=r"(u) : "f"(f));
    return u;
}
__device__ __forceinline__ float tfv(float f) { return __uint_as_float(f2tf32(f)); }

// half index of A-fragment-packed element (n, k) for m16n8k16
__device__ __forceinline__ int apack_idx(int n, int k) {
    int rt = n >> 7, row = n & 127, mb = row >> 4, fr = row & 15;
    int g = fr & 7, hr = fr >> 3;
    int kt = k >> 4, kk = k & 15, hk = kk >> 3, tig = (kk & 7) >> 1, par = kk & 1;
    int lane = g * 4 + tig;
    return (((rt * KT + kt) * 256 + mb * 32 + lane) << 3) + hk * 4 + hr * 2 + par;
}

// ----------------------------- setup kernels ------------------------------
__global__ void zero_int_k(int* p, int n) {
    int i = blockIdx.x * blockDim.x + threadIdx.x;
    if (i < n) p[i] = 0;
}

// zero padding ktiles (12,13) of the three packed-A half buffers
__global__ void zero_pack_k() {
    int i = blockIdx.x * blockDim.x + threadIdx.x;
    const int per = 256 * 2 * 1024;           // ints per buffer
    if (i < 3 * per) {
        int b = i / per, r = i % per;
        int rt = r / (2 * 1024), rem = r % (2 * 1024);
        int kt = 12 + rem / 1024, off = rem % 1024;
        __half* p = (b == 0) ? d_hpack0 : (b == 1) ? d_hpack1 : d_apack;
        ((unsigned*)p)[(rt * KT + kt) * 1024 + off] = 0u;
    }
}

__global__ void hist_k(const int* __restrict__ edst, const int* __restrict__ etyp) {
    int e = blockIdx.x * blockDim.x + threadIdx.x;
    if (e < EDGES) atomicAdd(&d_deg4[edst[e] * 4 + etyp[e]], 1);
}

__global__ void scan_k() {
    __shared__ int ssum[1024];
    int t = threadIdx.x;
    int loc[32];
    int s = 0;
#pragma unroll
    for (int i = 0; i < 32; i++) {
        int n = t * 32 + i;
        int d = d_deg4[n*4] + d_deg4[n*4+1] + d_deg4[n*4+2] + d_deg4[n*4+3];
        loc[i] = s; s += d;
    }
    ssum[t] = s;
    __syncthreads();
    if (t == 0) {
        int acc = 0;
        for (int i = 0; i < 1024; i++) { int v = ssum[i]; ssum[i] = acc; acc += v; }
        d_indptr[NTOT] = acc;
    }
    __syncthreads();
    int off = ssum[t];
#pragma unroll
    for (int i = 0; i < 32; i++) d_indptr[t * 32 + i] = off + loc[i];
}

__global__ void chunk_hist_k(const int* __restrict__ edst) {
    __shared__ int h[NPG];
    int g = blockIdx.y, c = blockIdx.x;
    h[threadIdx.x] = 0;
    __syncthreads();
    int e = g * EPG + c * 512 + threadIdx.x;
    atomicAdd(&h[edst[e] - g * NPG], 1);
    __syncthreads();
    d_ccnt[(g * NPG + threadIdx.x) * NCHK + c] = h[threadIdx.x];
}

__global__ void chunk_scan_k() {
    int n = blockIdx.x * blockDim.x + threadIdx.x;
    if (n < NTOT) {
        int base = d_indptr[n];
#pragma unroll
        for (int c = 0; c < NCHK; c++) {
            int v = d_ccnt[n * NCHK + c];
            d_ccnt[n * NCHK + c] = base;
            base += v;
        }
    }
}

__global__ void scatter_k(const int* __restrict__ esrc, const int* __restrict__ edst,
                          const int* __restrict__ etyp) {
    __shared__ int sd[512];
    int g = blockIdx.y, c = blockIdx.x;
    int e = g * EPG + c * 512 + threadIdx.x;
    int dl = edst[e] - g * NPG;
    sd[threadIdx.x] = dl;
    __syncthreads();
    int rank = 0;
    for (int i = 0; i < threadIdx.x; i++) rank += (sd[i] == dl);
    int pos = d_ccnt[(g * NPG + dl) * NCHK + c] + rank;
    d_srcs[pos] = esrc[e];
    d_typs[pos] = etyp[e];
}

// B fragment pack (fp16): thread per (ct,kt,c,tig); vec8B = {k0,k0+1,k0+8,k0+9}@col
__device__ __forceinline__ void packB_one(const float* W, __half* out,
                                          int Nreal, int t) {
    int tig = t & 3;
    int c   = (t >> 2) & 127;
    int kt  = (t >> 9) % KT;
    int ct  = t / (KT * 512);
    int cg  = (ct % 12) * 128 + c;   // caller adjusts base per matrix via pointer math
    (void)cg;
}

// combined B pack: ct 0..6 = etype_W [800][200]; ct 7..11 = W_hh [600][200].
__global__ void packB_comb(const float* __restrict__ Wst, const float* __restrict__ Whh) {
    int t = blockIdx.x * blockDim.x + threadIdx.x;
    if (t >= 12 * KT * 512) return;
    int tig = t & 3;
    int c   = (t >> 2) & 127;
    int kt  = (t >> 9) % KT;
    int ct  = t / (KT * 512);
    const float* W; int Nreal, cg;
    if (ct < 7) { W = Wst; Nreal = 800; cg = ct * 128 + c; }
    else        { W = Whh; Nreal = 600; cg = (ct - 7) * 128 + c; }
    float v0 = 0.f, v1 = 0.f, v2 = 0.f, v3 = 0.f;
    if (cg < Nreal) {
        int k0 = kt * 16 + 2 * tig;
        v0 = (k0     < 200) ? W[cg * 200 + k0    ] : 0.f;
        v1 = (k0 + 1 < 200) ? W[cg * 200 + k0 + 1] : 0.f;
        v2 = (k0 + 8 < 200) ? W[cg * 200 + k0 + 8] : 0.f;
        v3 = (k0 + 9 < 200) ? W[cg * 200 + k0 + 9] : 0.f;
    }
    int vi = (ct * KT + kt) * 512 + c * 4 + tig;
    __half2* o2 = (__half2*)d_Wcombp;
    o2[vi * 2]     = __floats2half2_rn(v0, v1);
    o2[vi * 2 + 1] = __floats2half2_rn(v2, v3);
}

__global__ void packB_k(const float* __restrict__ W, __half* __restrict__ out,
                        int Nreal, int nct) {
    int t = blockIdx.x * blockDim.x + threadIdx.x;
    if (t >= nct * KT * 512) return;
    int tig = t & 3;
    int c   = (t >> 2) & 127;
    int kt  = (t >> 9) % KT;
    int ct  = t / (KT * 512);
    int cg  = ct * 128 + c;
    float v0 = 0.f, v1 = 0.f, v2 = 0.f, v3 = 0.f;
    if (cg < Nreal) {
        int k0 = kt * 16 + 2 * tig;
        v0 = (k0     < 200) ? W[cg * 200 + k0    ] : 0.f;
        v1 = (k0 + 1 < 200) ? W[cg * 200 + k0 + 1] : 0.f;
        v2 = (k0 + 8 < 200) ? W[cg * 200 + k0 + 8] : 0.f;
        v3 = (k0 + 9 < 200) ? W[cg * 200 + k0 + 9] : 0.f;
    }
    int vi = (ct * KT + kt) * 512 + c * 4 + tig;
    __half2* o2 = (__half2*)out;
    o2[vi * 2]     = __floats2half2_rn(v0, v1);
    o2[vi * 2 + 1] = __floats2half2_rn(v2, v3);
}

// conv weight [C][C][3] -> [k][co][ci] tf32  (readout)
__global__ void pack_conv_tf_k(const float* __restrict__ W, float* __restrict__ out, int C) {
    int idx = blockIdx.x * blockDim.x + threadIdx.x;
    if (idx < 3 * C * C) {
        int ci = idx % C;
        int co = (idx / C) % C;
        int k  = idx / (C * C);
        out[idx] = tfv(W[(co * C + ci) * 3 + k]);
    }
}

__global__ void split_tf_k(const float* __restrict__ in, float* __restrict__ out, int n) {
    int i = blockIdx.x * blockDim.x + threadIdx.x;
    if (i < n) out[i] = tfv(in[i]);
}

__global__ void init_h_k(const float* __restrict__ feat) {
    int idx = blockIdx.x * blockDim.x + threadIdx.x;
    if (idx < NTOT * ODIM) {
        int d = idx % ODIM;
        int n = idx / ODIM;
        float v = (d < IDIM) ? feat[n * IDIM + d] : 0.f;
        d_h0[idx] = v;
        d_hpack0[apack_idx(n, d)] = __float2half(v);
    }
}

__global__ void nodebias_k(const float* __restrict__ eb) {
    int idx = blockIdx.x * blockDim.x + threadIdx.x;
    if (idx < NTOT * ODIM) {
        int o = idx % ODIM;
        int n = idx / ODIM;
        float s = 0.f;
#pragma unroll
        for (int t = 0; t < 4; t++) s += (float)d_deg4[n * 4 + t] * eb[t * ODIM + o];
        d_nbias[idx] = s;
    }
}

// warp-per-node SPMM: a[n][o] = nbias + sum edges Ht_h[src][t*200+o].
__global__ void spmm_k(const __half* __restrict__ Ht) {
    int warp = threadIdx.x >> 5, lane = threadIdx.x & 31;
    int n = blockIdx.x * 4 + warp;
    int beg = d_indptr[n], end = d_indptr[n + 1];
    float ax[4] = {}, ay[4] = {};
    for (int base = beg; base < end; base += 32) {
        int cnt = min(32, end - base);
        int off = 0;
        if (lane < cnt) off = d_srcs[base + lane] * 800 + d_typs[base + lane] * ODIM;
        for (int e = 0; e < cnt; e++) {
            int o = __shfl_sync(0xffffffffu, off, e);
#pragma unroll
            for (int q = 0; q < 4; q++) {
                int c = lane + q * 32;
                if (q < 3 || lane < 4) {
                    float2 f = __half22float2(*(const __half2*)&Ht[o + 2 * c]);
                    ax[q] += f.x; ay[q] += f.y;
                }
            }
        }
    }
#pragma unroll
    for (int q = 0; q < 4; q++) {
        int c = lane + q * 32;
        if (q < 3 || lane < 4) {
            int o = n * ODIM + 2 * c;
            *(__half2*)&d_apack[apack_idx(n, 2 * c)] =
                __floats2half2_rn(ax[q] + d_nbias[o], ay[q] + d_nbias[o + 1]);
        }
    }
}

// ----------------------------- MMA helpers --------------------------------
__device__ __forceinline__ void mma_f16(float* d, const unsigned* a, const unsigned* b) {
    asm volatile(
        "mma.sync.aligned.m16n8k16.row.col.f32.f16.f16.f32 "
        "{%0,%1,%2,%3}, {%4,%5,%6,%7}, {%8,%9}, {%0,%1,%2,%3};"
        : "+f"(d[0]), "+f"(d[1]), "+f"(d[2]), "+f"(d[3])
        : "r"(a[0]), "r"(a[1]), "r"(a[2]), "r"(a[3]), "r"(b[0]), "r"(b[1]));
}
__device__ __forceinline__ void mma_tf32(float* d, const unsigned* a, const unsigned* b) {
    asm volatile(
        "mma.sync.aligned.m16n8k8.row.col.f32.tf32.tf32.f32 "
        "{%0,%1,%2,%3}, {%4,%5,%6,%7}, {%8,%9}, {%0,%1,%2,%3};"
        : "+f"(d[0]), "+f"(d[1]), "+f"(d[2]), "+f"(d[3])
        : "r"(a[0]), "r"(a[1]), "r"(a[2]), "r"(a[3]), "r"(b[0]), "r"(b[1]));
}
__device__ __forceinline__ void cpa16(void* dst, const void* src, int sb) {
    unsigned sa = (unsigned)__cvta_generic_to_shared(dst);
    asm volatile("cp.async.cg.shared.global [%0], [%1], 16, %2;" :: "r"(sa), "l"(src), "r"(sb));
}
__device__ __forceinline__ void cpa16u(void* dst, const void* src) {
    unsigned sa = (unsigned)__cvta_generic_to_shared(dst);
    asm volatile("cp.async.cg.shared.global [%0], [%1], 16;" :: "r"(sa), "l"(src));
}
__device__ __forceinline__ void cpa4(void* dst, const void* src, int sb) {
    unsigned sa = (unsigned)__cvta_generic_to_shared(dst);
    asm volatile("cp.async.ca.shared.global [%0], [%1], 4, %2;" :: "r"(sa), "l"(src), "r"(sb));
}

// --------------------- fast GEMM (GGNN loop): fp16 m16n8k16 ----------------
// 2 ktiles per stage, 3-stage cp.async. A/B fragment-packed fp16.
#define SMEM_FAST (3 * 1024 * 16)

__global__ __launch_bounds__(256, 2) void gemm_fast2(
    const __half* __restrict__ Ap, const __half* __restrict__ Bp,
    __half* __restrict__ C1, int N1, const float* __restrict__ bias1,
    __half* __restrict__ C2, int N2, const float* __restrict__ bias2,
    int splitCt)
{
    extern __shared__ float sm[];
    uint4* smv = (uint4*)sm;
    const int tid  = threadIdx.x;
    const int lane = tid & 31;
    const int w    = tid >> 5;
    const int wm   = w & 3;
    const int wn   = w >> 2;
    const int rt   = blockIdx.y * KT;
    const int ct   = blockIdx.x * KT;
    const int row0 = blockIdx.y * 128;

    float acc[2][8][4] = {};

    int aoff[2];
#pragma unroll
    for (int mt = 0; mt < 2; mt++) aoff[mt] = (wm * 2 + mt) * 32 + lane;
    int cb[8];
#pragma unroll
    for (int nt = 0; nt < 8; nt++)
        cb[nt] = (wn * 64 + nt * 8 + (lane >> 2)) * 4 + (lane & 3);

    auto stage = [&](int it, int b) {
        uint4* d = smv + b * 1024;
        const uint4* sa = (const uint4*)Ap + (size_t)(rt + 2 * it) * 256;
        cpa16u(&d[tid],       &sa[tid]);
        cpa16u(&d[tid + 256], &sa[tid + 256]);
        uint4* db = d + 512;
        const uint4* sb = (const uint4*)Bp + (size_t)(ct + 2 * it) * 256;
        cpa16u(&db[tid],       &sb[tid]);
        cpa16u(&db[tid + 256], &sb[tid + 256]);
        asm volatile("cp.async.commit_group;");
    };

    stage(0, 0);
    stage(1, 1);

#pragma unroll 1
    for (int it = 0; it < KHALF; it++) {
        if (it < KHALF - 1) asm volatile("cp.async.wait_group 1;");
        else                asm volatile("cp.async.wait_group 0;");
        __syncthreads();
        if (it + 2 < KHALF) stage(it + 2, (it + 2) % 3);

        const uint4* base = smv + (it % 3) * 1024;
#pragma unroll
        for (int sub = 0; sub < 2; sub++) {
            const uint4* Ab = base + sub * 256;
            const uint2* Bb = (const uint2*)(base + 512) + sub * 512;

            unsigned ah[2][4];
#pragma unroll
            for (int mt = 0; mt < 2; mt++) {
                uint4 v = Ab[aoff[mt]];
                ah[mt][0] = v.x; ah[mt][1] = v.y; ah[mt][2] = v.z; ah[mt][3] = v.w;
            }
#pragma unroll
            for (int nt = 0; nt < 8; nt++) {
                uint2 bv = Bb[cb[nt]];
                unsigned bb[2] = {bv.x, bv.y};
#pragma unroll
                for (int mt = 0; mt < 2; mt++)
                    mma_f16(acc[mt][nt], ah[mt], bb);
            }
        }
    }

    const bool first = (int)blockIdx.x < splitCt;
    __half* C = first ? C1 : C2;
    const int Nreal = first ? N1 : N2;
    const float* bias = first ? bias1 : bias2;
    const int colb = (first ? blockIdx.x : blockIdx.x - splitCt) * 128;

    const int gid = lane >> 2, tig = lane & 3;
#pragma unroll
    for (int mt = 0; mt < 2; mt++) {
#pragma unroll
        for (int half_ = 0; half_ < 2; half_++) {
            int r = row0 + wm * 32 + mt * 16 + half_ * 8 + gid;
#pragma unroll
            for (int nt = 0; nt < 8; nt++) {
                int c = colb + wn * 64 + nt * 8 + tig * 2;
                if (c >= Nreal) continue;
                float v0 = acc[mt][nt][half_ * 2 + 0];
                float v1 = acc[mt][nt][half_ * 2 + 1];
                if (bias) { v0 += bias[c]; v1 += bias[c + 1]; }
                *(__half2*)(C + (size_t)r * Nreal + c) = __floats2half2_rn(v0, v1);
            }
        }
    }
}

static void launch_fast2(const __half* Ap, const __half* Bp,
                         __half* C1, int N1, const float* bias1,
                         __half* C2, int N2, const float* bias2,
                         int splitCt, int totalCt)
{
    cudaFuncSetAttribute(gemm_fast2, cudaFuncAttributeMaxDynamicSharedMemorySize, SMEM_FAST);
    gemm_fast2<<<dim3(totalCt, 256), 256, SMEM_FAST>>>(Ap, Bp, C1, N1, bias1, C2, N2, bias2, splitCt);
}

// --------------------- general GEMM (readout, 1xTF32, all-float) -----------
#define APAD  20
#define BPADF 132
#define SMEM_TC (2 * 128 * APAD * 4 + 2 * 16 * BPADF * 4)

template<int BMODE, int NSPLIT>
__global__ __launch_bounds__(256, 2) void gemm_tc(
    const float* __restrict__ A, const float* __restrict__ B,
    float* __restrict__ C, const float* __restrict__ bias,
    int M, int N, int K, int lda, int ldb, int ldc, int aStep)
{
    extern __shared__ char smraw[];
    float* Af = (float*)smraw;
    float* Bf = (float*)(smraw + 2 * 128 * APAD * 4);

    const int tid  = threadIdx.x;
    const int lane = tid & 31;
    const int w    = tid >> 5;
    const int wm   = w & 3;
    const int wn   = w >> 2;
    const int row0 = blockIdx.y * 128;
    const int col0 = blockIdx.x * 128;

    const int ktiles = (K + 15) >> 4;
    const int total  = ktiles * NSPLIT;

    float acc[2][8][4] = {};

    auto stage = [&](int t, int b) {
        const int sI = (NSPLIT == 1) ? 0 : (t / ktiles);
        const int kt = (NSPLIT == 1) ? t : (t % ktiles);
        const int k0 = kt << 4;
        const float* Ap = A + (size_t)sI * aStep;
#pragma unroll
        for (int i = 0; i < 2; i++) {
            int ch = tid + (i << 8);
            int row = ch >> 2, part = (ch & 3) << 2;
            int gr = row0 + row, gk = k0 + part;
            int sb = (gr < M && gk < K) ? 16 : 0;
            const float* src = sb ? (Ap + (size_t)gr * lda + gk) : Ap;
            cpa16(&Af[(size_t)b * (128 * APAD) + row * APAD + part], src, sb);
        }
        if (NSPLIT == 1) {
#pragma unroll
            for (int i = 0; i < 2; i++) {
                int ch = tid + (i << 8);
                int krow = ch >> 5, cp = (ch & 31) << 2;
                int gk = k0 + krow, gc = col0 + cp;
                int sb = (gk < K && gc < N) ? 16 : 0;
                const float* src = sb ? (B + (size_t)gk * ldb + gc) : B;
                cpa16(&Bf[(b * 16 + krow) * BPADF + cp], src, sb);
            }
        } else {
#pragma unroll
            for (int i = 0; i < 8; i++) {
                int ch = tid + (i << 8);
                int krow = ch >> 7, c = ch & 127;
                int gk = k0 + krow, gc = col0 + c;
                int sb = (gk < K && gc < N) ? 4 : 0;
                const float* src = sb ? (B + (size_t)gk * ldb + gc + sI) : B;
                cpa4(&Bf[(b * 16 + krow) * BPADF + c], src, sb);
            }
        }
        asm volatile("cp.async.commit_group;");
    };

    stage(0, 0);
    asm volatile("cp.async.wait_group 0;");
    __syncthreads();

    int buf = 0;
    const int r_  = lane >> 2;
    const int cc_ = lane & 3;

    for (int t = 0; t < total; t++) {
        if (t + 1 < total) stage(t + 1, buf ^ 1);

#pragma unroll
        for (int k2 = 0; k2 < 2; k2++) {
            unsigned ah[2][4];
#pragma unroll
            for (int mt = 0; mt < 2; mt++) {
                int rb = wm * 32 + mt * 16;
                const float* Ar = Af + (size_t)buf * (128 * APAD);
                ah[mt][0] = __float_as_uint(Ar[(rb + r_    ) * APAD + k2 * 8 + cc_]);
                ah[mt][1] = __float_as_uint(Ar[(rb + r_ + 8) * APAD + k2 * 8 + cc_]);
                ah[mt][2] = __float_as_uint(Ar[(rb + r_    ) * APAD + k2 * 8 + cc_ + 4]);
                ah[mt][3] = __float_as_uint(Ar[(rb + r_ + 8) * APAD + k2 * 8 + cc_ + 4]);
            }
#pragma unroll
            for (int nt = 0; nt < 8; nt++) {
                int cb2 = wn * 64 + nt * 8 + r_;
                int kb = k2 * 8 + cc_;
                unsigned bh[2];
                bh[0] = __float_as_uint(Bf[(buf * 16 + kb    ) * BPADF + cb2]);
                bh[1] = __float_as_uint(Bf[(buf * 16 + kb + 4) * BPADF + cb2]);
#pragma unroll
                for (int mt = 0; mt < 2; mt++) {
                    mma_tf32(acc[mt][nt], ah[mt], bh);
                }
            }
        }

        if (t + 1 < total) asm volatile("cp.async.wait_group 0;");
        __syncthreads();
        buf ^= 1;
    }

    const int gid = lane >> 2, tig = lane & 3;
#pragma unroll
    for (int mt = 0; mt < 2; mt++) {
#pragma unroll
        for (int half_ = 0; half_ < 2; half_++) {
            int r = row0 + wm * 32 + mt * 16 + half_ * 8 + gid;
            if (r >= M) continue;
            float rb = (BMODE == 3) ? bias[r] : 0.f;
#pragma unroll
            for (int nt = 0; nt < 8; nt++) {
                int c = col0 + wn * 64 + nt * 8 + tig * 2;
                if (c >= N) continue;
                float v0 = acc[mt][nt][half_ * 2 + 0];
                float v1 = acc[mt][nt][half_ * 2 + 1];
                if (BMODE == 1)      { v0 += bias[c]; v1 += bias[c + 1]; }
                else if (BMODE == 3) { v0 += rb; v1 += rb; }
                float2 o; o.x = v0; o.y = v1;
                *(float2*)(C + (size_t)r * ldc + c) = o;
            }
        }
    }
}

template<int BMODE, int NSPLIT>
static void launch_gemm(const float* A, const float* B, float* C, const float* bias,
                        int M, int N, int K, int lda, int ldb, int ldc, int aStep)
{
    cudaFuncSetAttribute(gemm_tc<BMODE, NSPLIT>,
                         cudaFuncAttributeMaxDynamicSharedMemorySize, SMEM_TC);
    dim3 grid((N + 127) / 128, (M + 127) / 128);
    gemm_tc<BMODE, NSPLIT><<<grid, 256, SMEM_TC>>>(A, B, C, bias, M, N, K, lda, ldb, ldc, aStep);
}

// GRU gates: half gi/gh inputs; raw + fp16 fragment-packed h out
__global__ void gates_k(const float* __restrict__ hin, float* __restrict__ hout,
                        __half* __restrict__ hp) {
    int idx = blockIdx.x * blockDim.x + threadIdx.x;
    if (idx < NTOT * 50) {
        int n = idx / 50, q = idx % 50;
        const __half2* gi2 = (const __half2*)d_gih;
        const __half2* gh2 = (const __half2*)d_ghh;
        size_t b2 = (size_t)n * 300 + q * 2;
        float2 irA = __half22float2(gi2[b2      ]), irB = __half22float2(gi2[b2 + 1  ]);
        float2 hrA = __half22float2(gh2[b2      ]), hrB = __half22float2(gh2[b2 + 1  ]);
        float2 izA = __half22float2(gi2[b2 + 100]), izB = __half22float2(gi2[b2 + 101]);
        float2 hzA = __half22float2(gh2[b2 + 100]), hzB = __half22float2(gh2[b2 + 101]);
        float2 inA = __half22float2(gi2[b2 + 200]), inB = __half22float2(gi2[b2 + 201]);
        float2 hnA = __half22float2(gh2[b2 + 200]), hnB = __half22float2(gh2[b2 + 201]);
        float4 h4  = ((const float4*)hin)[(size_t)n * 50 + q];
        float ir[4] = {irA.x, irA.y, irB.x, irB.y};
        float hr[4] = {hrA.x, hrA.y, hrB.x, hrB.y};
        float iz[4] = {izA.x, izA.y, izB.x, izB.y};
        float hz[4] = {hzA.x, hzA.y, hzB.x, hzB.y};
        float in_[4] = {inA.x, inA.y, inB.x, inB.y};
        float hn[4] = {hnA.x, hnA.y, hnB.x, hnB.y};
        float hv[4] = {h4.x, h4.y, h4.z, h4.w};
        float ov[4];
#pragma unroll
        for (int i = 0; i < 4; i++) {
            float r = 1.f / (1.f + __expf(-(ir[i] + hr[i])));
            float z = 1.f / (1.f + __expf(-(iz[i] + hz[i])));
            float nn = tanhf(in_[i] + r * hn[i]);
            ov[i] = (1.f - z) * nn + z * hv[i];
        }
        float4 o; o.x = ov[0]; o.y = ov[1]; o.z = ov[2]; o.w = ov[3];
        ((float4*)hout)[(size_t)n * 50 + q] = o;
        int k0 = q * 4;
        hp[apack_idx(n, k0    )] = __float2half(ov[0]);
        hp[apack_idx(n, k0 + 1)] = __float2half(ov[1]);
        hp[apack_idx(n, k0 + 2)] = __float2half(ov[2]);
        hp[apack_idx(n, k0 + 3)] = __float2half(ov[3]);
    }
}

// in [G][C] raw -> out [C][G] tf32  (readout)
__global__ void transpose_tf_k(const float* __restrict__ in, float* __restrict__ out,
                               int G, int C) {
    __shared__ float tile[32][33];
    int c0 = blockIdx.x * 32;
    int g0 = blockIdx.y * 32;
    int c = c0 + threadIdx.x;
#pragma unroll
    for (int j = 0; j < 32; j += 8) {
        int g = g0 + threadIdx.y + j;
        tile[threadIdx.y + j][threadIdx.x] = (c < C && g < G) ? in[(size_t)g * C + c] : 0.f;
    }
    __syncthreads();
    int g = g0 + threadIdx.x;
#pragma unroll
    for (int j = 0; j < 32; j += 8) {
        int cc = c0 + threadIdx.y + j;
        if (cc < C && g < G) out[(size_t)cc * G + g] = tfv(tile[threadIdx.x][threadIdx.y + j]);
    }
}

__global__ void pool3_k(const float* __restrict__ in, float* __restrict__ out, int C) {
    int idx = blockIdx.x * blockDim.x + threadIdx.x;
    if (idx < C * GP1) {
        int co = idx / GP1;
        int r = idx % GP1;
        int b = r / P1, p = r % P1;
        int base = co * NTOT + b * NPG + 2 * p;
        float m = fmaxf(fmaxf(in[base], in[base + 1]), in[base + 2]);
        out[idx] = tfv(fmaxf(m, 0.f));
    }
}

__global__ void pool2_k(const float* __restrict__ in, float* __restrict__ out, int C) {
    int idx = blockIdx.x * blockDim.x + threadIdx.x;
    if (idx < C * GP2) {
        int co = idx / GP2;
        int r = idx % GP2;
        int b = r / P2, p = r % P2;
        int base = co * GP1 + b * P1 + 2 * p;
        out[idx] = tfv(fmaxf(fmaxf(in[base], in[base + 1]), 0.f));
    }
}

__global__ void final_k(const float* __restrict__ by, const float* __restrict__ bz,
                        float* __restrict__ out) {
    __shared__ float red[NCLS][128];
    int b = blockIdx.x;
    int tid = threadIdx.x;
    float part[NCLS] = {};
    for (int p = tid; p < P2; p += blockDim.x) {
        int base = b * P2 + p;
#pragma unroll
        for (int cl = 0; cl < NCLS; cl++) {
            float y = d_ly[cl * GP2 + base] + by[cl];
            float z = d_lz[cl * GP2 + base] + bz[cl];
            part[cl] += y * z;
        }
    }
#pragma unroll
    for (int cl = 0; cl < NCLS; cl++) red[cl][tid] = part[cl];
    __syncthreads();
    if (tid == 0) {
        float v[NCLS];
        for (int cl = 0; cl < NCLS; cl++) {
            float s = 0.f;
            for (int i = 0; i < 128; i++) s += red[cl][i];
            v[cl] = s / (float)P2;
        }
        float mx = v[0];
        for (int cl = 1; cl < NCLS; cl++) mx = fmaxf(mx, v[cl]);
        float se = 0.f;
        for (int cl = 0; cl < NCLS; cl++) { v[cl] = __expf(v[cl] - mx); se += v[cl]; }
        for (int cl = 0; cl < NCLS; cl++) out[b * NCLS + cl] = v[cl] / se;
    }
}

// ----------------------------- host side ----------------------------------
static void* getsym(const void* s) {
    void* p = nullptr;
    cudaGetSymbolAddress(&p, s);
    return p;
}

extern "C" void kernel_launch(void* const* d_in, const int* in_sizes, int n_in,
                              void* d_out, int out_size)
{
    const float* features = (const float*)d_in[0];
    const int*   esrc     = (const int*)  d_in[1];
    const int*   edst     = (const int*)  d_in[2];
    const int*   etyp     = (const int*)  d_in[3];
    const float* etype_W  = (const float*)d_in[4];
    const float* etype_b  = (const float*)d_in[5];
    const float* W_ih     = (const float*)d_in[6];
    const float* b_ih     = (const float*)d_in[7];
    const float* W_hh     = (const float*)d_in[8];
    const float* b_hh     = (const float*)d_in[9];
    const float* conv1_w  = (const float*)d_in[10];
    const float* conv1_b  = (const float*)d_in[11];
    const float* conv2_w  = (const float*)d_in[12];
    const float* conv2_b  = (const float*)d_in[13];
    const float* convc1_w = (const float*)d_in[14];
    const float* convc1_b = (const float*)d_in[15];
    const float* convc2_w = (const float*)d_in[16];
    const float* convc2_b = (const float*)d_in[17];
    const float* mlp_y_w  = (const float*)d_in[18];
    const float* mlp_y_b  = (const float*)d_in[19];
    const float* mlp_z_w  = (const float*)d_in[20];
    const float* mlp_z_b  = (const float*)d_in[21];

    float*  p_h0    = (float*) getsym(d_h0);
    float*  p_h1    = (float*) getsym(d_h1);
    __half* p_hp0   = (__half*)getsym(d_hpack0);
    __half* p_hp1   = (__half*)getsym(d_hpack1);
    __half* p_ap    = (__half*)getsym(d_apack);
    __half* p_Hth   = (__half*)getsym(d_Hth);
    __half* p_gih   = (__half*)getsym(d_gih);
    __half* p_ghh   = (__half*)getsym(d_ghh);
    __half* p_Wcomb = (__half*)getsym(d_Wcombp);
    __half* p_Wihp  = (__half*)getsym(d_Wihp);
    int*    p_deg4  = (int*)   getsym(d_deg4);
    float*  p_cTt   = (float*) getsym(d_cTt);
    float*  p_w1yt  = (float*) getsym(d_w1yt);
    float*  p_w1zt  = (float*) getsym(d_w1zt);
    float*  p_w2yt  = (float*) getsym(d_w2yt);
    float*  p_w2zt  = (float*) getsym(d_w2zt);
    float*  p_wmyt  = (float*) getsym(d_wmyt);
    float*  p_wmzt  = (float*) getsym(d_wmzt);
    float*  p_y1    = (float*) getsym(d_y1);
    float*  p_z1    = (float*) getsym(d_z1);
    float*  p_yp1t  = (float*) getsym(d_yp1t);
    float*  p_zp1t  = (float*) getsym(d_zp1t);
    float*  p_y2    = (float*) getsym(d_y2);
    float*  p_z2    = (float*) getsym(d_z2);
    float*  p_yp2t  = (float*) getsym(d_yp2t);
    float*  p_zp2t  = (float*) getsym(d_zp2t);
    float*  p_ly    = (float*) getsym(d_ly);
    float*  p_lz    = (float*) getsym(d_lz);

    const int T = 256;

    // ---- first launches ----
    zero_pack_k<<<(3 * 256 * 2 * 1024 + T - 1) / T, T>>>();                      // 0
    init_h_k<<<(NTOT * ODIM + T - 1) / T, T>>>(features);                        // 1
    packB_comb<<<(12 * KT * 512 + T - 1) / T, T>>>(etype_W, W_hh);               // 2
    launch_fast2(p_hp0, p_Wcomb, p_Hth, 800, nullptr, p_ghh, H3, b_hh, 7, 12);   // 3 (step-0 Ht+gh)

    // ---- rest of setup ----
    packB_k<<<(5 * KT * 512 + T - 1) / T, T>>>(W_ih, p_Wihp, H3, 5);
    zero_int_k<<<(NTOT * 4 + T - 1) / T, T>>>(p_deg4, NTOT * 4);
    hist_k<<<(EDGES + T - 1) / T, T>>>(edst, etyp);
    scan_k<<<1, 1024>>>();
    chunk_hist_k<<<dim3(NCHK, BATCH), 512>>>(edst);
    chunk_scan_k<<<(NTOT + T - 1) / T, T>>>();
    scatter_k<<<dim3(NCHK, BATCH), 512>>>(esrc, edst, etyp);
    pack_conv_tf_k<<<(3 * ODIM * ODIM + T - 1) / T, T>>>(conv1_w, p_w1yt, ODIM);
    pack_conv_tf_k<<<(3 * CDIM * CDIM + T - 1) / T, T>>>(convc1_w, p_w1zt, CDIM);
    split_tf_k<<<(ODIM * ODIM + T - 1) / T, T>>>(conv2_w, p_w2yt, ODIM * ODIM);
    split_tf_k<<<(CDIM * CDIM + T - 1) / T, T>>>(convc2_w, p_w2zt, CDIM * CDIM);
    split_tf_k<<<(NCLS * ODIM + T - 1) / T, T>>>(mlp_y_w, p_wmyt, NCLS * ODIM);
    split_tf_k<<<(NCLS * CDIM + T - 1) / T, T>>>(mlp_z_w, p_wmzt, NCLS * CDIM);
    nodebias_k<<<(NTOT * ODIM + T - 1) / T, T>>>(etype_b);

    // ---- GGNN: 8 steps ----
    for (int s = 0; s < 8; s++) {
        const float*  hin  = (s & 1) ? p_h1 : p_h0;
        float*        hout = (s & 1) ? p_h0 : p_h1;
        const __half* hpin = (s & 1) ? p_hp1 : p_hp0;
        __half*       hpout= (s & 1) ? p_hp0 : p_hp1;
        if (s > 0)
            launch_fast2(hpin, p_Wcomb, p_Hth, 800, nullptr, p_ghh, H3, b_hh, 7, 12);
        spmm_k<<<NTOT / 4, 128>>>(p_Hth);
        launch_fast2(p_ap, p_Wihp, p_gih, H3, b_ih, nullptr, 0, nullptr, 5, 5);
        gates_k<<<(NTOT * 50 + T - 1) / T, T>>>(hin, hout, hpout);
    }
    float* p_hf = p_h0;

    // ---- readout ----
    transpose_tf_k<<<dim3((ODIM + 31) / 32, NTOT / 32), dim3(32, 8)>>>(p_hf, p_cTt, NTOT, ODIM);
    transpose_tf_k<<<dim3((IDIM + 31) / 32, NTOT / 32), dim3(32, 8)>>>(features, p_cTt + (size_t)ODIM * NTOT, NTOT, IDIM);

    launch_gemm<3,3>(p_w1yt, p_cTt, p_y1, conv1_b, ODIM, NTOT, ODIM, ODIM, NTOT, NTOT, ODIM * ODIM);
    pool3_k<<<(ODIM * GP1 + T - 1) / T, T>>>(p_y1, p_yp1t, ODIM);
    launch_gemm<3,1>(p_w2yt, p_yp1t, p_y2, conv2_b, ODIM, GP1, ODIM, ODIM, GP1, GP1, 0);
    pool2_k<<<(ODIM * GP2 + T - 1) / T, T>>>(p_y2, p_yp2t, ODIM);

    launch_gemm<3,3>(p_w1zt, p_cTt, p_z1, convc1_b, CDIM, NTOT, CDIM, CDIM, NTOT, NTOT, CDIM * CDIM);
    pool3_k<<<(CDIM * GP1 + T - 1) / T, T>>>(p_z1, p_zp1t, CDIM);
    launch_gemm<3,1>(p_w2zt, p_zp1t, p_z2, convc2_b, CDIM, GP1, CDIM, CDIM, GP1, GP1, 0);
    pool2_k<<<(CDIM * GP2 + T - 1) / T, T>>>(p_z2, p_zp2t, CDIM);

    launch_gemm<0,1>(p_wmyt, p_yp2t, p_ly, nullptr, NCLS, GP2, ODIM, ODIM, GP2, GP2, 0);
    launch_gemm<0,1>(p_wmzt, p_zp2t, p_lz, nullptr, NCLS, GP2, CDIM, CDIM, GP2, GP2, 0);

    final_k<<<BATCH, 128>>>(mlp_y_b, mlp_z_b, (float*)d_out);
}

// round 17
// speedup vs baseline: 3.6260x; 1.1095x over previous
#include <cuda_runtime.h>
#include <cuda_fp16.h>

#define BATCH  64
#define NPG    512
#define NTOT   32768
#define EDGES  524288
#define EPG    8192
#define NCHK   16
#define ODIM   200
#define IDIM   100
#define H3     600
#define CDIM   300
#define P1     254
#define P2     127
#define GP1    16256
#define GP2    8128
#define NCLS   7
#define KT     14                        /* GGNN padded K 224 / 16 */
#define KHALF  7
#define HPACK_HALFS (256*KT*2048)
#define KTY    13                        /* readout K=200 pad 208 */
#define KTZ    19                        /* readout K=300 pad 304 */
#define NBPT   (NTOT+8)
#define NBP2   8192

// ----------------------------- device scratch -----------------------------
__device__ float  d_h0[NTOT*ODIM];
__device__ float  d_h1[NTOT*ODIM];
__device__ __half d_hpack0[HPACK_HALFS];
__device__ __half d_hpack1[HPACK_HALFS];
__device__ __half d_apack[HPACK_HALFS];
__device__ __half d_Hth[NTOT*4*ODIM];
__device__ __half d_gih[NTOT*H3];
__device__ __half d_ghh[NTOT*H3];
__device__ __half d_Wcombp[12*KT*2048];
__device__ __half d_Wihp[5*KT*2048];
__device__ float  d_nbias[NTOT*ODIM];
__device__ int    d_deg4[NTOT*4];
__device__ int    d_indptr[NTOT+1];
__device__ int    d_ccnt[NTOT*NCHK];
__device__ int    d_srcs[EDGES];
__device__ int    d_typs[EDGES];
// readout (fp16 fragment-packed)
__device__ __half d_cTp[KTZ*NBPT*16];
__device__ __half d_w1yp[3*2*KTY*2048];
__device__ __half d_w1zp[3*3*KTZ*2048];
__device__ __half d_w2yp[2*KTY*2048];
__device__ __half d_w2zp[3*KTZ*2048];
__device__ __half d_wmyp[KTY*2048];
__device__ __half d_wmzp[KTZ*2048];
__device__ __half d_y1h[200*NTOT];
__device__ __half d_z1h[300*NTOT];
__device__ __half d_y2h[200*GP1];
__device__ __half d_z2h[300*GP1];
__device__ __half d_yp1p[KTY*GP1*16];
__device__ __half d_zp1p[KTZ*GP1*16];
__device__ __half d_yp2p[KTY*NBP2*16];
__device__ __half d_zp2p[KTZ*NBP2*16];
__device__ float  d_ly[NCLS*GP2];
__device__ float  d_lz[NCLS*GP2];

// ----------------------------- helpers ------------------------------------
// half index of A-fragment element (m, k), nkt ktiles
__device__ __forceinline__ int apg(int m, int k, int nkt) {
    int rt = m >> 7, row = m & 127, mb = row >> 4, fr = row & 15;
    int g = fr & 7, hr = fr >> 3;
    int kt = k >> 4, kk = k & 15, hk = kk >> 3, tig = (kk & 7) >> 1, par = kk & 1;
    int lane = g * 4 + tig;
    return (((rt * nkt + kt) * 256 + mb * 32 + lane) << 3) + hk * 4 + hr * 2 + par;
}
__device__ __forceinline__ int apack_idx(int n, int k) { return apg(n, k, KT); }
// half index of global-column B-fragment element (k, g), column space nbp
__device__ __forceinline__ int bidx(int k, int g, int nbp) {
    int kt = k >> 4, kk = k & 15;
    int tig = (kk & 7) >> 1, hk = kk >> 3, par = kk & 1;
    return ((kt * nbp + g) * 4 + tig) * 4 + hk * 2 + par;
}

// ----------------------------- setup kernels ------------------------------
__global__ void zero_int_k(int* p, int n) {
    int i = blockIdx.x * blockDim.x + threadIdx.x;
    if (i < n) p[i] = 0;
}

__global__ void zero_pack_k() {
    int i = blockIdx.x * blockDim.x + threadIdx.x;
    const int per = 256 * 2 * 1024;
    if (i < 3 * per) {
        int b = i / per, r = i % per;
        int rt = r / (2 * 1024), rem = r % (2 * 1024);
        int kt = 12 + rem / 1024, off = rem % 1024;
        __half* p = (b == 0) ? d_hpack0 : (b == 1) ? d_hpack1 : d_apack;
        ((unsigned*)p)[(rt * KT + kt) * 1024 + off] = 0u;
    }
}

__global__ void hist_k(const int* __restrict__ edst, const int* __restrict__ etyp) {
    int e = blockIdx.x * blockDim.x + threadIdx.x;
    if (e < EDGES) atomicAdd(&d_deg4[edst[e] * 4 + etyp[e]], 1);
}

__global__ void scan_k() {
    __shared__ int ssum[1024];
    int t = threadIdx.x;
    int loc[32];
    int s = 0;
#pragma unroll
    for (int i = 0; i < 32; i++) {
        int n = t * 32 + i;
        int d = d_deg4[n*4] + d_deg4[n*4+1] + d_deg4[n*4+2] + d_deg4[n*4+3];
        loc[i] = s; s += d;
    }
    ssum[t] = s;
    __syncthreads();
    if (t == 0) {
        int acc = 0;
        for (int i = 0; i < 1024; i++) { int v = ssum[i]; ssum[i] = acc; acc += v; }
        d_indptr[NTOT] = acc;
    }
    __syncthreads();
    int off = ssum[t];
#pragma unroll
    for (int i = 0; i < 32; i++) d_indptr[t * 32 + i] = off + loc[i];
}

__global__ void chunk_hist_k(const int* __restrict__ edst) {
    __shared__ int h[NPG];
    int g = blockIdx.y, c = blockIdx.x;
    h[threadIdx.x] = 0;
    __syncthreads();
    int e = g * EPG + c * 512 + threadIdx.x;
    atomicAdd(&h[edst[e] - g * NPG], 1);
    __syncthreads();
    d_ccnt[(g * NPG + threadIdx.x) * NCHK + c] = h[threadIdx.x];
}

__global__ void chunk_scan_k() {
    int n = blockIdx.x * blockDim.x + threadIdx.x;
    if (n < NTOT) {
        int base = d_indptr[n];
#pragma unroll
        for (int c = 0; c < NCHK; c++) {
            int v = d_ccnt[n * NCHK + c];
            d_ccnt[n * NCHK + c] = base;
            base += v;
        }
    }
}

__global__ void scatter_k(const int* __restrict__ esrc, const int* __restrict__ edst,
                          const int* __restrict__ etyp) {
    __shared__ int sd[512];
    int g = blockIdx.y, c = blockIdx.x;
    int e = g * EPG + c * 512 + threadIdx.x;
    int dl = edst[e] - g * NPG;
    sd[threadIdx.x] = dl;
    __syncthreads();
    int rank = 0;
    for (int i = 0; i < threadIdx.x; i++) rank += (sd[i] == dl);
    int pos = d_ccnt[(g * NPG + dl) * NCHK + c] + rank;
    d_srcs[pos] = esrc[e];
    d_typs[pos] = etyp[e];
}

// combined GGNN B pack
__global__ void packB_comb(const float* __restrict__ Wst, const float* __restrict__ Whh) {
    int t = blockIdx.x * blockDim.x + threadIdx.x;
    if (t >= 12 * KT * 512) return;
    int tig = t & 3;
    int c   = (t >> 2) & 127;
    int kt  = (t >> 9) % KT;
    int ct  = t / (KT * 512);
    const float* W; int Nreal, cg;
    if (ct < 7) { W = Wst; Nreal = 800; cg = ct * 128 + c; }
    else        { W = Whh; Nreal = 600; cg = (ct - 7) * 128 + c; }
    float v0 = 0.f, v1 = 0.f, v2 = 0.f, v3 = 0.f;
    if (cg < Nreal) {
        int k0 = kt * 16 + 2 * tig;
        v0 = (k0     < 200) ? W[cg * 200 + k0    ] : 0.f;
        v1 = (k0 + 1 < 200) ? W[cg * 200 + k0 + 1] : 0.f;
        v2 = (k0 + 8 < 200) ? W[cg * 200 + k0 + 8] : 0.f;
        v3 = (k0 + 9 < 200) ? W[cg * 200 + k0 + 9] : 0.f;
    }
    int vi = (ct * KT + kt) * 512 + c * 4 + tig;
    __half2* o2 = (__half2*)d_Wcombp;
    o2[vi * 2]     = __floats2half2_rn(v0, v1);
    o2[vi * 2 + 1] = __floats2half2_rn(v2, v3);
}

__global__ void packB_k(const float* __restrict__ W, __half* __restrict__ out,
                        int Nreal, int nct) {
    int t = blockIdx.x * blockDim.x + threadIdx.x;
    if (t >= nct * KT * 512) return;
    int tig = t & 3;
    int c   = (t >> 2) & 127;
    int kt  = (t >> 9) % KT;
    int ct  = t / (KT * 512);
    int cg  = ct * 128 + c;
    float v0 = 0.f, v1 = 0.f, v2 = 0.f, v3 = 0.f;
    if (cg < Nreal) {
        int k0 = kt * 16 + 2 * tig;
        v0 = (k0     < 200) ? W[cg * 200 + k0    ] : 0.f;
        v1 = (k0 + 1 < 200) ? W[cg * 200 + k0 + 1] : 0.f;
        v2 = (k0 + 8 < 200) ? W[cg * 200 + k0 + 8] : 0.f;
        v3 = (k0 + 9 < 200) ? W[cg * 200 + k0 + 9] : 0.f;
    }
    int vi = (ct * KT + kt) * 512 + c * 4 + tig;
    __half2* o2 = (__half2*)out;
    o2[vi * 2]     = __floats2half2_rn(v0, v1);
    o2[vi * 2 + 1] = __floats2half2_rn(v2, v3);
}

// conv1 weight [co][ci][3] -> per-shift A-fragment pack (zeros beyond C)
__global__ void packA_c1(const float* __restrict__ W, __half* __restrict__ out,
                         int C, int nkt, int nrt) {
    int per = nrt * 128 * nkt * 16;
    int i = blockIdx.x * blockDim.x + threadIdx.x;
    if (i >= 3 * per) return;
    int s = i / per, r = i % per;
    int m = r / (nkt * 16), k = r % (nkt * 16);
    float v = (m < C && k < C) ? W[(m * C + k) * 3 + s] : 0.f;
    out[(size_t)s * per + apg(m, k, nkt)] = __float2half(v);
}

// dense weight [Mreal][K] -> A-fragment pack
__global__ void packA_m(const float* __restrict__ W, __half* __restrict__ out,
                        int Mreal, int K, int nkt, int nrt) {
    int i = blockIdx.x * blockDim.x + threadIdx.x;
    if (i >= nrt * 128 * nkt * 16) return;
    int m = i / (nkt * 16), k = i % (nkt * 16);
    float v = (m < Mreal && k < K) ? W[m * K + k] : 0.f;
    out[apg(m, k, nkt)] = __float2half(v);
}

// cT = [h ; features] packed into global-column B fragments (304 k-rows, NBPT cols)
__global__ void pack_cT(const float* __restrict__ hf, const float* __restrict__ feat) {
    int i = blockIdx.x * blockDim.x + threadIdx.x;
    if (i >= KTZ * NBPT * 4) return;
    int tig = i & 3, g = (i >> 2) % NBPT, kt = i / (NBPT * 4);
    int k0 = kt * 16 + 2 * tig;
    int ks[4] = {k0, k0 + 1, k0 + 8, k0 + 9};
    float v[4];
#pragma unroll
    for (int j = 0; j < 4; j++) {
        float x = 0.f;
        if (g < NTOT && ks[j] < 300)
            x = (ks[j] < 200) ? hf[(size_t)g * ODIM + ks[j]]
                              : feat[(size_t)g * IDIM + ks[j] - 200];
        v[j] = x;
    }
    __half2* o = (__half2*)d_cTp;
    int vi = (kt * NBPT + g) * 4 + tig;
    o[vi * 2]     = __floats2half2_rn(v[0], v[1]);
    o[vi * 2 + 1] = __floats2half2_rn(v[2], v[3]);
}

__global__ void init_h_k(const float* __restrict__ feat) {
    int idx = blockIdx.x * blockDim.x + threadIdx.x;
    if (idx < NTOT * ODIM) {
        int d = idx % ODIM;
        int n = idx / ODIM;
        float v = (d < IDIM) ? feat[n * IDIM + d] : 0.f;
        d_h0[idx] = v;
        d_hpack0[apack_idx(n, d)] = __float2half(v);
    }
}

__global__ void nodebias_k(const float* __restrict__ eb) {
    int idx = blockIdx.x * blockDim.x + threadIdx.x;
    if (idx < NTOT * ODIM) {
        int o = idx % ODIM;
        int n = idx / ODIM;
        float s = 0.f;
#pragma unroll
        for (int t = 0; t < 4; t++) s += (float)d_deg4[n * 4 + t] * eb[t * ODIM + o];
        d_nbias[idx] = s;
    }
}

// warp-per-node SPMM
__global__ void spmm_k(const __half* __restrict__ Ht) {
    int warp = threadIdx.x >> 5, lane = threadIdx.x & 31;
    int n = blockIdx.x * 4 + warp;
    int beg = d_indptr[n], end = d_indptr[n + 1];
    float ax[4] = {}, ay[4] = {};
    for (int base = beg; base < end; base += 32) {
        int cnt = min(32, end - base);
        int off = 0;
        if (lane < cnt) off = d_srcs[base + lane] * 800 + d_typs[base + lane] * ODIM;
        for (int e = 0; e < cnt; e++) {
            int o = __shfl_sync(0xffffffffu, off, e);
#pragma unroll
            for (int q = 0; q < 4; q++) {
                int c = lane + q * 32;
                if (q < 3 || lane < 4) {
                    float2 f = __half22float2(*(const __half2*)&Ht[o + 2 * c]);
                    ax[q] += f.x; ay[q] += f.y;
                }
            }
        }
    }
#pragma unroll
    for (int q = 0; q < 4; q++) {
        int c = lane + q * 32;
        if (q < 3 || lane < 4) {
            int o = n * ODIM + 2 * c;
            *(__half2*)&d_apack[apack_idx(n, 2 * c)] =
                __floats2half2_rn(ax[q] + d_nbias[o], ay[q] + d_nbias[o + 1]);
        }
    }
}

// ----------------------------- MMA helpers --------------------------------
__device__ __forceinline__ void mma_f16(float* d, const unsigned* a, const unsigned* b) {
    asm volatile(
        "mma.sync.aligned.m16n8k16.row.col.f32.f16.f16.f32 "
        "{%0,%1,%2,%3}, {%4,%5,%6,%7}, {%8,%9}, {%0,%1,%2,%3};"
        : "+f"(d[0]), "+f"(d[1]), "+f"(d[2]), "+f"(d[3])
        : "r"(a[0]), "r"(a[1]), "r"(a[2]), "r"(a[3]), "r"(b[0]), "r"(b[1]));
}
__device__ __forceinline__ void cpa16u(void* dst, const void* src) {
    unsigned sa = (unsigned)__cvta_generic_to_shared(dst);
    asm volatile("cp.async.cg.shared.global [%0], [%1], 16;" :: "r"(sa), "l"(src));
}

// --------------------- fast GEMM (GGNN loop) -------------------------------
#define SMEM_FAST (3 * 1024 * 16)

__global__ __launch_bounds__(256, 2) void gemm_fast2(
    const __half* __restrict__ Ap, const __half* __restrict__ Bp,
    __half* __restrict__ C1, int N1, const float* __restrict__ bias1,
    __half* __restrict__ C2, int N2, const float* __restrict__ bias2,
    int splitCt)
{
    extern __shared__ float sm[];
    uint4* smv = (uint4*)sm;
    const int tid  = threadIdx.x;
    const int lane = tid & 31;
    const int w    = tid >> 5;
    const int wm   = w & 3;
    const int wn   = w >> 2;
    const int rt   = blockIdx.y * KT;
    const int ct   = blockIdx.x * KT;
    const int row0 = blockIdx.y * 128;

    float acc[2][8][4] = {};

    int aoff[2];
#pragma unroll
    for (int mt = 0; mt < 2; mt++) aoff[mt] = (wm * 2 + mt) * 32 + lane;
    int cb[8];
#pragma unroll
    for (int nt = 0; nt < 8; nt++)
        cb[nt] = (wn * 64 + nt * 8 + (lane >> 2)) * 4 + (lane & 3);

    auto stage = [&](int it, int b) {
        uint4* d = smv + b * 1024;
        const uint4* sa = (const uint4*)Ap + (size_t)(rt + 2 * it) * 256;
        cpa16u(&d[tid],       &sa[tid]);
        cpa16u(&d[tid + 256], &sa[tid + 256]);
        uint4* db = d + 512;
        const uint4* sb = (const uint4*)Bp + (size_t)(ct + 2 * it) * 256;
        cpa16u(&db[tid],       &sb[tid]);
        cpa16u(&db[tid + 256], &sb[tid + 256]);
        asm volatile("cp.async.commit_group;");
    };

    stage(0, 0);
    stage(1, 1);

#pragma unroll 1
    for (int it = 0; it < KHALF; it++) {
        if (it < KHALF - 1) asm volatile("cp.async.wait_group 1;");
        else                asm volatile("cp.async.wait_group 0;");
        __syncthreads();
        if (it + 2 < KHALF) stage(it + 2, (it + 2) % 3);

        const uint4* base = smv + (it % 3) * 1024;
#pragma unroll
        for (int sub = 0; sub < 2; sub++) {
            const uint4* Ab = base + sub * 256;
            const uint2* Bb = (const uint2*)(base + 512) + sub * 512;

            unsigned ah[2][4];
#pragma unroll
            for (int mt = 0; mt < 2; mt++) {
                uint4 v = Ab[aoff[mt]];
                ah[mt][0] = v.x; ah[mt][1] = v.y; ah[mt][2] = v.z; ah[mt][3] = v.w;
            }
#pragma unroll
            for (int nt = 0; nt < 8; nt++) {
                uint2 bv = Bb[cb[nt]];
                unsigned bb[2] = {bv.x, bv.y};
#pragma unroll
                for (int mt = 0; mt < 2; mt++)
                    mma_f16(acc[mt][nt], ah[mt], bb);
            }
        }
    }

    const bool first = (int)blockIdx.x < splitCt;
    __half* C = first ? C1 : C2;
    const int Nreal = first ? N1 : N2;
    const float* bias = first ? bias1 : bias2;
    const int colb = (first ? blockIdx.x : blockIdx.x - splitCt) * 128;

    const int gid = lane >> 2, tig = lane & 3;
#pragma unroll
    for (int mt = 0; mt < 2; mt++) {
#pragma unroll
        for (int half_ = 0; half_ < 2; half_++) {
            int r = row0 + wm * 32 + mt * 16 + half_ * 8 + gid;
#pragma unroll
            for (int nt = 0; nt < 8; nt++) {
                int c = colb + wn * 64 + nt * 8 + tig * 2;
                if (c >= Nreal) continue;
                float v0 = acc[mt][nt][half_ * 2 + 0];
                float v1 = acc[mt][nt][half_ * 2 + 1];
                if (bias) { v0 += bias[c]; v1 += bias[c + 1]; }
                *(__half2*)(C + (size_t)r * Nreal + c) = __floats2half2_rn(v0, v1);
            }
        }
    }
}

static void launch_fast2(const __half* Ap, const __half* Bp,
                         __half* C1, int N1, const float* bias1,
                         __half* C2, int N2, const float* bias2,
                         int splitCt, int totalCt)
{
    cudaFuncSetAttribute(gemm_fast2, cudaFuncAttributeMaxDynamicSharedMemorySize, SMEM_FAST);
    gemm_fast2<<<dim3(totalCt, 256), 256, SMEM_FAST>>>(Ap, Bp, C1, N1, bias1, C2, N2, bias2, splitCt);
}

// --------------------- readout GEMM: fp16, global-col B, shift support -----
// C[M,N] = sum_s A_s * B(cols+s). A fragment-packed per split; B global-packed.
// OUTH: 1 = fp16 C, 0 = fp32 C. RBIAS: 1 = bias[row].
#define SMEM_FR (3 * 512 * 16)

template<int OUTH, int RBIAS>
__global__ __launch_bounds__(256, 2) void gemm_fr(
    const __half* __restrict__ Ap, const __half* __restrict__ Bp,
    void* __restrict__ Cv, const float* __restrict__ bias,
    int M, int Nreal, int NBP, int nkt, int nsplit, int aStepH)
{
    extern __shared__ float sm[];
    uint4* smv = (uint4*)sm;
    const int tid  = threadIdx.x;
    const int lane = tid & 31;
    const int w    = tid >> 5;
    const int wm   = w & 3;
    const int wn   = w >> 2;
    const int row0 = blockIdx.y * 128;
    const int colb = blockIdx.x * 128;
    const int total = nkt * nsplit;

    float acc[2][8][4] = {};

    int aoff[2];
#pragma unroll
    for (int mt = 0; mt < 2; mt++) aoff[mt] = (wm * 2 + mt) * 32 + lane;
    int cb[8];
#pragma unroll
    for (int nt = 0; nt < 8; nt++)
        cb[nt] = (wn * 64 + nt * 8 + (lane >> 2)) * 4 + (lane & 3);

    auto stage = [&](int t, int b) {
        int s = t / nkt, kt = t % nkt;
        uint4* d = smv + b * 512;
        const uint4* sa = (const uint4*)(Ap + (size_t)s * aStepH)
                          + (size_t)(blockIdx.y * nkt + kt) * 256;
        cpa16u(&d[tid], &sa[tid]);
        uint4* db = d + 256;
        const uint4* sb = (const uint4*)Bp + ((size_t)kt * NBP + colb + s) * 2;
        cpa16u(&db[tid], &sb[tid]);
        asm volatile("cp.async.commit_group;");
    };

    stage(0, 0);
    if (total > 1) stage(1, 1);

#pragma unroll 1
    for (int t = 0; t < total; t++) {
        if (t < total - 1) asm volatile("cp.async.wait_group 1;");
        else               asm volatile("cp.async.wait_group 0;");
        __syncthreads();
        if (t + 2 < total) stage(t + 2, (t + 2) % 3);

        const uint4* Ab = smv + (t % 3) * 512;
        const uint2* Bb = (const uint2*)(Ab + 256);

        unsigned ah[2][4];
#pragma unroll
        for (int mt = 0; mt < 2; mt++) {
            uint4 v = Ab[aoff[mt]];
            ah[mt][0] = v.x; ah[mt][1] = v.y; ah[mt][2] = v.z; ah[mt][3] = v.w;
        }
#pragma unroll
        for (int nt = 0; nt < 8; nt++) {
            uint2 bv = Bb[cb[nt]];
            unsigned bb[2] = {bv.x, bv.y};
#pragma unroll
            for (int mt = 0; mt < 2; mt++)
                mma_f16(acc[mt][nt], ah[mt], bb);
        }
    }

    const int gid = lane >> 2, tig = lane & 3;
#pragma unroll
    for (int mt = 0; mt < 2; mt++) {
#pragma unroll
        for (int half_ = 0; half_ < 2; half_++) {
            int r = row0 + wm * 32 + mt * 16 + half_ * 8 + gid;
            if (r >= M) continue;
            float rb = RBIAS ? bias[r] : 0.f;
#pragma unroll
            for (int nt = 0; nt < 8; nt++) {
                int c = colb + wn * 64 + nt * 8 + tig * 2;
                if (c >= Nreal) continue;
                float v0 = acc[mt][nt][half_ * 2 + 0] + rb;
                float v1 = acc[mt][nt][half_ * 2 + 1] + rb;
                if (OUTH)
                    *(__half2*)((__half*)Cv + (size_t)r * Nreal + c) = __floats2half2_rn(v0, v1);
                else {
                    float2 o; o.x = v0; o.y = v1;
                    *(float2*)((float*)Cv + (size_t)r * Nreal + c) = o;
                }
            }
        }
    }
}

template<int OUTH, int RBIAS>
static void launch_fr(const __half* Ap, const __half* Bp, void* C, const float* bias,
                      int M, int Nreal, int NBP, int nkt, int nsplit, int aStepH,
                      int ctiles, int rtiles)
{
    cudaFuncSetAttribute(gemm_fr<OUTH, RBIAS>,
                         cudaFuncAttributeMaxDynamicSharedMemorySize, SMEM_FR);
    gemm_fr<OUTH, RBIAS><<<dim3(ctiles, rtiles), 256, SMEM_FR>>>(
        Ap, Bp, C, bias, M, Nreal, NBP, nkt, nsplit, aStepH);
}

// GRU gates: half gi/gh inputs; raw + fp16 fragment-packed h out
__global__ void gates_k(const float* __restrict__ hin, float* __restrict__ hout,
                        __half* __restrict__ hp) {
    int idx = blockIdx.x * blockDim.x + threadIdx.x;
    if (idx < NTOT * 50) {
        int n = idx / 50, q = idx % 50;
        const __half2* gi2 = (const __half2*)d_gih;
        const __half2* gh2 = (const __half2*)d_ghh;
        size_t b2 = (size_t)n * 300 + q * 2;
        float2 irA = __half22float2(gi2[b2      ]), irB = __half22float2(gi2[b2 + 1  ]);
        float2 hrA = __half22float2(gh2[b2      ]), hrB = __half22float2(gh2[b2 + 1  ]);
        float2 izA = __half22float2(gi2[b2 + 100]), izB = __half22float2(gi2[b2 + 101]);
        float2 hzA = __half22float2(gh2[b2 + 100]), hzB = __half22float2(gh2[b2 + 101]);
        float2 inA = __half22float2(gi2[b2 + 200]), inB = __half22float2(gi2[b2 + 201]);
        float2 hnA = __half22float2(gh2[b2 + 200]), hnB = __half22float2(gh2[b2 + 201]);
        float4 h4  = ((const float4*)hin)[(size_t)n * 50 + q];
        float ir[4] = {irA.x, irA.y, irB.x, irB.y};
        float hr[4] = {hrA.x, hrA.y, hrB.x, hrB.y};
        float iz[4] = {izA.x, izA.y, izB.x, izB.y};
        float hz[4] = {hzA.x, hzA.y, hzB.x, hzB.y};
        float in_[4] = {inA.x, inA.y, inB.x, inB.y};
        float hn[4] = {hnA.x, hnA.y, hnB.x, hnB.y};
        float hv[4] = {h4.x, h4.y, h4.z, h4.w};
        float ov[4];
#pragma unroll
        for (int i = 0; i < 4; i++) {
            float r = 1.f / (1.f + __expf(-(ir[i] + hr[i])));
            float z = 1.f / (1.f + __expf(-(iz[i] + hz[i])));
            float nn = tanhf(in_[i] + r * hn[i]);
            ov[i] = (1.f - z) * nn + z * hv[i];
        }
        float4 o; o.x = ov[0]; o.y = ov[1]; o.z = ov[2]; o.w = ov[3];
        ((float4*)hout)[(size_t)n * 50 + q] = o;
        int k0 = q * 4;
        hp[apack_idx(n, k0    )] = __float2half(ov[0]);
        hp[apack_idx(n, k0 + 1)] = __float2half(ov[1]);
        hp[apack_idx(n, k0 + 2)] = __float2half(ov[2]);
        hp[apack_idx(n, k0 + 3)] = __float2half(ov[3]);
    }
}

// relu+maxpool3 s2, fp16 in -> packed fp16 out (NBP = GP1)
__global__ void pool3h_k(const __half* __restrict__ in, __half* __restrict__ out,
                         int C, int nkt) {
    int i = blockIdx.x * blockDim.x + threadIdx.x;
    if (i >= nkt * GP1 * 4) return;
    int tig = i & 3, g = (i >> 2) % GP1, kt = i / (GP1 * 4);
    int b = g / P1, p = g % P1;
    int base = b * NPG + 2 * p;
    int k0 = kt * 16 + 2 * tig;
    int ks[4] = {k0, k0 + 1, k0 + 8, k0 + 9};
    float v[4];
#pragma unroll
    for (int j = 0; j < 4; j++) {
        float x = 0.f;
        if (ks[j] < C) {
            const __half* r = in + (size_t)ks[j] * NTOT + base;
            float m = fmaxf(fmaxf(__half2float(r[0]), __half2float(r[1])), __half2float(r[2]));
            x = fmaxf(m, 0.f);
        }
        v[j] = x;
    }
    __half2* o = (__half2*)out;
    int vi = (kt * GP1 + g) * 4 + tig;
    o[vi * 2]     = __floats2half2_rn(v[0], v[1]);
    o[vi * 2 + 1] = __floats2half2_rn(v[2], v[3]);
}

// relu+maxpool2 s2, fp16 in -> packed fp16 out (NBP = NBP2, zero pad cols)
__global__ void pool2h_k(const __half* __restrict__ in, __half* __restrict__ out,
                         int C, int nkt) {
    int i = blockIdx.x * blockDim.x + threadIdx.x;
    if (i >= nkt * NBP2 * 4) return;
    int tig = i & 3, g = (i >> 2) % NBP2, kt = i / (NBP2 * 4);
    int k0 = kt * 16 + 2 * tig;
    int ks[4] = {k0, k0 + 1, k0 + 8, k0 + 9};
    float v[4];
#pragma unroll
    for (int j = 0; j < 4; j++) {
        float x = 0.f;
        if (g < GP2 && ks[j] < C) {
            int b = g / P2, p = g % P2;
            const __half* r = in + (size_t)ks[j] * GP1 + b * P1 + 2 * p;
            x = fmaxf(fmaxf(__half2float(r[0]), __half2float(r[1])), 0.f);
        }
        v[j] = x;
    }
    __half2* o = (__half2*)out;
    int vi = (kt * NBP2 + g) * 4 + tig;
    o[vi * 2]     = __floats2half2_rn(v[0], v[1]);
    o[vi * 2 + 1] = __floats2half2_rn(v[2], v[3]);
}

__global__ void final_k(const float* __restrict__ by, const float* __restrict__ bz,
                        float* __restrict__ out) {
    __shared__ float red[NCLS][128];
    int b = blockIdx.x;
    int tid = threadIdx.x;
    float part[NCLS] = {};
    for (int p = tid; p < P2; p += blockDim.x) {
        int base = b * P2 + p;
#pragma unroll
        for (int cl = 0; cl < NCLS; cl++) {
            float y = d_ly[cl * GP2 + base] + by[cl];
            float z = d_lz[cl * GP2 + base] + bz[cl];
            part[cl] += y * z;
        }
    }
#pragma unroll
    for (int cl = 0; cl < NCLS; cl++) red[cl][tid] = part[cl];
    __syncthreads();
    if (tid == 0) {
        float v[NCLS];
        for (int cl = 0; cl < NCLS; cl++) {
            float s = 0.f;
            for (int i = 0; i < 128; i++) s += red[cl][i];
            v[cl] = s / (float)P2;
        }
        float mx = v[0];
        for (int cl = 1; cl < NCLS; cl++) mx = fmaxf(mx, v[cl]);
        float se = 0.f;
        for (int cl = 0; cl < NCLS; cl++) { v[cl] = __expf(v[cl] - mx); se += v[cl]; }
        for (int cl = 0; cl < NCLS; cl++) out[b * NCLS + cl] = v[cl] / se;
    }
}

// ----------------------------- host side ----------------------------------
static void* getsym(const void* s) {
    void* p = nullptr;
    cudaGetSymbolAddress(&p, s);
    return p;
}

extern "C" void kernel_launch(void* const* d_in, const int* in_sizes, int n_in,
                              void* d_out, int out_size)
{
    const float* features = (const float*)d_in[0];
    const int*   esrc     = (const int*)  d_in[1];
    const int*   edst     = (const int*)  d_in[2];
    const int*   etyp     = (const int*)  d_in[3];
    const float* etype_W  = (const float*)d_in[4];
    const float* etype_b  = (const float*)d_in[5];
    const float* W_ih     = (const float*)d_in[6];
    const float* b_ih     = (const float*)d_in[7];
    const float* W_hh     = (const float*)d_in[8];
    const float* b_hh     = (const float*)d_in[9];
    const float* conv1_w  = (const float*)d_in[10];
    const float* conv1_b  = (const float*)d_in[11];
    const float* conv2_w  = (const float*)d_in[12];
    const float* conv2_b  = (const float*)d_in[13];
    const float* convc1_w = (const float*)d_in[14];
    const float* convc1_b = (const float*)d_in[15];
    const float* convc2_w = (const float*)d_in[16];
    const float* convc2_b = (const float*)d_in[17];
    const float* mlp_y_w  = (const float*)d_in[18];
    const float* mlp_y_b  = (const float*)d_in[19];
    const float* mlp_z_w  = (const float*)d_in[20];
    const float* mlp_z_b  = (const float*)d_in[21];

    float*  p_h0    = (float*) getsym(d_h0);
    float*  p_h1    = (float*) getsym(d_h1);
    __half* p_hp0   = (__half*)getsym(d_hpack0);
    __half* p_hp1   = (__half*)getsym(d_hpack1);
    __half* p_ap    = (__half*)getsym(d_apack);
    __half* p_Hth   = (__half*)getsym(d_Hth);
    __half* p_gih   = (__half*)getsym(d_gih);
    __half* p_ghh   = (__half*)getsym(d_ghh);
    __half* p_Wcomb = (__half*)getsym(d_Wcombp);
    __half* p_Wihp  = (__half*)getsym(d_Wihp);
    int*    p_deg4  = (int*)   getsym(d_deg4);
    __half* p_cTp   = (__half*)getsym(d_cTp);
    __half* p_w1yp  = (__half*)getsym(d_w1yp);
    __half* p_w1zp  = (__half*)getsym(d_w1zp);
    __half* p_w2yp  = (__half*)getsym(d_w2yp);
    __half* p_w2zp  = (__half*)getsym(d_w2zp);
    __half* p_wmyp  = (__half*)getsym(d_wmyp);
    __half* p_wmzp  = (__half*)getsym(d_wmzp);
    __half* p_y1h   = (__half*)getsym(d_y1h);
    __half* p_z1h   = (__half*)getsym(d_z1h);
    __half* p_y2h   = (__half*)getsym(d_y2h);
    __half* p_z2h   = (__half*)getsym(d_z2h);
    __half* p_yp1p  = (__half*)getsym(d_yp1p);
    __half* p_zp1p  = (__half*)getsym(d_zp1p);
    __half* p_yp2p  = (__half*)getsym(d_yp2p);
    __half* p_zp2p  = (__half*)getsym(d_zp2p);
    float*  p_ly    = (float*) getsym(d_ly);
    float*  p_lz    = (float*) getsym(d_lz);

    const int T = 256;

    // ---- first launches (slot 3 = merged GGNN GEMM) ----
    zero_pack_k<<<(3 * 256 * 2 * 1024 + T - 1) / T, T>>>();                      // 0
    init_h_k<<<(NTOT * ODIM + T - 1) / T, T>>>(features);                        // 1
    packB_comb<<<(12 * KT * 512 + T - 1) / T, T>>>(etype_W, W_hh);               // 2
    launch_fast2(p_hp0, p_Wcomb, p_Hth, 800, nullptr, p_ghh, H3, b_hh, 7, 12);   // 3

    // ---- rest of setup ----
    packB_k<<<(5 * KT * 512 + T - 1) / T, T>>>(W_ih, p_Wihp, H3, 5);
    zero_int_k<<<(NTOT * 4 + T - 1) / T, T>>>(p_deg4, NTOT * 4);
    hist_k<<<(EDGES + T - 1) / T, T>>>(edst, etyp);
    scan_k<<<1, 1024>>>();
    chunk_hist_k<<<dim3(NCHK, BATCH), 512>>>(edst);
    chunk_scan_k<<<(NTOT + T - 1) / T, T>>>();
    scatter_k<<<dim3(NCHK, BATCH), 512>>>(esrc, edst, etyp);
    packA_c1<<<(3 * 2 * 128 * KTY * 16 + T - 1) / T, T>>>(conv1_w, p_w1yp, ODIM, KTY, 2);
    packA_c1<<<(3 * 3 * 128 * KTZ * 16 + T - 1) / T, T>>>(convc1_w, p_w1zp, CDIM, KTZ, 3);
    packA_m<<<(2 * 128 * KTY * 16 + T - 1) / T, T>>>(conv2_w, p_w2yp, ODIM, ODIM, KTY, 2);
    packA_m<<<(3 * 128 * KTZ * 16 + T - 1) / T, T>>>(convc2_w, p_w2zp, CDIM, CDIM, KTZ, 3);
    packA_m<<<(128 * KTY * 16 + T - 1) / T, T>>>(mlp_y_w, p_wmyp, NCLS, ODIM, KTY, 1);
    packA_m<<<(128 * KTZ * 16 + T - 1) / T, T>>>(mlp_z_w, p_wmzp, NCLS, CDIM, KTZ, 1);
    nodebias_k<<<(NTOT * ODIM + T - 1) / T, T>>>(etype_b);

    // ---- GGNN: 8 steps ----
    for (int s = 0; s < 8; s++) {
        const float*  hin  = (s & 1) ? p_h1 : p_h0;
        float*        hout = (s & 1) ? p_h0 : p_h1;
        const __half* hpin = (s & 1) ? p_hp1 : p_hp0;
        __half*       hpout= (s & 1) ? p_hp0 : p_hp1;
        if (s > 0)
            launch_fast2(hpin, p_Wcomb, p_Hth, 800, nullptr, p_ghh, H3, b_hh, 7, 12);
        spmm_k<<<NTOT / 4, 128>>>(p_Hth);
        launch_fast2(p_ap, p_Wihp, p_gih, H3, b_ih, nullptr, 0, nullptr, 5, 5);
        gates_k<<<(NTOT * 50 + T - 1) / T, T>>>(hin, hout, hpout);
    }
    float* p_hf = p_h0;

    // ---- readout (fp16 fragment path) ----
    pack_cT<<<(KTZ * NBPT * 4 + T - 1) / T, T>>>(p_hf, features);

    launch_fr<1,1>(p_w1yp, p_cTp, p_y1h, conv1_b, ODIM, NTOT, NBPT, KTY, 3,
                   2 * KTY * 2048, 256, 2);
    pool3h_k<<<(KTY * GP1 * 4 + T - 1) / T, T>>>(p_y1h, p_yp1p, ODIM, KTY);
    launch_fr<1,1>(p_w2yp, p_yp1p, p_y2h, conv2_b, ODIM, GP1, GP1, KTY, 1, 0, 127, 2);
    pool2h_k<<<(KTY * NBP2 * 4 + T - 1) / T, T>>>(p_y2h, p_yp2p, ODIM, KTY);
    launch_fr<0,0>(p_wmyp, p_yp2p, p_ly, nullptr, NCLS, GP2, NBP2, KTY, 1, 0, 64, 1);

    launch_fr<1,1>(p_w1zp, p_cTp, p_z1h, convc1_b, CDIM, NTOT, NBPT, KTZ, 3,
                   3 * KTZ * 2048, 256, 3);
    pool3h_k<<<(KTZ * GP1 * 4 + T - 1) / T, T>>>(p_z1h, p_zp1p, CDIM, KTZ);
    launch_fr<1,1>(p_w2zp, p_zp1p, p_z2h, convc2_b, CDIM, GP1, GP1, KTZ, 1, 0, 127, 3);
    pool2h_k<<<(KTZ * NBP2 * 4 + T - 1) / T, T>>>(p_z2h, p_zp2p, CDIM, KTZ);
    launch_fr<0,0>(p_wmzp, p_zp2p, p_lz, nullptr, NCLS, GP2, NBP2, KTZ, 1, 0, 64, 1);

    final_k<<<BATCH, 128>>>(mlp_y_b, mlp_z_b, (float*)d_out);
}